// round 11
// baseline (speedup 1.0000x reference)
#include <cuda_runtime.h>
#include <cuda_bf16.h>
#include <cstdint>

// Problem constants
#define BATCH 2
#define SEQ 2048
#define DMODEL 1024
#define NH 16
#define NKV 4
#define HD 64
#define OUT_ELEMS  (BATCH*SEQ*DMODEL)
#define KV_ELEMS   (BATCH*SEQ*NKV*HD)

#define MTOT (BATCH*SEQ)        // 4096
#define GK   (3*DMODEL)         // 3072 split-K (hi|lo|hi vs hi|hi|lo)
#define NQKV 1536               // fused QKV output width

// ---------------------------------------------------------------------------
// Scratch (device globals; no runtime allocation allowed)
// ---------------------------------------------------------------------------
__device__ float g_qkv[MTOT*NQKV];                   // fused QKV gemm output
__device__ __nv_bfloat16 g_xc   [MTOT*GK];           // x split [M, 3K]
__device__ __nv_bfloat16 g_aoc  [MTOT*GK];           // attn out split [M, 3K]
__device__ __nv_bfloat16 g_wqkvt[NQKV*GK];           // [wq|wk|wv]^T split
__device__ __nv_bfloat16 g_wot  [DMODEL*GK];
// Attention operands (compact split bf16: [hi|lo], 128 cols)
__device__ __nv_bfloat16 g_qb [BATCH*NH*SEQ*128];    // [b][h][s][hi|lo]
__device__ __nv_bfloat16 g_kb [BATCH*NKV*SEQ*128];   // [b][kvh][s][hi|lo]
__device__ __nv_bfloat16 g_vhi[BATCH*NKV*HD*SEQ];    // [b][kvh][d][s] transposed
__device__ __nv_bfloat16 g_vlo[BATCH*NKV*HD*SEQ];

// ---------------------------------------------------------------------------
// Baseline-PTX helpers
// ---------------------------------------------------------------------------
__device__ __forceinline__ uint32_t smem_u32(const void* p) {
    uint32_t a;
    asm("{ .reg .u64 t; cvta.to.shared.u64 t, %1; cvt.u32.u64 %0, t; }" : "=r"(a) : "l"(p));
    return a;
}
__device__ __forceinline__ void cp16(uint32_t saddr, const void* g) {
    asm volatile("cp.async.cg.shared.global [%0], [%1], 16;" :: "r"(saddr), "l"(g) : "memory");
}
#define CP_COMMIT() asm volatile("cp.async.commit_group;" ::: "memory")
#define CP_WAIT(n)  asm volatile("cp.async.wait_group %0;" :: "n"(n) : "memory")

__device__ __forceinline__ void ldsm4(uint32_t& r0, uint32_t& r1, uint32_t& r2, uint32_t& r3,
                                      uint32_t a) {
    asm volatile("ldmatrix.sync.aligned.m8n8.x4.shared.b16 {%0,%1,%2,%3}, [%4];"
                 : "=r"(r0), "=r"(r1), "=r"(r2), "=r"(r3) : "r"(a));
}
__device__ __forceinline__ void mma16816(float* c, uint32_t a0, uint32_t a1, uint32_t a2,
                                         uint32_t a3, uint32_t b0, uint32_t b1) {
    asm volatile(
        "mma.sync.aligned.m16n8k16.row.col.f32.bf16.bf16.f32 "
        "{%0,%1,%2,%3},{%4,%5,%6,%7},{%8,%9},{%0,%1,%2,%3};"
        : "+f"(c[0]), "+f"(c[1]), "+f"(c[2]), "+f"(c[3])
        : "r"(a0), "r"(a1), "r"(a2), "r"(a3), "r"(b0), "r"(b1));
}
__device__ __forceinline__ uint32_t pack_bf16(float x, float y) {
    uint32_t r;
    asm("cvt.rn.bf16x2.f32 %0, %1, %2;" : "=r"(r) : "f"(y), "f"(x));
    return r;
}
__device__ __forceinline__ void split_bf16(float v, __nv_bfloat16& hi, __nv_bfloat16& lo) {
    hi = __float2bfloat16(v);
    lo = __float2bfloat16(v - __bfloat162float(hi));
}

// ---------------------------------------------------------------------------
// A-side split: src [M, K] fp32 -> dst [M, 3K] = [hi | lo | hi]
// ---------------------------------------------------------------------------
__global__ __launch_bounds__(256) void conv_a(const float* __restrict__ src,
                                              __nv_bfloat16* __restrict__ dst) {
    int idx = blockIdx.x * blockDim.x + threadIdx.x;
    const int K = DMODEL;
    if (idx >= MTOT * K / 4) return;
    int flat = idx * 4;
    int m = flat / K, k = flat % K;
    float4 v = *(const float4*)(src + flat);
    float vv[4] = {v.x, v.y, v.z, v.w};
    __nv_bfloat16 h[4], l[4];
#pragma unroll
    for (int j = 0; j < 4; j++) split_bf16(vv[j], h[j], l[j]);
    __nv_bfloat16* row = dst + (size_t)m * GK;
    *(uint2*)(row + k)         = *(uint2*)h;
    *(uint2*)(row + K + k)     = *(uint2*)l;
    *(uint2*)(row + 2 * K + k) = *(uint2*)h;
}

// Fused weight split for [wq|wk|wv] -> wqkvt [1536, 3K]
__global__ void conv_qkv(const float* __restrict__ wq, const float* __restrict__ wk,
                         const float* __restrict__ wv, __nv_bfloat16* __restrict__ dst) {
    __shared__ float tile[32][33];
    const int K = DMODEL;
    int k0 = blockIdx.y * 32, n0 = blockIdx.x * 32;
    const float* src;
    int nloc, N;
    float scale = 1.f;
    if (n0 < 1024)      { src = wq; nloc = n0;        N = 1024; scale = 0.125f; }
    else if (n0 < 1280) { src = wk; nloc = n0 - 1024; N = 256; }
    else                { src = wv; nloc = n0 - 1280; N = 256; }
    int tx = threadIdx.x, ty = threadIdx.y;
#pragma unroll
    for (int i = 0; i < 32; i += 8)
        tile[ty + i][tx] = src[(size_t)(k0 + ty + i) * N + nloc + tx] * scale;
    __syncthreads();
#pragma unroll
    for (int i = 0; i < 32; i += 8) {
        int n = n0 + ty + i, k = k0 + tx;
        __nv_bfloat16 h, l;
        split_bf16(tile[tx][ty + i], h, l);
        __nv_bfloat16* row = dst + (size_t)n * GK;
        row[k]         = h;
        row[K + k]     = h;
        row[2 * K + k] = l;
    }
}

// B-side split for wo
__global__ void conv_w(const float* __restrict__ src, __nv_bfloat16* __restrict__ dst,
                       int N) {
    __shared__ float tile[32][33];
    const int K = DMODEL;
    int k0 = blockIdx.y * 32, n0 = blockIdx.x * 32;
    int tx = threadIdx.x, ty = threadIdx.y;
#pragma unroll
    for (int i = 0; i < 32; i += 8)
        tile[ty + i][tx] = src[(size_t)(k0 + ty + i) * N + n0 + tx];
    __syncthreads();
#pragma unroll
    for (int i = 0; i < 32; i += 8) {
        int n = n0 + ty + i, k = k0 + tx;
        __nv_bfloat16 h, l;
        split_bf16(tile[tx][ty + i], h, l);
        __nv_bfloat16* row = dst + (size_t)n * GK;
        row[k]         = h;
        row[K + k]     = h;
        row[2 * K + k] = l;
    }
}

// ---------------------------------------------------------------------------
// bf16 mma.sync GEMM, templated on CTA N-tile width (unchanged from R10).
// ---------------------------------------------------------------------------
#define BMt 128
#define BKt 32
#define PADt 40
#define NCHt (GK/BKt)           // 96
#define STAGES 4
#define GEMM_SMEM_FOR(BN) (STAGES * (BMt + (BN)) * PADt * 2)

template<int BN>
__global__ __launch_bounds__(256, 2) void gemm_mma(const __nv_bfloat16* __restrict__ A,
                                                   const __nv_bfloat16* __restrict__ Bt,
                                                   float* __restrict__ C, int N) {
    constexpr int WN = BN / 4;
    constexpr int NT = WN / 8;
    constexpr int NP = WN / 16;
    constexpr int SEL = (BMt + BN) * PADt;
    constexpr int TOTCH = (BMt + BN) * 4;

    extern __shared__ __nv_bfloat16 gsm[];
    uint32_t smb = smem_u32(gsm);

    int t = threadIdx.x, w = t >> 5, lane = t & 31;
    int m0 = blockIdx.y * BMt, n0 = blockIdx.x * BN;
    int wm = (w >> 2) * 64;
    int wn = (w & 3) * WN;

    float acc[4][NT][4];
#pragma unroll
    for (int i = 0; i < 4; i++)
#pragma unroll
        for (int j = 0; j < NT; j++)
#pragma unroll
            for (int r = 0; r < 4; r++) acc[i][j][r] = 0.f;

    const __nv_bfloat16* Ab = A  + (size_t)m0 * GK;
    const __nv_bfloat16* Bb = Bt + (size_t)n0 * GK;

    auto load_tile = [&](int kc, int s) {
        if (kc < NCHt) {
            uint32_t ab = smb + s * (SEL * 2);
            uint32_t bb = ab + BMt * PADt * 2;
            const __nv_bfloat16* Ak = Ab + kc * BKt;
            const __nv_bfloat16* Bk = Bb + kc * BKt;
#pragma unroll
            for (int i = 0; i < TOTCH / 256; i++) {
                int idx = t + i * 256;
                int row = idx >> 2, ch = idx & 3;
                if (row < BMt)
                    cp16(ab + (row * PADt + ch * 8) * 2, Ak + (size_t)row * GK + ch * 8);
                else {
                    int r = row - BMt;
                    cp16(bb + (r * PADt + ch * 8) * 2, Bk + (size_t)r * GK + ch * 8);
                }
            }
        }
        CP_COMMIT();
    };

#pragma unroll
    for (int s = 0; s < STAGES - 1; s++) load_tile(s, s);

    int li = lane >> 3;
    int lr = lane & 7;

    for (int kc = 0; kc < NCHt; kc++) {
        CP_WAIT(STAGES - 2);
        __syncthreads();
        load_tile(kc + STAGES - 1, (kc + STAGES - 1) % STAGES);

        int s = kc % STAGES;
        uint32_t ab = smb + s * (SEL * 2);
        uint32_t bb = ab + BMt * PADt * 2;

#pragma unroll
        for (int ks = 0; ks < 2; ks++) {
            int k0 = ks * 16;
            uint32_t a[4][4];
#pragma unroll
            for (int mt = 0; mt < 4; mt++) {
                int row = wm + mt * 16 + (li & 1) * 8 + lr;
                int col = k0 + (li >> 1) * 8;
                ldsm4(a[mt][0], a[mt][1], a[mt][2], a[mt][3],
                      ab + (row * PADt + col) * 2);
            }
            uint32_t b[NP][4];
#pragma unroll
            for (int p = 0; p < NP; p++) {
                int row = wn + p * 16 + (li >> 1) * 8 + lr;
                int col = k0 + (li & 1) * 8;
                ldsm4(b[p][0], b[p][1], b[p][2], b[p][3],
                      bb + (row * PADt + col) * 2);
            }
#pragma unroll
            for (int mt = 0; mt < 4; mt++)
#pragma unroll
                for (int nt = 0; nt < NT; nt++) {
                    int p = nt >> 1, off = (nt & 1) * 2;
                    mma16816(acc[mt][nt], a[mt][0], a[mt][1], a[mt][2], a[mt][3],
                             b[p][off], b[p][off + 1]);
                }
        }
    }

    int cr = lane >> 2, cc = (lane & 3) * 2;
#pragma unroll
    for (int mt = 0; mt < 4; mt++)
#pragma unroll
        for (int nt = 0; nt < NT; nt++) {
            float* Cp = C + (size_t)(m0 + wm + mt * 16 + cr) * N + n0 + wn + nt * 8 + cc;
            *(float2*)Cp = make_float2(acc[mt][nt][0], acc[mt][nt][1]);
            *(float2*)(Cp + 8 * (size_t)N) = make_float2(acc[mt][nt][2], acc[mt][nt][3]);
        }
}

// ---------------------------------------------------------------------------
// finish_q / finish_k / finish_v (unchanged)
// ---------------------------------------------------------------------------
__global__ __launch_bounds__(256) void finish_q(const float* __restrict__ qkv,
                                                const float* __restrict__ cosT,
                                                const float* __restrict__ sinT,
                                                __nv_bfloat16* __restrict__ qb) {
    int idx = blockIdx.x * 256 + threadIdx.x;
    const int total = BATCH * SEQ * NH * 32;
    if (idx >= total) return;
    int j = idx & 31;
    int rest = idx >> 5;
    int h = rest % NH;
    int row = rest / NH;
    int s = row % SEQ, b = row / SEQ;

    const float* src = qkv + (size_t)row * NQKV + h * 64;
    float c  = cosT[s * 32 + j];
    float sn = sinT[s * 32 + j];
    float x1 = src[j], x2 = src[j + 32];
    float y1 = x1 * c - x2 * sn;
    float y2 = x2 * c + x1 * sn;

    __nv_bfloat16 h1, l1, h2, l2;
    split_bf16(y1, h1, l1);
    split_bf16(y2, h2, l2);
    __nv_bfloat16* d = qb + ((size_t)(b * NH + h) * SEQ + s) * 128;
    d[j]       = h1;  d[j + 32]  = h2;   // hi
    d[64 + j]  = l1;  d[96 + j]  = l2;   // lo
}

__global__ __launch_bounds__(256) void finish_k(const float* __restrict__ qkv,
                                                const float* __restrict__ cosT,
                                                const float* __restrict__ sinT,
                                                float* __restrict__ kout,
                                                __nv_bfloat16* __restrict__ kb) {
    int idx = blockIdx.x * 256 + threadIdx.x;
    const int total = BATCH * SEQ * NKV * 32;
    if (idx >= total) return;
    int j = idx & 31;
    int rest = idx >> 5;
    int kvh = rest % NKV;
    int row = rest / NKV;
    int s = row % SEQ, b = row / SEQ;

    const float* src = qkv + (size_t)row * NQKV + 1024 + kvh * 64;
    float c  = cosT[s * 32 + j];
    float sn = sinT[s * 32 + j];
    float x1 = src[j], x2 = src[j + 32];
    float y1 = x1 * c - x2 * sn;
    float y2 = x2 * c + x1 * sn;

    float* ko = kout + ((size_t)row * NKV + kvh) * 64;
    ko[j] = y1;
    ko[j + 32] = y2;

    __nv_bfloat16 h1, l1, h2, l2;
    split_bf16(y1, h1, l1);
    split_bf16(y2, h2, l2);
    __nv_bfloat16* d = kb + ((size_t)(b * NKV + kvh) * SEQ + s) * 128;
    d[j]       = h1;  d[j + 32]  = h2;   // hi
    d[64 + j]  = l1;  d[96 + j]  = l2;   // lo
}

__global__ void finish_v(const float* __restrict__ qkv,
                         float* __restrict__ vout,
                         __nv_bfloat16* __restrict__ vhi,
                         __nv_bfloat16* __restrict__ vlo) {
    __shared__ float tile[32][33];
    int bkv = blockIdx.z;
    int b = bkv / NKV, kvh = bkv % NKV;
    int s0 = blockIdx.x * 32, d0 = blockIdx.y * 32;
    int tx = threadIdx.x, ty = threadIdx.y;
#pragma unroll
    for (int i = 0; i < 32; i += 8) {
        int s = s0 + ty + i;
        float v = qkv[((size_t)b * SEQ + s) * NQKV + 1280 + kvh * 64 + d0 + tx];
        tile[ty + i][tx] = v;
        vout[(((size_t)b * SEQ + s) * NKV + kvh) * 64 + d0 + tx] = v;
    }
    __syncthreads();
#pragma unroll
    for (int i = 0; i < 32; i += 8) {
        int d = d0 + ty + i, s = s0 + tx;
        __nv_bfloat16 h, l;
        split_bf16(tile[tx][ty + i], h, l);
        size_t off = ((size_t)bkv * HD + d) * SEQ + s;
        vhi[off] = h;
        vlo[off] = l;
    }
}

// ---------------------------------------------------------------------------
// Tensor-core flash attention, compact [hi|lo] operands.
// BM=128 queries per CTA (256 threads, 8 warps x 16 rows); key tiles of 64.
// K/V tile loads amortized over 2x more queries (-45% load traffic).
// Extra fully-masked corner tiles are numerically inert (bit-identical).
// Smem: (128 + 64 + 64) x 136 bf16 = 69.6 KB -> 2 CTAs/SM (16 warps/SM).
// ---------------------------------------------------------------------------
#define APAD 136
#define ATTN2_SMEM ((128 + 64 + 64) * APAD * 2)

__global__ __launch_bounds__(256) void attn_mma(const __nv_bfloat16* __restrict__ Qb,
                                                const __nv_bfloat16* __restrict__ Kb,
                                                const __nv_bfloat16* __restrict__ Vhi,
                                                const __nv_bfloat16* __restrict__ Vlo,
                                                __nv_bfloat16* __restrict__ aoc) {
    extern __shared__ __nv_bfloat16 sb[];
    __nv_bfloat16* qs = sb;                 // [128][APAD]
    __nv_bfloat16* ks = sb + 128 * APAD;    // [64][APAD]
    __nv_bfloat16* vs = ks + 64 * APAD;     // [64][APAD]
    uint32_t qsa = smem_u32(qs), ksa = smem_u32(ks), vsa = smem_u32(vs);

    int t = threadIdx.x, w = t >> 5, lane = t & 31;
    int qt = gridDim.x - 1 - blockIdx.x;   // longest CTAs first (qt 0..15)
    int h = blockIdx.y, b = blockIdx.z;
    int kvh = h >> 2;
    int li = lane >> 3, lr = lane & 7;
    int r0 = lane >> 2;
    int cc = (lane & 3) * 2;

    // Q tile [128][128]
    const __nv_bfloat16* qsrc = Qb + ((size_t)(b * NH + h) * SEQ + (size_t)qt * 128) * 128;
#pragma unroll
    for (int i = 0; i < 8; i++) {
        int c = t + 256 * i;
        int row = c >> 4, seg = c & 15;
        cp16(qsa + (row * APAD + seg * 8) * 2, qsrc + (size_t)row * 128 + seg * 8);
    }
    CP_COMMIT();

    float m0 = -1e30f, m1 = -1e30f, l0 = 0.f, l1 = 0.f;
    float of[8][4];
#pragma unroll
    for (int j = 0; j < 8; j++)
#pragma unroll
        for (int e = 0; e < 4; e++) of[j][e] = 0.f;

    const __nv_bfloat16* ksrc0 = Kb + (size_t)(b * NKV + kvh) * SEQ * 128;
    const __nv_bfloat16* vh0 = Vhi + (size_t)(b * NKV + kvh) * HD * SEQ;
    const __nv_bfloat16* vl0 = Vlo + (size_t)(b * NKV + kvh) * HD * SEQ;

    int ntiles = 2 * qt + 2;
    for (int kt = 0; kt < ntiles; kt++) {
        // K tile [64][128] (own commit group)
        const __nv_bfloat16* ksrc = ksrc0 + (size_t)kt * 64 * 128;
#pragma unroll
        for (int i = 0; i < 4; i++) {
            int c = t + 256 * i;
            int row = c >> 4, seg = c & 15;
            cp16(ksa + (row * APAD + seg * 8) * 2, ksrc + (size_t)row * 128 + seg * 8);
        }
        CP_COMMIT();
        // V tile [64 d][Vhi(64)|Vlo(64)] (own commit group)
#pragma unroll
        for (int i = 0; i < 4; i++) {
            int c = t + 256 * i;
            int d = c >> 4, seg = c & 15;
            const __nv_bfloat16* src = (seg < 8 ? vh0 : vl0)
                                       + (size_t)d * SEQ + kt * 64 + (seg & 7) * 8;
            cp16(vsa + (d * APAD + seg * 8) * 2, src);
        }
        CP_COMMIT();

        CP_WAIT(1);     // Q + K landed; V may be in flight
        __syncthreads();

        // ---- S = Q' K'^T: ksteps 0-3 Qhi.Khi, 4-7 Qlo.Khi, 8-11 Qhi.Klo ----
        float sf[8][4];
#pragma unroll
        for (int j = 0; j < 8; j++)
#pragma unroll
            for (int e = 0; e < 4; e++) sf[j][e] = 0.f;
#pragma unroll
        for (int ks12 = 0; ks12 < 12; ks12++) {
            int aCol = (ks12 < 8 ? ks12 : ks12 - 8) * 16;
            int bCol = (ks12 < 4 ? ks12 * 16 : (ks12 < 8 ? (ks12 - 4) * 16
                                                          : 64 + (ks12 - 8) * 16));
            uint32_t a0, a1, a2, a3;
            ldsm4(a0, a1, a2, a3,
                  qsa + ((w * 16 + (li & 1) * 8 + lr) * APAD + aCol + (li >> 1) * 8) * 2);
#pragma unroll
            for (int p = 0; p < 4; p++) {
                uint32_t b0, b1, b2, b3;
                ldsm4(b0, b1, b2, b3,
                      ksa + ((p * 16 + (li >> 1) * 8 + lr) * APAD + bCol + (li & 1) * 8) * 2);
                mma16816(sf[2 * p],     a0, a1, a2, a3, b0, b1);
                mma16816(sf[2 * p + 1], a0, a1, a2, a3, b2, b3);
            }
        }

        // causal mask on the two diagonal-crossing tiles (global indices)
        if (kt >= 2 * qt) {
            int q0 = qt * 128 + w * 16 + r0, q1 = q0 + 8;
            int kbase = kt * 64;
#pragma unroll
            for (int j = 0; j < 8; j++) {
                int key = kbase + 8 * j + cc;
                if (key     > q0) sf[j][0] = -1e30f;
                if (key + 1 > q0) sf[j][1] = -1e30f;
                if (key     > q1) sf[j][2] = -1e30f;
                if (key + 1 > q1) sf[j][3] = -1e30f;
            }
        }

        // ---- online softmax ----
        float mx0 = -1e30f, mx1 = -1e30f;
#pragma unroll
        for (int j = 0; j < 8; j++) {
            mx0 = fmaxf(mx0, fmaxf(sf[j][0], sf[j][1]));
            mx1 = fmaxf(mx1, fmaxf(sf[j][2], sf[j][3]));
        }
        mx0 = fmaxf(mx0, __shfl_xor_sync(0xffffffffu, mx0, 1));
        mx0 = fmaxf(mx0, __shfl_xor_sync(0xffffffffu, mx0, 2));
        mx1 = fmaxf(mx1, __shfl_xor_sync(0xffffffffu, mx1, 1));
        mx1 = fmaxf(mx1, __shfl_xor_sync(0xffffffffu, mx1, 2));
        float nm0 = fmaxf(m0, mx0), nm1 = fmaxf(m1, mx1);
        float al0 = __expf(m0 - nm0), al1 = __expf(m1 - nm1);
        m0 = nm0; m1 = nm1;

        float s0 = 0.f, s1 = 0.f;
#pragma unroll
        for (int j = 0; j < 8; j++) {
            sf[j][0] = __expf(sf[j][0] - m0); s0 += sf[j][0];
            sf[j][1] = __expf(sf[j][1] - m0); s0 += sf[j][1];
            sf[j][2] = __expf(sf[j][2] - m1); s1 += sf[j][2];
            sf[j][3] = __expf(sf[j][3] - m1); s1 += sf[j][3];
        }
        s0 += __shfl_xor_sync(0xffffffffu, s0, 1);
        s0 += __shfl_xor_sync(0xffffffffu, s0, 2);
        s1 += __shfl_xor_sync(0xffffffffu, s1, 1);
        s1 += __shfl_xor_sync(0xffffffffu, s1, 2);
        l0 = l0 * al0 + s0;
        l1 = l1 * al1 + s1;

#pragma unroll
        for (int j = 0; j < 8; j++) {
            of[j][0] *= al0; of[j][1] *= al0;
            of[j][2] *= al1; of[j][3] *= al1;
        }

        // ---- split P into bf16 A-fragments ----
        uint32_t ah[4][4], alf[4][4];
#pragma unroll
        for (int kk = 0; kk < 4; kk++) {
            float c00 = sf[2 * kk][0], c01 = sf[2 * kk][1];
            float c02 = sf[2 * kk][2], c03 = sf[2 * kk][3];
            float c10 = sf[2 * kk + 1][0], c11 = sf[2 * kk + 1][1];
            float c12 = sf[2 * kk + 1][2], c13 = sf[2 * kk + 1][3];
            uint32_t h0 = pack_bf16(c00, c01), h1 = pack_bf16(c02, c03);
            uint32_t h2 = pack_bf16(c10, c11), h3 = pack_bf16(c12, c13);
            ah[kk][0] = h0; ah[kk][1] = h1; ah[kk][2] = h2; ah[kk][3] = h3;
            __nv_bfloat162 b0 = *(__nv_bfloat162*)&h0;
            __nv_bfloat162 b1 = *(__nv_bfloat162*)&h1;
            __nv_bfloat162 b2 = *(__nv_bfloat162*)&h2;
            __nv_bfloat162 b3 = *(__nv_bfloat162*)&h3;
            alf[kk][0] = pack_bf16(c00 - __bfloat162float(b0.x), c01 - __bfloat162float(b0.y));
            alf[kk][1] = pack_bf16(c02 - __bfloat162float(b1.x), c03 - __bfloat162float(b1.y));
            alf[kk][2] = pack_bf16(c10 - __bfloat162float(b2.x), c11 - __bfloat162float(b2.y));
            alf[kk][3] = pack_bf16(c12 - __bfloat162float(b3.x), c13 - __bfloat162float(b3.y));
        }

        CP_WAIT(0);     // V fully landed
        __syncthreads();

        // ---- O += P' V': Phi*Vhi, Plo*Vhi, Phi*Vlo ----
#pragma unroll
        for (int ks12 = 0; ks12 < 12; ks12++) {
            int kk = ks12 & 3, sel = ks12 >> 2;
            uint32_t* A = (sel == 1) ? alf[kk] : ah[kk];
            int k0 = (sel == 2 ? 64 : 0) + kk * 16;
#pragma unroll
            for (int p = 0; p < 4; p++) {
                uint32_t b0, b1, b2, b3;
                ldsm4(b0, b1, b2, b3,
                      vsa + ((p * 16 + (li >> 1) * 8 + lr) * APAD + k0 + (li & 1) * 8) * 2);
                mma16816(of[2 * p],     A[0], A[1], A[2], A[3], b0, b1);
                mma16816(of[2 * p + 1], A[0], A[1], A[2], A[3], b2, b3);
            }
        }
        __syncthreads();
    }

    // ---- epilogue: write split [hi|lo|hi] directly into aoc ----
    float inv0 = 1.f / l0, inv1 = 1.f / l1;
    int row0 = b * SEQ + qt * 128 + w * 16 + r0;
    int row1 = row0 + 8;
#pragma unroll
    for (int j = 0; j < 8; j++) {
        int colq = h * 64 + 8 * j + cc;
        {
            float v0 = of[j][0] * inv0, v1 = of[j][1] * inv0;
            uint32_t hp = pack_bf16(v0, v1);
            __nv_bfloat162 hb = *(__nv_bfloat162*)&hp;
            uint32_t lp = pack_bf16(v0 - __bfloat162float(hb.x), v1 - __bfloat162float(hb.y));
            uint32_t* base = (uint32_t*)(aoc + (size_t)row0 * GK + colq);
            base[0]              = hp;
            *(uint32_t*)((char*)base + 1024 * 2) = lp;
            *(uint32_t*)((char*)base + 2048 * 2) = hp;
        }
        {
            float v0 = of[j][2] * inv1, v1 = of[j][3] * inv1;
            uint32_t hp = pack_bf16(v0, v1);
            __nv_bfloat162 hb = *(__nv_bfloat162*)&hp;
            uint32_t lp = pack_bf16(v0 - __bfloat162float(hb.x), v1 - __bfloat162float(hb.y));
            uint32_t* base = (uint32_t*)(aoc + (size_t)row1 * GK + colq);
            base[0]              = hp;
            *(uint32_t*)((char*)base + 1024 * 2) = lp;
            *(uint32_t*)((char*)base + 2048 * 2) = hp;
        }
    }
}

// ---------------------------------------------------------------------------
extern "C" void kernel_launch(void* const* d_in, const int* in_sizes, int n_in,
                              void* d_out, int out_size) {
    const float* x    = (const float*)d_in[0];
    const float* cosT = (const float*)d_in[1];
    const float* sinT = (const float*)d_in[2];
    // d_in[3] = mask: unused
    const float* wq   = (const float*)d_in[4];
    const float* wk   = (const float*)d_in[5];
    const float* wv   = (const float*)d_in[6];
    const float* wo   = (const float*)d_in[7];

    float* out  = (float*)d_out;
    float* kout = out + OUT_ELEMS;
    float* vout = out + OUT_ELEMS + KV_ELEMS;

    float* qkv;
    __nv_bfloat16 *xc, *aoc, *wqkvt, *wot, *qb, *kb, *vhi, *vlo;
    cudaGetSymbolAddress((void**)&qkv, g_qkv);
    cudaGetSymbolAddress((void**)&xc,  g_xc);
    cudaGetSymbolAddress((void**)&aoc, g_aoc);
    cudaGetSymbolAddress((void**)&wqkvt, g_wqkvt);
    cudaGetSymbolAddress((void**)&wot, g_wot);
    cudaGetSymbolAddress((void**)&qb,  g_qb);
    cudaGetSymbolAddress((void**)&kb,  g_kb);
    cudaGetSymbolAddress((void**)&vhi, g_vhi);
    cudaGetSymbolAddress((void**)&vlo, g_vlo);

    cudaFuncSetAttribute(attn_mma, cudaFuncAttributeMaxDynamicSharedMemorySize, ATTN2_SMEM);
    cudaFuncSetAttribute(gemm_mma<128>, cudaFuncAttributeMaxDynamicSharedMemorySize,
                         GEMM_SMEM_FOR(128));
    cudaFuncSetAttribute(gemm_mma<192>, cudaFuncAttributeMaxDynamicSharedMemorySize,
                         GEMM_SMEM_FOR(192));

    // Split conversions
    conv_a<<<(MTOT * DMODEL / 4 + 255) / 256, 256>>>(x, xc);
    dim3 wb(32, 8);
    conv_qkv<<<dim3(NQKV / 32, DMODEL / 32), wb>>>(wq, wk, wv, wqkvt);
    conv_w<<<dim3(DMODEL / 32, DMODEL / 32), wb>>>(wo, wot, DMODEL);

    // Fused QKV projection: 128x192 tiles -> 256 CTAs = single wave
    gemm_mma<192><<<dim3(NQKV / 192, MTOT / 128), 256, GEMM_SMEM_FOR(192)>>>(
        xc, wqkvt, qkv, NQKV);

    // RoPE + compact split + fp32 kv-cache outputs
    finish_q<<<(BATCH * SEQ * NH * 32 + 255) / 256, 256>>>(qkv, cosT, sinT, qb);
    finish_k<<<(BATCH * SEQ * NKV * 32 + 255) / 256, 256>>>(qkv, cosT, sinT, kout, kb);
    finish_v<<<dim3(SEQ / 32, HD / 32, BATCH * NKV), dim3(32, 8)>>>(qkv, vout, vhi, vlo);

    // Tensor-core flash attention (BM=128, 256 threads)
    attn_mma<<<dim3(SEQ / 128, NH, BATCH), 256, ATTN2_SMEM>>>(qb, kb, vhi, vlo, aoc);

    // Output projection: exact R6 config (grid 256, single wave)
    gemm_mma<128><<<dim3(DMODEL / 128, MTOT / 128), 256, GEMM_SMEM_FOR(128)>>>(
        aoc, wot, out, DMODEL);
}

// round 12
// speedup vs baseline: 1.0692x; 1.0692x over previous
#include <cuda_runtime.h>
#include <cuda_bf16.h>
#include <cstdint>

// Problem constants
#define BATCH 2
#define SEQ 2048
#define DMODEL 1024
#define NH 16
#define NKV 4
#define HD 64
#define OUT_ELEMS  (BATCH*SEQ*DMODEL)
#define KV_ELEMS   (BATCH*SEQ*NKV*HD)

#define MTOT (BATCH*SEQ)        // 4096
#define GK   (3*DMODEL)         // 3072 split-K (hi|lo|hi vs hi|hi|lo)
#define NQKV 1536               // fused QKV output width

// ---------------------------------------------------------------------------
// Scratch (device globals; no runtime allocation allowed)
// ---------------------------------------------------------------------------
__device__ float g_qkv[MTOT*NQKV];                   // fused QKV gemm output
__device__ __nv_bfloat16 g_xc   [MTOT*GK];           // x split [M, 3K]
__device__ __nv_bfloat16 g_aoc  [MTOT*GK];           // attn out split [M, 3K]
__device__ __nv_bfloat16 g_wqkvt[NQKV*GK];           // [wq|wk|wv]^T split
__device__ __nv_bfloat16 g_wot  [DMODEL*GK];
// Attention operands (compact split bf16: [hi|lo], 128 cols)
__device__ __nv_bfloat16 g_qb [BATCH*NH*SEQ*128];    // [b][h][s][hi|lo]
__device__ __nv_bfloat16 g_kb [BATCH*NKV*SEQ*128];   // [b][kvh][s][hi|lo]
__device__ __nv_bfloat16 g_vhi[BATCH*NKV*HD*SEQ];    // [b][kvh][d][s] transposed
__device__ __nv_bfloat16 g_vlo[BATCH*NKV*HD*SEQ];

// ---------------------------------------------------------------------------
// Baseline-PTX helpers
// ---------------------------------------------------------------------------
__device__ __forceinline__ uint32_t smem_u32(const void* p) {
    uint32_t a;
    asm("{ .reg .u64 t; cvta.to.shared.u64 t, %1; cvt.u32.u64 %0, t; }" : "=r"(a) : "l"(p));
    return a;
}
__device__ __forceinline__ void cp16(uint32_t saddr, const void* g) {
    asm volatile("cp.async.cg.shared.global [%0], [%1], 16;" :: "r"(saddr), "l"(g) : "memory");
}
#define CP_COMMIT() asm volatile("cp.async.commit_group;" ::: "memory")
#define CP_WAIT(n)  asm volatile("cp.async.wait_group %0;" :: "n"(n) : "memory")

__device__ __forceinline__ void ldsm4(uint32_t& r0, uint32_t& r1, uint32_t& r2, uint32_t& r3,
                                      uint32_t a) {
    asm volatile("ldmatrix.sync.aligned.m8n8.x4.shared.b16 {%0,%1,%2,%3}, [%4];"
                 : "=r"(r0), "=r"(r1), "=r"(r2), "=r"(r3) : "r"(a));
}
__device__ __forceinline__ void mma16816(float* c, uint32_t a0, uint32_t a1, uint32_t a2,
                                         uint32_t a3, uint32_t b0, uint32_t b1) {
    asm volatile(
        "mma.sync.aligned.m16n8k16.row.col.f32.bf16.bf16.f32 "
        "{%0,%1,%2,%3},{%4,%5,%6,%7},{%8,%9},{%0,%1,%2,%3};"
        : "+f"(c[0]), "+f"(c[1]), "+f"(c[2]), "+f"(c[3])
        : "r"(a0), "r"(a1), "r"(a2), "r"(a3), "r"(b0), "r"(b1));
}
__device__ __forceinline__ uint32_t pack_bf16(float x, float y) {
    uint32_t r;
    asm("cvt.rn.bf16x2.f32 %0, %1, %2;" : "=r"(r) : "f"(y), "f"(x));
    return r;
}
__device__ __forceinline__ void split_bf16(float v, __nv_bfloat16& hi, __nv_bfloat16& lo) {
    hi = __float2bfloat16(v);
    lo = __float2bfloat16(v - __bfloat162float(hi));
}

// ---------------------------------------------------------------------------
// A-side split: src [M, K] fp32 -> dst [M, 3K] = [hi | lo | hi]
// ---------------------------------------------------------------------------
__global__ __launch_bounds__(256) void conv_a(const float* __restrict__ src,
                                              __nv_bfloat16* __restrict__ dst) {
    int idx = blockIdx.x * blockDim.x + threadIdx.x;
    const int K = DMODEL;
    if (idx >= MTOT * K / 4) return;
    int flat = idx * 4;
    int m = flat / K, k = flat % K;
    float4 v = *(const float4*)(src + flat);
    float vv[4] = {v.x, v.y, v.z, v.w};
    __nv_bfloat16 h[4], l[4];
#pragma unroll
    for (int j = 0; j < 4; j++) split_bf16(vv[j], h[j], l[j]);
    __nv_bfloat16* row = dst + (size_t)m * GK;
    *(uint2*)(row + k)         = *(uint2*)h;
    *(uint2*)(row + K + k)     = *(uint2*)l;
    *(uint2*)(row + 2 * K + k) = *(uint2*)h;
}

// Fused weight split for [wq|wk|wv] -> wqkvt [1536, 3K]
__global__ void conv_qkv(const float* __restrict__ wq, const float* __restrict__ wk,
                         const float* __restrict__ wv, __nv_bfloat16* __restrict__ dst) {
    __shared__ float tile[32][33];
    const int K = DMODEL;
    int k0 = blockIdx.y * 32, n0 = blockIdx.x * 32;
    const float* src;
    int nloc, N;
    float scale = 1.f;
    if (n0 < 1024)      { src = wq; nloc = n0;        N = 1024; scale = 0.125f; }
    else if (n0 < 1280) { src = wk; nloc = n0 - 1024; N = 256; }
    else                { src = wv; nloc = n0 - 1280; N = 256; }
    int tx = threadIdx.x, ty = threadIdx.y;
#pragma unroll
    for (int i = 0; i < 32; i += 8)
        tile[ty + i][tx] = src[(size_t)(k0 + ty + i) * N + nloc + tx] * scale;
    __syncthreads();
#pragma unroll
    for (int i = 0; i < 32; i += 8) {
        int n = n0 + ty + i, k = k0 + tx;
        __nv_bfloat16 h, l;
        split_bf16(tile[tx][ty + i], h, l);
        __nv_bfloat16* row = dst + (size_t)n * GK;
        row[k]         = h;
        row[K + k]     = h;
        row[2 * K + k] = l;
    }
}

// B-side split for wo
__global__ void conv_w(const float* __restrict__ src, __nv_bfloat16* __restrict__ dst,
                       int N) {
    __shared__ float tile[32][33];
    const int K = DMODEL;
    int k0 = blockIdx.y * 32, n0 = blockIdx.x * 32;
    int tx = threadIdx.x, ty = threadIdx.y;
#pragma unroll
    for (int i = 0; i < 32; i += 8)
        tile[ty + i][tx] = src[(size_t)(k0 + ty + i) * N + n0 + tx];
    __syncthreads();
#pragma unroll
    for (int i = 0; i < 32; i += 8) {
        int n = n0 + ty + i, k = k0 + tx;
        __nv_bfloat16 h, l;
        split_bf16(tile[tx][ty + i], h, l);
        __nv_bfloat16* row = dst + (size_t)n * GK;
        row[k]         = h;
        row[K + k]     = h;
        row[2 * K + k] = l;
    }
}

// ---------------------------------------------------------------------------
// bf16 mma.sync GEMM, templated on CTA N-tile width (unchanged from R10).
// ---------------------------------------------------------------------------
#define BMt 128
#define BKt 32
#define PADt 40
#define NCHt (GK/BKt)           // 96
#define STAGES 4
#define GEMM_SMEM_FOR(BN) (STAGES * (BMt + (BN)) * PADt * 2)

template<int BN>
__global__ __launch_bounds__(256, 2) void gemm_mma(const __nv_bfloat16* __restrict__ A,
                                                   const __nv_bfloat16* __restrict__ Bt,
                                                   float* __restrict__ C, int N) {
    constexpr int WN = BN / 4;
    constexpr int NT = WN / 8;
    constexpr int NP = WN / 16;
    constexpr int SEL = (BMt + BN) * PADt;
    constexpr int TOTCH = (BMt + BN) * 4;

    extern __shared__ __nv_bfloat16 gsm[];
    uint32_t smb = smem_u32(gsm);

    int t = threadIdx.x, w = t >> 5, lane = t & 31;
    int m0 = blockIdx.y * BMt, n0 = blockIdx.x * BN;
    int wm = (w >> 2) * 64;
    int wn = (w & 3) * WN;

    float acc[4][NT][4];
#pragma unroll
    for (int i = 0; i < 4; i++)
#pragma unroll
        for (int j = 0; j < NT; j++)
#pragma unroll
            for (int r = 0; r < 4; r++) acc[i][j][r] = 0.f;

    const __nv_bfloat16* Ab = A  + (size_t)m0 * GK;
    const __nv_bfloat16* Bb = Bt + (size_t)n0 * GK;

    auto load_tile = [&](int kc, int s) {
        if (kc < NCHt) {
            uint32_t ab = smb + s * (SEL * 2);
            uint32_t bb = ab + BMt * PADt * 2;
            const __nv_bfloat16* Ak = Ab + kc * BKt;
            const __nv_bfloat16* Bk = Bb + kc * BKt;
#pragma unroll
            for (int i = 0; i < TOTCH / 256; i++) {
                int idx = t + i * 256;
                int row = idx >> 2, ch = idx & 3;
                if (row < BMt)
                    cp16(ab + (row * PADt + ch * 8) * 2, Ak + (size_t)row * GK + ch * 8);
                else {
                    int r = row - BMt;
                    cp16(bb + (r * PADt + ch * 8) * 2, Bk + (size_t)r * GK + ch * 8);
                }
            }
        }
        CP_COMMIT();
    };

#pragma unroll
    for (int s = 0; s < STAGES - 1; s++) load_tile(s, s);

    int li = lane >> 3;
    int lr = lane & 7;

    for (int kc = 0; kc < NCHt; kc++) {
        CP_WAIT(STAGES - 2);
        __syncthreads();
        load_tile(kc + STAGES - 1, (kc + STAGES - 1) % STAGES);

        int s = kc % STAGES;
        uint32_t ab = smb + s * (SEL * 2);
        uint32_t bb = ab + BMt * PADt * 2;

#pragma unroll
        for (int ks = 0; ks < 2; ks++) {
            int k0 = ks * 16;
            uint32_t a[4][4];
#pragma unroll
            for (int mt = 0; mt < 4; mt++) {
                int row = wm + mt * 16 + (li & 1) * 8 + lr;
                int col = k0 + (li >> 1) * 8;
                ldsm4(a[mt][0], a[mt][1], a[mt][2], a[mt][3],
                      ab + (row * PADt + col) * 2);
            }
            uint32_t b[NP][4];
#pragma unroll
            for (int p = 0; p < NP; p++) {
                int row = wn + p * 16 + (li >> 1) * 8 + lr;
                int col = k0 + (li & 1) * 8;
                ldsm4(b[p][0], b[p][1], b[p][2], b[p][3],
                      bb + (row * PADt + col) * 2);
            }
#pragma unroll
            for (int mt = 0; mt < 4; mt++)
#pragma unroll
                for (int nt = 0; nt < NT; nt++) {
                    int p = nt >> 1, off = (nt & 1) * 2;
                    mma16816(acc[mt][nt], a[mt][0], a[mt][1], a[mt][2], a[mt][3],
                             b[p][off], b[p][off + 1]);
                }
        }
    }

    int cr = lane >> 2, cc = (lane & 3) * 2;
#pragma unroll
    for (int mt = 0; mt < 4; mt++)
#pragma unroll
        for (int nt = 0; nt < NT; nt++) {
            float* Cp = C + (size_t)(m0 + wm + mt * 16 + cr) * N + n0 + wn + nt * 8 + cc;
            *(float2*)Cp = make_float2(acc[mt][nt][0], acc[mt][nt][1]);
            *(float2*)(Cp + 8 * (size_t)N) = make_float2(acc[mt][nt][2], acc[mt][nt][3]);
        }
}

// ---------------------------------------------------------------------------
// finish_q / finish_k / finish_v (unchanged)
// ---------------------------------------------------------------------------
__global__ __launch_bounds__(256) void finish_q(const float* __restrict__ qkv,
                                                const float* __restrict__ cosT,
                                                const float* __restrict__ sinT,
                                                __nv_bfloat16* __restrict__ qb) {
    int idx = blockIdx.x * 256 + threadIdx.x;
    const int total = BATCH * SEQ * NH * 32;
    if (idx >= total) return;
    int j = idx & 31;
    int rest = idx >> 5;
    int h = rest % NH;
    int row = rest / NH;
    int s = row % SEQ, b = row / SEQ;

    const float* src = qkv + (size_t)row * NQKV + h * 64;
    float c  = cosT[s * 32 + j];
    float sn = sinT[s * 32 + j];
    float x1 = src[j], x2 = src[j + 32];
    float y1 = x1 * c - x2 * sn;
    float y2 = x2 * c + x1 * sn;

    __nv_bfloat16 h1, l1, h2, l2;
    split_bf16(y1, h1, l1);
    split_bf16(y2, h2, l2);
    __nv_bfloat16* d = qb + ((size_t)(b * NH + h) * SEQ + s) * 128;
    d[j]       = h1;  d[j + 32]  = h2;   // hi
    d[64 + j]  = l1;  d[96 + j]  = l2;   // lo
}

__global__ __launch_bounds__(256) void finish_k(const float* __restrict__ qkv,
                                                const float* __restrict__ cosT,
                                                const float* __restrict__ sinT,
                                                float* __restrict__ kout,
                                                __nv_bfloat16* __restrict__ kb) {
    int idx = blockIdx.x * 256 + threadIdx.x;
    const int total = BATCH * SEQ * NKV * 32;
    if (idx >= total) return;
    int j = idx & 31;
    int rest = idx >> 5;
    int kvh = rest % NKV;
    int row = rest / NKV;
    int s = row % SEQ, b = row / SEQ;

    const float* src = qkv + (size_t)row * NQKV + 1024 + kvh * 64;
    float c  = cosT[s * 32 + j];
    float sn = sinT[s * 32 + j];
    float x1 = src[j], x2 = src[j + 32];
    float y1 = x1 * c - x2 * sn;
    float y2 = x2 * c + x1 * sn;

    float* ko = kout + ((size_t)row * NKV + kvh) * 64;
    ko[j] = y1;
    ko[j + 32] = y2;

    __nv_bfloat16 h1, l1, h2, l2;
    split_bf16(y1, h1, l1);
    split_bf16(y2, h2, l2);
    __nv_bfloat16* d = kb + ((size_t)(b * NKV + kvh) * SEQ + s) * 128;
    d[j]       = h1;  d[j + 32]  = h2;   // hi
    d[64 + j]  = l1;  d[96 + j]  = l2;   // lo
}

__global__ void finish_v(const float* __restrict__ qkv,
                         float* __restrict__ vout,
                         __nv_bfloat16* __restrict__ vhi,
                         __nv_bfloat16* __restrict__ vlo) {
    __shared__ float tile[32][33];
    int bkv = blockIdx.z;
    int b = bkv / NKV, kvh = bkv % NKV;
    int s0 = blockIdx.x * 32, d0 = blockIdx.y * 32;
    int tx = threadIdx.x, ty = threadIdx.y;
#pragma unroll
    for (int i = 0; i < 32; i += 8) {
        int s = s0 + ty + i;
        float v = qkv[((size_t)b * SEQ + s) * NQKV + 1280 + kvh * 64 + d0 + tx];
        tile[ty + i][tx] = v;
        vout[(((size_t)b * SEQ + s) * NKV + kvh) * 64 + d0 + tx] = v;
    }
    __syncthreads();
#pragma unroll
    for (int i = 0; i < 32; i += 8) {
        int d = d0 + ty + i, s = s0 + tx;
        __nv_bfloat16 h, l;
        split_bf16(tile[tx][ty + i], h, l);
        size_t off = ((size_t)bkv * HD + d) * SEQ + s;
        vhi[off] = h;
        vlo[off] = l;
    }
}

// ---------------------------------------------------------------------------
// Tensor-core flash attention, compact [hi|lo] operands, SOFTWARE-PIPELINED:
// K(kt+1) issued after mid-tile sync (overlaps PV), V(kt+1) issued after
// end-of-tile sync (overlaps next S). Same buffers, 4 CTAs/SM.
// ---------------------------------------------------------------------------
#define APAD 136
#define ATTN2_SMEM (3 * 64 * APAD * 2)

__global__ __launch_bounds__(128) void attn_mma(const __nv_bfloat16* __restrict__ Qb,
                                                const __nv_bfloat16* __restrict__ Kb,
                                                const __nv_bfloat16* __restrict__ Vhi,
                                                const __nv_bfloat16* __restrict__ Vlo,
                                                __nv_bfloat16* __restrict__ aoc) {
    extern __shared__ __nv_bfloat16 sb[];
    __nv_bfloat16* qs = sb;
    __nv_bfloat16* ks = sb + 64 * APAD;
    __nv_bfloat16* vs = sb + 2 * 64 * APAD;
    uint32_t qsa = smem_u32(qs), ksa = smem_u32(ks), vsa = smem_u32(vs);

    int t = threadIdx.x, w = t >> 5, lane = t & 31;
    int qt = gridDim.x - 1 - blockIdx.x;   // longest CTAs first
    int h = blockIdx.y, b = blockIdx.z;
    int kvh = h >> 2;
    int li = lane >> 3, lr = lane & 7;
    int r0 = lane >> 2;
    int cc = (lane & 3) * 2;

    const __nv_bfloat16* ksrc0 = Kb + (size_t)(b * NKV + kvh) * SEQ * 128;
    const __nv_bfloat16* vh0 = Vhi + (size_t)(b * NKV + kvh) * HD * SEQ;
    const __nv_bfloat16* vl0 = Vlo + (size_t)(b * NKV + kvh) * HD * SEQ;

    auto issueK = [&](int kt) {
        const __nv_bfloat16* ksrc = ksrc0 + (size_t)kt * 64 * 128;
#pragma unroll
        for (int i = 0; i < 8; i++) {
            int c = t + 128 * i;
            int row = c >> 4, seg = c & 15;
            cp16(ksa + (row * APAD + seg * 8) * 2, ksrc + (size_t)row * 128 + seg * 8);
        }
        CP_COMMIT();
    };
    auto issueV = [&](int kt) {
#pragma unroll
        for (int i = 0; i < 8; i++) {
            int c = t + 128 * i;
            int d = c >> 4, seg = c & 15;
            const __nv_bfloat16* src = (seg < 8 ? vh0 : vl0)
                                       + (size_t)d * SEQ + kt * 64 + (seg & 7) * 8;
            cp16(vsa + (d * APAD + seg * 8) * 2, src);
        }
        CP_COMMIT();
    };

    // Prologue: Q tile, then K(0), V(0)
    const __nv_bfloat16* qsrc = Qb + ((size_t)(b * NH + h) * SEQ + (size_t)qt * 64) * 128;
#pragma unroll
    for (int i = 0; i < 8; i++) {
        int c = t + 128 * i;
        int row = c >> 4, seg = c & 15;
        cp16(qsa + (row * APAD + seg * 8) * 2, qsrc + (size_t)row * 128 + seg * 8);
    }
    CP_COMMIT();
    issueK(0);
    issueV(0);

    float m0 = -1e30f, m1 = -1e30f, l0 = 0.f, l1 = 0.f;
    float of[8][4];
#pragma unroll
    for (int j = 0; j < 8; j++)
#pragma unroll
        for (int e = 0; e < 4; e++) of[j][e] = 0.f;

    for (int kt = 0; kt <= qt; kt++) {
        CP_WAIT(1);         // Q + K(kt) landed; V(kt) may be in flight
        __syncthreads();

        // ---- S = Q' K'^T: ksteps 0-3 Qhi.Khi, 4-7 Qlo.Khi, 8-11 Qhi.Klo ----
        float sf[8][4];
#pragma unroll
        for (int j = 0; j < 8; j++)
#pragma unroll
            for (int e = 0; e < 4; e++) sf[j][e] = 0.f;
#pragma unroll
        for (int ks12 = 0; ks12 < 12; ks12++) {
            int aCol = (ks12 < 8 ? ks12 : ks12 - 8) * 16;
            int bCol = (ks12 < 4 ? ks12 * 16 : (ks12 < 8 ? (ks12 - 4) * 16
                                                          : 64 + (ks12 - 8) * 16));
            uint32_t a0, a1, a2, a3;
            ldsm4(a0, a1, a2, a3,
                  qsa + ((w * 16 + (li & 1) * 8 + lr) * APAD + aCol + (li >> 1) * 8) * 2);
#pragma unroll
            for (int p = 0; p < 4; p++) {
                uint32_t b0, b1, b2, b3;
                ldsm4(b0, b1, b2, b3,
                      ksa + ((p * 16 + (li >> 1) * 8 + lr) * APAD + bCol + (li & 1) * 8) * 2);
                mma16816(sf[2 * p],     a0, a1, a2, a3, b0, b1);
                mma16816(sf[2 * p + 1], a0, a1, a2, a3, b2, b3);
            }
        }

        if (kt == qt) {
            int q0 = w * 16 + r0, q1 = q0 + 8;
#pragma unroll
            for (int j = 0; j < 8; j++) {
                int key = 8 * j + cc;
                if (key     > q0) sf[j][0] = -1e30f;
                if (key + 1 > q0) sf[j][1] = -1e30f;
                if (key     > q1) sf[j][2] = -1e30f;
                if (key + 1 > q1) sf[j][3] = -1e30f;
            }
        }

        // ---- online softmax ----
        float mx0 = -1e30f, mx1 = -1e30f;
#pragma unroll
        for (int j = 0; j < 8; j++) {
            mx0 = fmaxf(mx0, fmaxf(sf[j][0], sf[j][1]));
            mx1 = fmaxf(mx1, fmaxf(sf[j][2], sf[j][3]));
        }
        mx0 = fmaxf(mx0, __shfl_xor_sync(0xffffffffu, mx0, 1));
        mx0 = fmaxf(mx0, __shfl_xor_sync(0xffffffffu, mx0, 2));
        mx1 = fmaxf(mx1, __shfl_xor_sync(0xffffffffu, mx1, 1));
        mx1 = fmaxf(mx1, __shfl_xor_sync(0xffffffffu, mx1, 2));
        float nm0 = fmaxf(m0, mx0), nm1 = fmaxf(m1, mx1);
        float al0 = __expf(m0 - nm0), al1 = __expf(m1 - nm1);
        m0 = nm0; m1 = nm1;

        float s0 = 0.f, s1 = 0.f;
#pragma unroll
        for (int j = 0; j < 8; j++) {
            sf[j][0] = __expf(sf[j][0] - m0); s0 += sf[j][0];
            sf[j][1] = __expf(sf[j][1] - m0); s0 += sf[j][1];
            sf[j][2] = __expf(sf[j][2] - m1); s1 += sf[j][2];
            sf[j][3] = __expf(sf[j][3] - m1); s1 += sf[j][3];
        }
        s0 += __shfl_xor_sync(0xffffffffu, s0, 1);
        s0 += __shfl_xor_sync(0xffffffffu, s0, 2);
        s1 += __shfl_xor_sync(0xffffffffu, s1, 1);
        s1 += __shfl_xor_sync(0xffffffffu, s1, 2);
        l0 = l0 * al0 + s0;
        l1 = l1 * al1 + s1;

#pragma unroll
        for (int j = 0; j < 8; j++) {
            of[j][0] *= al0; of[j][1] *= al0;
            of[j][2] *= al1; of[j][3] *= al1;
        }

        // ---- split P into bf16 A-fragments ----
        uint32_t ah[4][4], alf[4][4];
#pragma unroll
        for (int kk = 0; kk < 4; kk++) {
            float c00 = sf[2 * kk][0], c01 = sf[2 * kk][1];
            float c02 = sf[2 * kk][2], c03 = sf[2 * kk][3];
            float c10 = sf[2 * kk + 1][0], c11 = sf[2 * kk + 1][1];
            float c12 = sf[2 * kk + 1][2], c13 = sf[2 * kk + 1][3];
            uint32_t h0 = pack_bf16(c00, c01), h1 = pack_bf16(c02, c03);
            uint32_t h2 = pack_bf16(c10, c11), h3 = pack_bf16(c12, c13);
            ah[kk][0] = h0; ah[kk][1] = h1; ah[kk][2] = h2; ah[kk][3] = h3;
            __nv_bfloat162 b0 = *(__nv_bfloat162*)&h0;
            __nv_bfloat162 b1 = *(__nv_bfloat162*)&h1;
            __nv_bfloat162 b2 = *(__nv_bfloat162*)&h2;
            __nv_bfloat162 b3 = *(__nv_bfloat162*)&h3;
            alf[kk][0] = pack_bf16(c00 - __bfloat162float(b0.x), c01 - __bfloat162float(b0.y));
            alf[kk][1] = pack_bf16(c02 - __bfloat162float(b1.x), c03 - __bfloat162float(b1.y));
            alf[kk][2] = pack_bf16(c10 - __bfloat162float(b2.x), c11 - __bfloat162float(b2.y));
            alf[kk][3] = pack_bf16(c12 - __bfloat162float(b3.x), c13 - __bfloat162float(b3.y));
        }

        CP_WAIT(0);          // V(kt) landed (all outstanding groups done)
        __syncthreads();     // all warps done with ks reads; vs visible

        // ks is now dead for this tile: prefetch K(kt+1), overlapping PV
        if (kt < qt) issueK(kt + 1);

        // ---- O += P' V': Phi*Vhi, Plo*Vhi, Phi*Vlo ----
#pragma unroll
        for (int ks12 = 0; ks12 < 12; ks12++) {
            int kk = ks12 & 3, sel = ks12 >> 2;
            uint32_t* A = (sel == 1) ? alf[kk] : ah[kk];
            int k0 = (sel == 2 ? 64 : 0) + kk * 16;
#pragma unroll
            for (int p = 0; p < 4; p++) {
                uint32_t b0, b1, b2, b3;
                ldsm4(b0, b1, b2, b3,
                      vsa + ((p * 16 + (li >> 1) * 8 + lr) * APAD + k0 + (li & 1) * 8) * 2);
                mma16816(of[2 * p],     A[0], A[1], A[2], A[3], b0, b1);
                mma16816(of[2 * p + 1], A[0], A[1], A[2], A[3], b2, b3);
            }
        }
        __syncthreads();     // all warps done with vs reads

        // vs is now dead: prefetch V(kt+1), overlapping next tile's S phase
        if (kt < qt) issueV(kt + 1);
    }

    // ---- epilogue: write split [hi|lo|hi] directly into aoc ----
    float inv0 = 1.f / l0, inv1 = 1.f / l1;
    int row0 = b * SEQ + qt * 64 + w * 16 + r0;
    int row1 = row0 + 8;
#pragma unroll
    for (int j = 0; j < 8; j++) {
        int colq = h * 64 + 8 * j + cc;
        {
            float v0 = of[j][0] * inv0, v1 = of[j][1] * inv0;
            uint32_t hp = pack_bf16(v0, v1);
            __nv_bfloat162 hb = *(__nv_bfloat162*)&hp;
            uint32_t lp = pack_bf16(v0 - __bfloat162float(hb.x), v1 - __bfloat162float(hb.y));
            uint32_t* base = (uint32_t*)(aoc + (size_t)row0 * GK + colq);
            base[0]              = hp;
            *(uint32_t*)((char*)base + 1024 * 2) = lp;
            *(uint32_t*)((char*)base + 2048 * 2) = hp;
        }
        {
            float v0 = of[j][2] * inv1, v1 = of[j][3] * inv1;
            uint32_t hp = pack_bf16(v0, v1);
            __nv_bfloat162 hb = *(__nv_bfloat162*)&hp;
            uint32_t lp = pack_bf16(v0 - __bfloat162float(hb.x), v1 - __bfloat162float(hb.y));
            uint32_t* base = (uint32_t*)(aoc + (size_t)row1 * GK + colq);
            base[0]              = hp;
            *(uint32_t*)((char*)base + 1024 * 2) = lp;
            *(uint32_t*)((char*)base + 2048 * 2) = hp;
        }
    }
}

// ---------------------------------------------------------------------------
extern "C" void kernel_launch(void* const* d_in, const int* in_sizes, int n_in,
                              void* d_out, int out_size) {
    const float* x    = (const float*)d_in[0];
    const float* cosT = (const float*)d_in[1];
    const float* sinT = (const float*)d_in[2];
    // d_in[3] = mask: unused
    const float* wq   = (const float*)d_in[4];
    const float* wk   = (const float*)d_in[5];
    const float* wv   = (const float*)d_in[6];
    const float* wo   = (const float*)d_in[7];

    float* out  = (float*)d_out;
    float* kout = out + OUT_ELEMS;
    float* vout = out + OUT_ELEMS + KV_ELEMS;

    float* qkv;
    __nv_bfloat16 *xc, *aoc, *wqkvt, *wot, *qb, *kb, *vhi, *vlo;
    cudaGetSymbolAddress((void**)&qkv, g_qkv);
    cudaGetSymbolAddress((void**)&xc,  g_xc);
    cudaGetSymbolAddress((void**)&aoc, g_aoc);
    cudaGetSymbolAddress((void**)&wqkvt, g_wqkvt);
    cudaGetSymbolAddress((void**)&wot, g_wot);
    cudaGetSymbolAddress((void**)&qb,  g_qb);
    cudaGetSymbolAddress((void**)&kb,  g_kb);
    cudaGetSymbolAddress((void**)&vhi, g_vhi);
    cudaGetSymbolAddress((void**)&vlo, g_vlo);

    cudaFuncSetAttribute(attn_mma, cudaFuncAttributeMaxDynamicSharedMemorySize, ATTN2_SMEM);
    cudaFuncSetAttribute(gemm_mma<128>, cudaFuncAttributeMaxDynamicSharedMemorySize,
                         GEMM_SMEM_FOR(128));
    cudaFuncSetAttribute(gemm_mma<192>, cudaFuncAttributeMaxDynamicSharedMemorySize,
                         GEMM_SMEM_FOR(192));

    // Split conversions
    conv_a<<<(MTOT * DMODEL / 4 + 255) / 256, 256>>>(x, xc);
    dim3 wb(32, 8);
    conv_qkv<<<dim3(NQKV / 32, DMODEL / 32), wb>>>(wq, wk, wv, wqkvt);
    conv_w<<<dim3(DMODEL / 32, DMODEL / 32), wb>>>(wo, wot, DMODEL);

    // Fused QKV projection: 128x192 tiles -> 256 CTAs = single wave
    gemm_mma<192><<<dim3(NQKV / 192, MTOT / 128), 256, GEMM_SMEM_FOR(192)>>>(
        xc, wqkvt, qkv, NQKV);

    // RoPE + compact split + fp32 kv-cache outputs
    finish_q<<<(BATCH * SEQ * NH * 32 + 255) / 256, 256>>>(qkv, cosT, sinT, qb);
    finish_k<<<(BATCH * SEQ * NKV * 32 + 255) / 256, 256>>>(qkv, cosT, sinT, kout, kb);
    finish_v<<<dim3(SEQ / 32, HD / 32, BATCH * NKV), dim3(32, 8)>>>(qkv, vout, vhi, vlo);

    // Tensor-core flash attention (pipelined K/V prefetch, 4 CTAs/SM)
    attn_mma<<<dim3(SEQ / 64, NH, BATCH), 128, ATTN2_SMEM>>>(qb, kb, vhi, vlo, aoc);

    // Output projection
    gemm_mma<128><<<dim3(DMODEL / 128, MTOT / 128), 256, GEMM_SMEM_FOR(128)>>>(
        aoc, wot, out, DMODEL);
}

// round 13
// speedup vs baseline: 1.1414x; 1.0675x over previous
#include <cuda_runtime.h>
#include <cuda_bf16.h>
#include <cuda_fp16.h>
#include <cstdint>

// Problem constants
#define BATCH 2
#define SEQ 2048
#define DMODEL 1024
#define NH 16
#define NKV 4
#define HD 64
#define OUT_ELEMS  (BATCH*SEQ*DMODEL)
#define KV_ELEMS   (BATCH*SEQ*NKV*HD)

#define MTOT (BATCH*SEQ)        // 4096
#define GK   (3*DMODEL)         // 3072 split-K (hi|lo|hi vs hi|hi|lo)
#define NQKV 1536               // fused QKV output width

// ---------------------------------------------------------------------------
// Scratch (device globals; no runtime allocation allowed)
// ---------------------------------------------------------------------------
__device__ float g_qkv[MTOT*NQKV];                   // fused QKV gemm output
__device__ __nv_bfloat16 g_xc   [MTOT*GK];           // x split [M, 3K]
__device__ __nv_bfloat16 g_aoc  [MTOT*GK];           // attn out split [M, 3K]
__device__ __nv_bfloat16 g_wqkvt[NQKV*GK];           // [wq|wk|wv]^T split
__device__ __nv_bfloat16 g_wot  [DMODEL*GK];
// Attention operands
__device__ __nv_bfloat16 g_qb [BATCH*NH*SEQ*128];    // [b][h][s][hi|lo]
__device__ __nv_bfloat16 g_kb [BATCH*NKV*SEQ*128];   // [b][kvh][s][hi|lo]
__device__ __half        g_vf [BATCH*NKV*HD*SEQ];    // [b][kvh][d][s] fp16

// ---------------------------------------------------------------------------
// Baseline-PTX helpers
// ---------------------------------------------------------------------------
__device__ __forceinline__ uint32_t smem_u32(const void* p) {
    uint32_t a;
    asm("{ .reg .u64 t; cvta.to.shared.u64 t, %1; cvt.u32.u64 %0, t; }" : "=r"(a) : "l"(p));
    return a;
}
__device__ __forceinline__ void cp16(uint32_t saddr, const void* g) {
    asm volatile("cp.async.cg.shared.global [%0], [%1], 16;" :: "r"(saddr), "l"(g) : "memory");
}
#define CP_COMMIT() asm volatile("cp.async.commit_group;" ::: "memory")
#define CP_WAIT(n)  asm volatile("cp.async.wait_group %0;" :: "n"(n) : "memory")

__device__ __forceinline__ void ldsm4(uint32_t& r0, uint32_t& r1, uint32_t& r2, uint32_t& r3,
                                      uint32_t a) {
    asm volatile("ldmatrix.sync.aligned.m8n8.x4.shared.b16 {%0,%1,%2,%3}, [%4];"
                 : "=r"(r0), "=r"(r1), "=r"(r2), "=r"(r3) : "r"(a));
}
__device__ __forceinline__ void mma16816(float* c, uint32_t a0, uint32_t a1, uint32_t a2,
                                         uint32_t a3, uint32_t b0, uint32_t b1) {
    asm volatile(
        "mma.sync.aligned.m16n8k16.row.col.f32.bf16.bf16.f32 "
        "{%0,%1,%2,%3},{%4,%5,%6,%7},{%8,%9},{%0,%1,%2,%3};"
        : "+f"(c[0]), "+f"(c[1]), "+f"(c[2]), "+f"(c[3])
        : "r"(a0), "r"(a1), "r"(a2), "r"(a3), "r"(b0), "r"(b1));
}
__device__ __forceinline__ void mma16816h(float* c, uint32_t a0, uint32_t a1, uint32_t a2,
                                          uint32_t a3, uint32_t b0, uint32_t b1) {
    asm volatile(
        "mma.sync.aligned.m16n8k16.row.col.f32.f16.f16.f32 "
        "{%0,%1,%2,%3},{%4,%5,%6,%7},{%8,%9},{%0,%1,%2,%3};"
        : "+f"(c[0]), "+f"(c[1]), "+f"(c[2]), "+f"(c[3])
        : "r"(a0), "r"(a1), "r"(a2), "r"(a3), "r"(b0), "r"(b1));
}
__device__ __forceinline__ uint32_t pack_bf16(float x, float y) {
    uint32_t r;
    asm("cvt.rn.bf16x2.f32 %0, %1, %2;" : "=r"(r) : "f"(y), "f"(x));
    return r;
}
__device__ __forceinline__ uint32_t pack_f16(float x, float y) {
    uint32_t r;
    asm("cvt.rn.f16x2.f32 %0, %1, %2;" : "=r"(r) : "f"(y), "f"(x));
    return r;
}
__device__ __forceinline__ void split_bf16(float v, __nv_bfloat16& hi, __nv_bfloat16& lo) {
    hi = __float2bfloat16(v);
    lo = __float2bfloat16(v - __bfloat162float(hi));
}

// ---------------------------------------------------------------------------
// A-side split: src [M, K] fp32 -> dst [M, 3K] = [hi | lo | hi]
// ---------------------------------------------------------------------------
__global__ __launch_bounds__(256) void conv_a(const float* __restrict__ src,
                                              __nv_bfloat16* __restrict__ dst) {
    int idx = blockIdx.x * blockDim.x + threadIdx.x;
    const int K = DMODEL;
    if (idx >= MTOT * K / 4) return;
    int flat = idx * 4;
    int m = flat / K, k = flat % K;
    float4 v = *(const float4*)(src + flat);
    float vv[4] = {v.x, v.y, v.z, v.w};
    __nv_bfloat16 h[4], l[4];
#pragma unroll
    for (int j = 0; j < 4; j++) split_bf16(vv[j], h[j], l[j]);
    __nv_bfloat16* row = dst + (size_t)m * GK;
    *(uint2*)(row + k)         = *(uint2*)h;
    *(uint2*)(row + K + k)     = *(uint2*)l;
    *(uint2*)(row + 2 * K + k) = *(uint2*)h;
}

// Fused weight split for [wq|wk|wv] -> wqkvt [1536, 3K]
__global__ void conv_qkv(const float* __restrict__ wq, const float* __restrict__ wk,
                         const float* __restrict__ wv, __nv_bfloat16* __restrict__ dst) {
    __shared__ float tile[32][33];
    const int K = DMODEL;
    int k0 = blockIdx.y * 32, n0 = blockIdx.x * 32;
    const float* src;
    int nloc, N;
    float scale = 1.f;
    if (n0 < 1024)      { src = wq; nloc = n0;        N = 1024; scale = 0.125f; }
    else if (n0 < 1280) { src = wk; nloc = n0 - 1024; N = 256; }
    else                { src = wv; nloc = n0 - 1280; N = 256; }
    int tx = threadIdx.x, ty = threadIdx.y;
#pragma unroll
    for (int i = 0; i < 32; i += 8)
        tile[ty + i][tx] = src[(size_t)(k0 + ty + i) * N + nloc + tx] * scale;
    __syncthreads();
#pragma unroll
    for (int i = 0; i < 32; i += 8) {
        int n = n0 + ty + i, k = k0 + tx;
        __nv_bfloat16 h, l;
        split_bf16(tile[tx][ty + i], h, l);
        __nv_bfloat16* row = dst + (size_t)n * GK;
        row[k]         = h;
        row[K + k]     = h;
        row[2 * K + k] = l;
    }
}

// B-side split for wo
__global__ void conv_w(const float* __restrict__ src, __nv_bfloat16* __restrict__ dst,
                       int N) {
    __shared__ float tile[32][33];
    const int K = DMODEL;
    int k0 = blockIdx.y * 32, n0 = blockIdx.x * 32;
    int tx = threadIdx.x, ty = threadIdx.y;
#pragma unroll
    for (int i = 0; i < 32; i += 8)
        tile[ty + i][tx] = src[(size_t)(k0 + ty + i) * N + n0 + tx];
    __syncthreads();
#pragma unroll
    for (int i = 0; i < 32; i += 8) {
        int n = n0 + ty + i, k = k0 + tx;
        __nv_bfloat16 h, l;
        split_bf16(tile[tx][ty + i], h, l);
        __nv_bfloat16* row = dst + (size_t)n * GK;
        row[k]         = h;
        row[K + k]     = h;
        row[2 * K + k] = l;
    }
}

// ---------------------------------------------------------------------------
// bf16 mma.sync GEMM, templated on CTA N-tile width (unchanged from R10).
// ---------------------------------------------------------------------------
#define BMt 128
#define BKt 32
#define PADt 40
#define NCHt (GK/BKt)           // 96
#define STAGES 4
#define GEMM_SMEM_FOR(BN) (STAGES * (BMt + (BN)) * PADt * 2)

template<int BN>
__global__ __launch_bounds__(256, 2) void gemm_mma(const __nv_bfloat16* __restrict__ A,
                                                   const __nv_bfloat16* __restrict__ Bt,
                                                   float* __restrict__ C, int N) {
    constexpr int WN = BN / 4;
    constexpr int NT = WN / 8;
    constexpr int NP = WN / 16;
    constexpr int SEL = (BMt + BN) * PADt;
    constexpr int TOTCH = (BMt + BN) * 4;

    extern __shared__ __nv_bfloat16 gsm[];
    uint32_t smb = smem_u32(gsm);

    int t = threadIdx.x, w = t >> 5, lane = t & 31;
    int m0 = blockIdx.y * BMt, n0 = blockIdx.x * BN;
    int wm = (w >> 2) * 64;
    int wn = (w & 3) * WN;

    float acc[4][NT][4];
#pragma unroll
    for (int i = 0; i < 4; i++)
#pragma unroll
        for (int j = 0; j < NT; j++)
#pragma unroll
            for (int r = 0; r < 4; r++) acc[i][j][r] = 0.f;

    const __nv_bfloat16* Ab = A  + (size_t)m0 * GK;
    const __nv_bfloat16* Bb = Bt + (size_t)n0 * GK;

    auto load_tile = [&](int kc, int s) {
        if (kc < NCHt) {
            uint32_t ab = smb + s * (SEL * 2);
            uint32_t bb = ab + BMt * PADt * 2;
            const __nv_bfloat16* Ak = Ab + kc * BKt;
            const __nv_bfloat16* Bk = Bb + kc * BKt;
#pragma unroll
            for (int i = 0; i < TOTCH / 256; i++) {
                int idx = t + i * 256;
                int row = idx >> 2, ch = idx & 3;
                if (row < BMt)
                    cp16(ab + (row * PADt + ch * 8) * 2, Ak + (size_t)row * GK + ch * 8);
                else {
                    int r = row - BMt;
                    cp16(bb + (r * PADt + ch * 8) * 2, Bk + (size_t)r * GK + ch * 8);
                }
            }
        }
        CP_COMMIT();
    };

#pragma unroll
    for (int s = 0; s < STAGES - 1; s++) load_tile(s, s);

    int li = lane >> 3;
    int lr = lane & 7;

    for (int kc = 0; kc < NCHt; kc++) {
        CP_WAIT(STAGES - 2);
        __syncthreads();
        load_tile(kc + STAGES - 1, (kc + STAGES - 1) % STAGES);

        int s = kc % STAGES;
        uint32_t ab = smb + s * (SEL * 2);
        uint32_t bb = ab + BMt * PADt * 2;

#pragma unroll
        for (int ks = 0; ks < 2; ks++) {
            int k0 = ks * 16;
            uint32_t a[4][4];
#pragma unroll
            for (int mt = 0; mt < 4; mt++) {
                int row = wm + mt * 16 + (li & 1) * 8 + lr;
                int col = k0 + (li >> 1) * 8;
                ldsm4(a[mt][0], a[mt][1], a[mt][2], a[mt][3],
                      ab + (row * PADt + col) * 2);
            }
            uint32_t b[NP][4];
#pragma unroll
            for (int p = 0; p < NP; p++) {
                int row = wn + p * 16 + (li >> 1) * 8 + lr;
                int col = k0 + (li & 1) * 8;
                ldsm4(b[p][0], b[p][1], b[p][2], b[p][3],
                      bb + (row * PADt + col) * 2);
            }
#pragma unroll
            for (int mt = 0; mt < 4; mt++)
#pragma unroll
                for (int nt = 0; nt < NT; nt++) {
                    int p = nt >> 1, off = (nt & 1) * 2;
                    mma16816(acc[mt][nt], a[mt][0], a[mt][1], a[mt][2], a[mt][3],
                             b[p][off], b[p][off + 1]);
                }
        }
    }

    int cr = lane >> 2, cc = (lane & 3) * 2;
#pragma unroll
    for (int mt = 0; mt < 4; mt++)
#pragma unroll
        for (int nt = 0; nt < NT; nt++) {
            float* Cp = C + (size_t)(m0 + wm + mt * 16 + cr) * N + n0 + wn + nt * 8 + cc;
            *(float2*)Cp = make_float2(acc[mt][nt][0], acc[mt][nt][1]);
            *(float2*)(Cp + 8 * (size_t)N) = make_float2(acc[mt][nt][2], acc[mt][nt][3]);
        }
}

// ---------------------------------------------------------------------------
// finish_q / finish_k: RoPE + compact [hi|lo] split (128 cols)
// ---------------------------------------------------------------------------
__global__ __launch_bounds__(256) void finish_q(const float* __restrict__ qkv,
                                                const float* __restrict__ cosT,
                                                const float* __restrict__ sinT,
                                                __nv_bfloat16* __restrict__ qb) {
    int idx = blockIdx.x * 256 + threadIdx.x;
    const int total = BATCH * SEQ * NH * 32;
    if (idx >= total) return;
    int j = idx & 31;
    int rest = idx >> 5;
    int h = rest % NH;
    int row = rest / NH;
    int s = row % SEQ, b = row / SEQ;

    const float* src = qkv + (size_t)row * NQKV + h * 64;
    float c  = cosT[s * 32 + j];
    float sn = sinT[s * 32 + j];
    float x1 = src[j], x2 = src[j + 32];
    float y1 = x1 * c - x2 * sn;
    float y2 = x2 * c + x1 * sn;

    __nv_bfloat16 h1, l1, h2, l2;
    split_bf16(y1, h1, l1);
    split_bf16(y2, h2, l2);
    __nv_bfloat16* d = qb + ((size_t)(b * NH + h) * SEQ + s) * 128;
    d[j]       = h1;  d[j + 32]  = h2;   // hi
    d[64 + j]  = l1;  d[96 + j]  = l2;   // lo
}

__global__ __launch_bounds__(256) void finish_k(const float* __restrict__ qkv,
                                                const float* __restrict__ cosT,
                                                const float* __restrict__ sinT,
                                                float* __restrict__ kout,
                                                __nv_bfloat16* __restrict__ kb) {
    int idx = blockIdx.x * 256 + threadIdx.x;
    const int total = BATCH * SEQ * NKV * 32;
    if (idx >= total) return;
    int j = idx & 31;
    int rest = idx >> 5;
    int kvh = rest % NKV;
    int row = rest / NKV;
    int s = row % SEQ, b = row / SEQ;

    const float* src = qkv + (size_t)row * NQKV + 1024 + kvh * 64;
    float c  = cosT[s * 32 + j];
    float sn = sinT[s * 32 + j];
    float x1 = src[j], x2 = src[j + 32];
    float y1 = x1 * c - x2 * sn;
    float y2 = x2 * c + x1 * sn;

    float* ko = kout + ((size_t)row * NKV + kvh) * 64;
    ko[j] = y1;
    ko[j + 32] = y2;

    __nv_bfloat16 h1, l1, h2, l2;
    split_bf16(y1, h1, l1);
    split_bf16(y2, h2, l2);
    __nv_bfloat16* d = kb + ((size_t)(b * NKV + kvh) * SEQ + s) * 128;
    d[j]       = h1;  d[j + 32]  = h2;   // hi
    d[64 + j]  = l1;  d[96 + j]  = l2;   // lo
}

// finish_v: fp32 new_v to d_out + transposed single-fp16 V
__global__ void finish_v(const float* __restrict__ qkv,
                         float* __restrict__ vout,
                         __half* __restrict__ vf) {
    __shared__ float tile[32][33];
    int bkv = blockIdx.z;
    int b = bkv / NKV, kvh = bkv % NKV;
    int s0 = blockIdx.x * 32, d0 = blockIdx.y * 32;
    int tx = threadIdx.x, ty = threadIdx.y;
#pragma unroll
    for (int i = 0; i < 32; i += 8) {
        int s = s0 + ty + i;
        float v = qkv[((size_t)b * SEQ + s) * NQKV + 1280 + kvh * 64 + d0 + tx];
        tile[ty + i][tx] = v;
        vout[(((size_t)b * SEQ + s) * NKV + kvh) * 64 + d0 + tx] = v;
    }
    __syncthreads();
#pragma unroll
    for (int i = 0; i < 32; i += 8) {
        int d = d0 + ty + i, s = s0 + tx;
        vf[((size_t)bkv * HD + d) * SEQ + s] = __float2half(tile[tx][ty + i]);
    }
}

// ---------------------------------------------------------------------------
// Tensor-core flash attention.
// S: bf16 3-term split (12 ksteps, unchanged).
// PV: fp16 2-term — P split to fp16 (hi, lo), V single fp16 (8 ksteps).
// Smem: qs/ks 64x136 bf16 + vs 64x72 fp16 = 44 KB -> 4+ CTAs/SM.
// ---------------------------------------------------------------------------
#define APAD 136
#define VPAD2 72
#define ATTN2_SMEM ((2 * 64 * APAD + 64 * VPAD2) * 2)

__global__ __launch_bounds__(128) void attn_mma(const __nv_bfloat16* __restrict__ Qb,
                                                const __nv_bfloat16* __restrict__ Kb,
                                                const __half* __restrict__ Vf,
                                                __nv_bfloat16* __restrict__ aoc) {
    extern __shared__ __nv_bfloat16 sb[];
    __nv_bfloat16* qs = sb;
    __nv_bfloat16* ks = sb + 64 * APAD;
    __half*        vs = (__half*)(sb + 2 * 64 * APAD);
    uint32_t qsa = smem_u32(qs), ksa = smem_u32(ks), vsa = smem_u32(vs);

    int t = threadIdx.x, w = t >> 5, lane = t & 31;
    int qt = gridDim.x - 1 - blockIdx.x;   // longest CTAs first
    int h = blockIdx.y, b = blockIdx.z;
    int kvh = h >> 2;
    int li = lane >> 3, lr = lane & 7;
    int r0 = lane >> 2;
    int cc = (lane & 3) * 2;

    const __nv_bfloat16* ksrc0 = Kb + (size_t)(b * NKV + kvh) * SEQ * 128;
    const __half* vf0 = Vf + (size_t)(b * NKV + kvh) * HD * SEQ;

    auto issueK = [&](int kt) {
        const __nv_bfloat16* ksrc = ksrc0 + (size_t)kt * 64 * 128;
#pragma unroll
        for (int i = 0; i < 8; i++) {
            int c = t + 128 * i;
            int row = c >> 4, seg = c & 15;
            cp16(ksa + (row * APAD + seg * 8) * 2, ksrc + (size_t)row * 128 + seg * 8);
        }
        CP_COMMIT();
    };
    auto issueV = [&](int kt) {
#pragma unroll
        for (int i = 0; i < 4; i++) {
            int c = t + 128 * i;          // 512 chunks: 64 rows x 8 chunks
            int d = c >> 3, seg = c & 7;
            cp16(vsa + (d * VPAD2 + seg * 8) * 2,
                 vf0 + (size_t)d * SEQ + kt * 64 + seg * 8);
        }
        CP_COMMIT();
    };

    // Prologue: Q tile, then K(0), V(0)
    const __nv_bfloat16* qsrc = Qb + ((size_t)(b * NH + h) * SEQ + (size_t)qt * 64) * 128;
#pragma unroll
    for (int i = 0; i < 8; i++) {
        int c = t + 128 * i;
        int row = c >> 4, seg = c & 15;
        cp16(qsa + (row * APAD + seg * 8) * 2, qsrc + (size_t)row * 128 + seg * 8);
    }
    CP_COMMIT();
    issueK(0);
    issueV(0);

    float m0 = -1e30f, m1 = -1e30f, l0 = 0.f, l1 = 0.f;
    float of[8][4];
#pragma unroll
    for (int j = 0; j < 8; j++)
#pragma unroll
        for (int e = 0; e < 4; e++) of[j][e] = 0.f;

    for (int kt = 0; kt <= qt; kt++) {
        CP_WAIT(1);         // Q + K(kt) landed; V(kt) may be in flight
        __syncthreads();

        // ---- S = Q' K'^T: ksteps 0-3 Qhi.Khi, 4-7 Qlo.Khi, 8-11 Qhi.Klo ----
        float sf[8][4];
#pragma unroll
        for (int j = 0; j < 8; j++)
#pragma unroll
            for (int e = 0; e < 4; e++) sf[j][e] = 0.f;
#pragma unroll
        for (int ks12 = 0; ks12 < 12; ks12++) {
            int aCol = (ks12 < 8 ? ks12 : ks12 - 8) * 16;
            int bCol = (ks12 < 4 ? ks12 * 16 : (ks12 < 8 ? (ks12 - 4) * 16
                                                          : 64 + (ks12 - 8) * 16));
            uint32_t a0, a1, a2, a3;
            ldsm4(a0, a1, a2, a3,
                  qsa + ((w * 16 + (li & 1) * 8 + lr) * APAD + aCol + (li >> 1) * 8) * 2);
#pragma unroll
            for (int p = 0; p < 4; p++) {
                uint32_t b0, b1, b2, b3;
                ldsm4(b0, b1, b2, b3,
                      ksa + ((p * 16 + (li >> 1) * 8 + lr) * APAD + bCol + (li & 1) * 8) * 2);
                mma16816(sf[2 * p],     a0, a1, a2, a3, b0, b1);
                mma16816(sf[2 * p + 1], a0, a1, a2, a3, b2, b3);
            }
        }

        if (kt == qt) {
            int q0 = w * 16 + r0, q1 = q0 + 8;
#pragma unroll
            for (int j = 0; j < 8; j++) {
                int key = 8 * j + cc;
                if (key     > q0) sf[j][0] = -1e30f;
                if (key + 1 > q0) sf[j][1] = -1e30f;
                if (key     > q1) sf[j][2] = -1e30f;
                if (key + 1 > q1) sf[j][3] = -1e30f;
            }
        }

        // ---- online softmax ----
        float mx0 = -1e30f, mx1 = -1e30f;
#pragma unroll
        for (int j = 0; j < 8; j++) {
            mx0 = fmaxf(mx0, fmaxf(sf[j][0], sf[j][1]));
            mx1 = fmaxf(mx1, fmaxf(sf[j][2], sf[j][3]));
        }
        mx0 = fmaxf(mx0, __shfl_xor_sync(0xffffffffu, mx0, 1));
        mx0 = fmaxf(mx0, __shfl_xor_sync(0xffffffffu, mx0, 2));
        mx1 = fmaxf(mx1, __shfl_xor_sync(0xffffffffu, mx1, 1));
        mx1 = fmaxf(mx1, __shfl_xor_sync(0xffffffffu, mx1, 2));
        float nm0 = fmaxf(m0, mx0), nm1 = fmaxf(m1, mx1);
        float al0 = __expf(m0 - nm0), al1 = __expf(m1 - nm1);
        m0 = nm0; m1 = nm1;

        float s0 = 0.f, s1 = 0.f;
#pragma unroll
        for (int j = 0; j < 8; j++) {
            sf[j][0] = __expf(sf[j][0] - m0); s0 += sf[j][0];
            sf[j][1] = __expf(sf[j][1] - m0); s0 += sf[j][1];
            sf[j][2] = __expf(sf[j][2] - m1); s1 += sf[j][2];
            sf[j][3] = __expf(sf[j][3] - m1); s1 += sf[j][3];
        }
        s0 += __shfl_xor_sync(0xffffffffu, s0, 1);
        s0 += __shfl_xor_sync(0xffffffffu, s0, 2);
        s1 += __shfl_xor_sync(0xffffffffu, s1, 1);
        s1 += __shfl_xor_sync(0xffffffffu, s1, 2);
        l0 = l0 * al0 + s0;
        l1 = l1 * al1 + s1;

#pragma unroll
        for (int j = 0; j < 8; j++) {
            of[j][0] *= al0; of[j][1] *= al0;
            of[j][2] *= al1; of[j][3] *= al1;
        }

        // ---- split P into fp16 A-fragments (hi, lo) ----
        uint32_t ah[4][4], alf[4][4];
#pragma unroll
        for (int kk = 0; kk < 4; kk++) {
            float c00 = sf[2 * kk][0], c01 = sf[2 * kk][1];
            float c02 = sf[2 * kk][2], c03 = sf[2 * kk][3];
            float c10 = sf[2 * kk + 1][0], c11 = sf[2 * kk + 1][1];
            float c12 = sf[2 * kk + 1][2], c13 = sf[2 * kk + 1][3];
            uint32_t h0 = pack_f16(c00, c01), h1 = pack_f16(c02, c03);
            uint32_t h2 = pack_f16(c10, c11), h3 = pack_f16(c12, c13);
            ah[kk][0] = h0; ah[kk][1] = h1; ah[kk][2] = h2; ah[kk][3] = h3;
            __half2 b0 = *(__half2*)&h0;
            __half2 b1 = *(__half2*)&h1;
            __half2 b2 = *(__half2*)&h2;
            __half2 b3 = *(__half2*)&h3;
            alf[kk][0] = pack_f16(c00 - __half2float(b0.x), c01 - __half2float(b0.y));
            alf[kk][1] = pack_f16(c02 - __half2float(b1.x), c03 - __half2float(b1.y));
            alf[kk][2] = pack_f16(c10 - __half2float(b2.x), c11 - __half2float(b2.y));
            alf[kk][3] = pack_f16(c12 - __half2float(b3.x), c13 - __half2float(b3.y));
        }

        CP_WAIT(0);          // V(kt) landed
        __syncthreads();     // all warps done with ks reads; vs visible

        // ks dead: prefetch K(kt+1), overlapping PV
        if (kt < qt) issueK(kt + 1);

        // ---- O += P V (fp16): ksteps 0-3 Phi.Vf, 4-7 Plo.Vf ----
#pragma unroll
        for (int ks8 = 0; ks8 < 8; ks8++) {
            int kk = ks8 & 3, sel = ks8 >> 2;
            uint32_t* A = (sel == 1) ? alf[kk] : ah[kk];
            int k0 = kk * 16;
#pragma unroll
            for (int p = 0; p < 4; p++) {
                uint32_t b0, b1, b2, b3;
                ldsm4(b0, b1, b2, b3,
                      vsa + ((p * 16 + (li >> 1) * 8 + lr) * VPAD2 + k0 + (li & 1) * 8) * 2);
                mma16816h(of[2 * p],     A[0], A[1], A[2], A[3], b0, b1);
                mma16816h(of[2 * p + 1], A[0], A[1], A[2], A[3], b2, b3);
            }
        }
        __syncthreads();     // all warps done with vs reads

        // vs dead: prefetch V(kt+1), overlapping next tile's S phase
        if (kt < qt) issueV(kt + 1);
    }

    // ---- epilogue: write split [hi|lo|hi] directly into aoc ----
    float inv0 = 1.f / l0, inv1 = 1.f / l1;
    int row0 = b * SEQ + qt * 64 + w * 16 + r0;
    int row1 = row0 + 8;
#pragma unroll
    for (int j = 0; j < 8; j++) {
        int colq = h * 64 + 8 * j + cc;
        {
            float v0 = of[j][0] * inv0, v1 = of[j][1] * inv0;
            uint32_t hp = pack_bf16(v0, v1);
            __nv_bfloat162 hb = *(__nv_bfloat162*)&hp;
            uint32_t lp = pack_bf16(v0 - __bfloat162float(hb.x), v1 - __bfloat162float(hb.y));
            uint32_t* base = (uint32_t*)(aoc + (size_t)row0 * GK + colq);
            base[0]              = hp;
            *(uint32_t*)((char*)base + 1024 * 2) = lp;
            *(uint32_t*)((char*)base + 2048 * 2) = hp;
        }
        {
            float v0 = of[j][2] * inv1, v1 = of[j][3] * inv1;
            uint32_t hp = pack_bf16(v0, v1);
            __nv_bfloat162 hb = *(__nv_bfloat162*)&hp;
            uint32_t lp = pack_bf16(v0 - __bfloat162float(hb.x), v1 - __bfloat162float(hb.y));
            uint32_t* base = (uint32_t*)(aoc + (size_t)row1 * GK + colq);
            base[0]              = hp;
            *(uint32_t*)((char*)base + 1024 * 2) = lp;
            *(uint32_t*)((char*)base + 2048 * 2) = hp;
        }
    }
}

// ---------------------------------------------------------------------------
extern "C" void kernel_launch(void* const* d_in, const int* in_sizes, int n_in,
                              void* d_out, int out_size) {
    const float* x    = (const float*)d_in[0];
    const float* cosT = (const float*)d_in[1];
    const float* sinT = (const float*)d_in[2];
    // d_in[3] = mask: unused
    const float* wq   = (const float*)d_in[4];
    const float* wk   = (const float*)d_in[5];
    const float* wv   = (const float*)d_in[6];
    const float* wo   = (const float*)d_in[7];

    float* out  = (float*)d_out;
    float* kout = out + OUT_ELEMS;
    float* vout = out + OUT_ELEMS + KV_ELEMS;

    float* qkv;
    __nv_bfloat16 *xc, *aoc, *wqkvt, *wot, *qb, *kb;
    __half* vf;
    cudaGetSymbolAddress((void**)&qkv, g_qkv);
    cudaGetSymbolAddress((void**)&xc,  g_xc);
    cudaGetSymbolAddress((void**)&aoc, g_aoc);
    cudaGetSymbolAddress((void**)&wqkvt, g_wqkvt);
    cudaGetSymbolAddress((void**)&wot, g_wot);
    cudaGetSymbolAddress((void**)&qb,  g_qb);
    cudaGetSymbolAddress((void**)&kb,  g_kb);
    cudaGetSymbolAddress((void**)&vf,  g_vf);

    cudaFuncSetAttribute(attn_mma, cudaFuncAttributeMaxDynamicSharedMemorySize, ATTN2_SMEM);
    cudaFuncSetAttribute(gemm_mma<128>, cudaFuncAttributeMaxDynamicSharedMemorySize,
                         GEMM_SMEM_FOR(128));
    cudaFuncSetAttribute(gemm_mma<192>, cudaFuncAttributeMaxDynamicSharedMemorySize,
                         GEMM_SMEM_FOR(192));

    // Split conversions
    conv_a<<<(MTOT * DMODEL / 4 + 255) / 256, 256>>>(x, xc);
    dim3 wb(32, 8);
    conv_qkv<<<dim3(NQKV / 32, DMODEL / 32), wb>>>(wq, wk, wv, wqkvt);
    conv_w<<<dim3(DMODEL / 32, DMODEL / 32), wb>>>(wo, wot, DMODEL);

    // Fused QKV projection: 128x192 tiles -> 256 CTAs = single wave
    gemm_mma<192><<<dim3(NQKV / 192, MTOT / 128), 256, GEMM_SMEM_FOR(192)>>>(
        xc, wqkvt, qkv, NQKV);

    // RoPE + compact split + fp32 kv-cache outputs
    finish_q<<<(BATCH * SEQ * NH * 32 + 255) / 256, 256>>>(qkv, cosT, sinT, qb);
    finish_k<<<(BATCH * SEQ * NKV * 32 + 255) / 256, 256>>>(qkv, cosT, sinT, kout, kb);
    finish_v<<<dim3(SEQ / 32, HD / 32, BATCH * NKV), dim3(32, 8)>>>(qkv, vout, vf);

    // Tensor-core flash attention (fp16 2-term PV, pipelined prefetch)
    attn_mma<<<dim3(SEQ / 64, NH, BATCH), 128, ATTN2_SMEM>>>(qb, kb, vf, aoc);

    // Output projection
    gemm_mma<128><<<dim3(DMODEL / 128, MTOT / 128), 256, GEMM_SMEM_FOR(128)>>>(
        aoc, wot, out, DMODEL);
}

// round 14
// speedup vs baseline: 1.2027x; 1.0537x over previous
#include <cuda_runtime.h>
#include <cuda_bf16.h>
#include <cuda_fp16.h>
#include <cstdint>

// Problem constants
#define BATCH 2
#define SEQ 2048
#define DMODEL 1024
#define NH 16
#define NKV 4
#define HD 64
#define OUT_ELEMS  (BATCH*SEQ*DMODEL)
#define KV_ELEMS   (BATCH*SEQ*NKV*HD)

#define MTOT (BATCH*SEQ)        // 4096
#define GK   (3*DMODEL)         // 3072 split-K (hi|lo|hi vs hi|hi|lo)
#define NQKV 1536               // fused QKV output width

// ---------------------------------------------------------------------------
// Scratch (device globals; no runtime allocation allowed)
// ---------------------------------------------------------------------------
__device__ float g_qkv[MTOT*NQKV];                   // fused QKV gemm output
__device__ __nv_bfloat16 g_xc   [MTOT*GK];           // x split [M, 3K]
__device__ __nv_bfloat16 g_aoc  [MTOT*GK];           // attn out split [M, 3K]
__device__ __nv_bfloat16 g_wqkvt[NQKV*GK];           // [wq|wk|wv]^T split
__device__ __nv_bfloat16 g_wot  [DMODEL*GK];
// Attention operands
__device__ __nv_bfloat16 g_qb [BATCH*NH*SEQ*128];    // [b][h][s][hi|lo]
__device__ __nv_bfloat16 g_kb [BATCH*NKV*SEQ*128];   // [b][kvh][s][hi|lo]
__device__ __half        g_vf [BATCH*NKV*HD*SEQ];    // [b][kvh][d][s] fp16

// ---------------------------------------------------------------------------
// Baseline-PTX helpers
// ---------------------------------------------------------------------------
__device__ __forceinline__ uint32_t smem_u32(const void* p) {
    uint32_t a;
    asm("{ .reg .u64 t; cvta.to.shared.u64 t, %1; cvt.u32.u64 %0, t; }" : "=r"(a) : "l"(p));
    return a;
}
__device__ __forceinline__ void cp16(uint32_t saddr, const void* g) {
    asm volatile("cp.async.cg.shared.global [%0], [%1], 16;" :: "r"(saddr), "l"(g) : "memory");
}
#define CP_COMMIT() asm volatile("cp.async.commit_group;" ::: "memory")
#define CP_WAIT(n)  asm volatile("cp.async.wait_group %0;" :: "n"(n) : "memory")

__device__ __forceinline__ void ldsm4(uint32_t& r0, uint32_t& r1, uint32_t& r2, uint32_t& r3,
                                      uint32_t a) {
    asm volatile("ldmatrix.sync.aligned.m8n8.x4.shared.b16 {%0,%1,%2,%3}, [%4];"
                 : "=r"(r0), "=r"(r1), "=r"(r2), "=r"(r3) : "r"(a));
}
__device__ __forceinline__ void mma16816(float* c, uint32_t a0, uint32_t a1, uint32_t a2,
                                         uint32_t a3, uint32_t b0, uint32_t b1) {
    asm volatile(
        "mma.sync.aligned.m16n8k16.row.col.f32.bf16.bf16.f32 "
        "{%0,%1,%2,%3},{%4,%5,%6,%7},{%8,%9},{%0,%1,%2,%3};"
        : "+f"(c[0]), "+f"(c[1]), "+f"(c[2]), "+f"(c[3])
        : "r"(a0), "r"(a1), "r"(a2), "r"(a3), "r"(b0), "r"(b1));
}
__device__ __forceinline__ void mma16816h(float* c, uint32_t a0, uint32_t a1, uint32_t a2,
                                          uint32_t a3, uint32_t b0, uint32_t b1) {
    asm volatile(
        "mma.sync.aligned.m16n8k16.row.col.f32.f16.f16.f32 "
        "{%0,%1,%2,%3},{%4,%5,%6,%7},{%8,%9},{%0,%1,%2,%3};"
        : "+f"(c[0]), "+f"(c[1]), "+f"(c[2]), "+f"(c[3])
        : "r"(a0), "r"(a1), "r"(a2), "r"(a3), "r"(b0), "r"(b1));
}
__device__ __forceinline__ uint32_t pack_bf16(float x, float y) {
    uint32_t r;
    asm("cvt.rn.bf16x2.f32 %0, %1, %2;" : "=r"(r) : "f"(y), "f"(x));
    return r;
}
__device__ __forceinline__ uint32_t pack_f16(float x, float y) {
    uint32_t r;
    asm("cvt.rn.f16x2.f32 %0, %1, %2;" : "=r"(r) : "f"(y), "f"(x));
    return r;
}
__device__ __forceinline__ void split_bf16(float v, __nv_bfloat16& hi, __nv_bfloat16& lo) {
    hi = __float2bfloat16(v);
    lo = __float2bfloat16(v - __bfloat162float(hi));
}

// ---------------------------------------------------------------------------
// A-side split: src [M, K] fp32 -> dst [M, 3K] = [hi | lo | hi]
// ---------------------------------------------------------------------------
__global__ __launch_bounds__(256) void conv_a(const float* __restrict__ src,
                                              __nv_bfloat16* __restrict__ dst) {
    int idx = blockIdx.x * blockDim.x + threadIdx.x;
    const int K = DMODEL;
    if (idx >= MTOT * K / 4) return;
    int flat = idx * 4;
    int m = flat / K, k = flat % K;
    float4 v = *(const float4*)(src + flat);
    float vv[4] = {v.x, v.y, v.z, v.w};
    __nv_bfloat16 h[4], l[4];
#pragma unroll
    for (int j = 0; j < 4; j++) split_bf16(vv[j], h[j], l[j]);
    __nv_bfloat16* row = dst + (size_t)m * GK;
    *(uint2*)(row + k)         = *(uint2*)h;
    *(uint2*)(row + K + k)     = *(uint2*)l;
    *(uint2*)(row + 2 * K + k) = *(uint2*)h;
}

// Fused weight split for [wq|wk|wv] -> wqkvt [1536, 3K]
__global__ void conv_qkv(const float* __restrict__ wq, const float* __restrict__ wk,
                         const float* __restrict__ wv, __nv_bfloat16* __restrict__ dst) {
    __shared__ float tile[32][33];
    const int K = DMODEL;
    int k0 = blockIdx.y * 32, n0 = blockIdx.x * 32;
    const float* src;
    int nloc, N;
    float scale = 1.f;
    if (n0 < 1024)      { src = wq; nloc = n0;        N = 1024; scale = 0.125f; }
    else if (n0 < 1280) { src = wk; nloc = n0 - 1024; N = 256; }
    else                { src = wv; nloc = n0 - 1280; N = 256; }
    int tx = threadIdx.x, ty = threadIdx.y;
#pragma unroll
    for (int i = 0; i < 32; i += 8)
        tile[ty + i][tx] = src[(size_t)(k0 + ty + i) * N + nloc + tx] * scale;
    __syncthreads();
#pragma unroll
    for (int i = 0; i < 32; i += 8) {
        int n = n0 + ty + i, k = k0 + tx;
        __nv_bfloat16 h, l;
        split_bf16(tile[tx][ty + i], h, l);
        __nv_bfloat16* row = dst + (size_t)n * GK;
        row[k]         = h;
        row[K + k]     = h;
        row[2 * K + k] = l;
    }
}

// B-side split for wo
__global__ void conv_w(const float* __restrict__ src, __nv_bfloat16* __restrict__ dst,
                       int N) {
    __shared__ float tile[32][33];
    const int K = DMODEL;
    int k0 = blockIdx.y * 32, n0 = blockIdx.x * 32;
    int tx = threadIdx.x, ty = threadIdx.y;
#pragma unroll
    for (int i = 0; i < 32; i += 8)
        tile[ty + i][tx] = src[(size_t)(k0 + ty + i) * N + n0 + tx];
    __syncthreads();
#pragma unroll
    for (int i = 0; i < 32; i += 8) {
        int n = n0 + ty + i, k = k0 + tx;
        __nv_bfloat16 h, l;
        split_bf16(tile[tx][ty + i], h, l);
        __nv_bfloat16* row = dst + (size_t)n * GK;
        row[k]         = h;
        row[K + k]     = h;
        row[2 * K + k] = l;
    }
}

// ---------------------------------------------------------------------------
// bf16 mma.sync GEMM, templated on CTA N-tile width (unchanged from R10).
// ---------------------------------------------------------------------------
#define BMt 128
#define BKt 32
#define PADt 40
#define NCHt (GK/BKt)           // 96
#define STAGES 4
#define GEMM_SMEM_FOR(BN) (STAGES * (BMt + (BN)) * PADt * 2)

template<int BN>
__global__ __launch_bounds__(256, 2) void gemm_mma(const __nv_bfloat16* __restrict__ A,
                                                   const __nv_bfloat16* __restrict__ Bt,
                                                   float* __restrict__ C, int N) {
    constexpr int WN = BN / 4;
    constexpr int NT = WN / 8;
    constexpr int NP = WN / 16;
    constexpr int SEL = (BMt + BN) * PADt;
    constexpr int TOTCH = (BMt + BN) * 4;

    extern __shared__ __nv_bfloat16 gsm[];
    uint32_t smb = smem_u32(gsm);

    int t = threadIdx.x, w = t >> 5, lane = t & 31;
    int m0 = blockIdx.y * BMt, n0 = blockIdx.x * BN;
    int wm = (w >> 2) * 64;
    int wn = (w & 3) * WN;

    float acc[4][NT][4];
#pragma unroll
    for (int i = 0; i < 4; i++)
#pragma unroll
        for (int j = 0; j < NT; j++)
#pragma unroll
            for (int r = 0; r < 4; r++) acc[i][j][r] = 0.f;

    const __nv_bfloat16* Ab = A  + (size_t)m0 * GK;
    const __nv_bfloat16* Bb = Bt + (size_t)n0 * GK;

    auto load_tile = [&](int kc, int s) {
        if (kc < NCHt) {
            uint32_t ab = smb + s * (SEL * 2);
            uint32_t bb = ab + BMt * PADt * 2;
            const __nv_bfloat16* Ak = Ab + kc * BKt;
            const __nv_bfloat16* Bk = Bb + kc * BKt;
#pragma unroll
            for (int i = 0; i < TOTCH / 256; i++) {
                int idx = t + i * 256;
                int row = idx >> 2, ch = idx & 3;
                if (row < BMt)
                    cp16(ab + (row * PADt + ch * 8) * 2, Ak + (size_t)row * GK + ch * 8);
                else {
                    int r = row - BMt;
                    cp16(bb + (r * PADt + ch * 8) * 2, Bk + (size_t)r * GK + ch * 8);
                }
            }
        }
        CP_COMMIT();
    };

#pragma unroll
    for (int s = 0; s < STAGES - 1; s++) load_tile(s, s);

    int li = lane >> 3;
    int lr = lane & 7;

    for (int kc = 0; kc < NCHt; kc++) {
        CP_WAIT(STAGES - 2);
        __syncthreads();
        load_tile(kc + STAGES - 1, (kc + STAGES - 1) % STAGES);

        int s = kc % STAGES;
        uint32_t ab = smb + s * (SEL * 2);
        uint32_t bb = ab + BMt * PADt * 2;

#pragma unroll
        for (int ks = 0; ks < 2; ks++) {
            int k0 = ks * 16;
            uint32_t a[4][4];
#pragma unroll
            for (int mt = 0; mt < 4; mt++) {
                int row = wm + mt * 16 + (li & 1) * 8 + lr;
                int col = k0 + (li >> 1) * 8;
                ldsm4(a[mt][0], a[mt][1], a[mt][2], a[mt][3],
                      ab + (row * PADt + col) * 2);
            }
            uint32_t b[NP][4];
#pragma unroll
            for (int p = 0; p < NP; p++) {
                int row = wn + p * 16 + (li >> 1) * 8 + lr;
                int col = k0 + (li & 1) * 8;
                ldsm4(b[p][0], b[p][1], b[p][2], b[p][3],
                      bb + (row * PADt + col) * 2);
            }
#pragma unroll
            for (int mt = 0; mt < 4; mt++)
#pragma unroll
                for (int nt = 0; nt < NT; nt++) {
                    int p = nt >> 1, off = (nt & 1) * 2;
                    mma16816(acc[mt][nt], a[mt][0], a[mt][1], a[mt][2], a[mt][3],
                             b[p][off], b[p][off + 1]);
                }
        }
    }

    int cr = lane >> 2, cc = (lane & 3) * 2;
#pragma unroll
    for (int mt = 0; mt < 4; mt++)
#pragma unroll
        for (int nt = 0; nt < NT; nt++) {
            float* Cp = C + (size_t)(m0 + wm + mt * 16 + cr) * N + n0 + wn + nt * 8 + cc;
            *(float2*)Cp = make_float2(acc[mt][nt][0], acc[mt][nt][1]);
            *(float2*)(Cp + 8 * (size_t)N) = make_float2(acc[mt][nt][2], acc[mt][nt][3]);
        }
}

// ---------------------------------------------------------------------------
// finish_q / finish_k: RoPE + compact [hi|lo] split (128 cols)
// ---------------------------------------------------------------------------
__global__ __launch_bounds__(256) void finish_q(const float* __restrict__ qkv,
                                                const float* __restrict__ cosT,
                                                const float* __restrict__ sinT,
                                                __nv_bfloat16* __restrict__ qb) {
    int idx = blockIdx.x * 256 + threadIdx.x;
    const int total = BATCH * SEQ * NH * 32;
    if (idx >= total) return;
    int j = idx & 31;
    int rest = idx >> 5;
    int h = rest % NH;
    int row = rest / NH;
    int s = row % SEQ, b = row / SEQ;

    const float* src = qkv + (size_t)row * NQKV + h * 64;
    float c  = cosT[s * 32 + j];
    float sn = sinT[s * 32 + j];
    float x1 = src[j], x2 = src[j + 32];
    float y1 = x1 * c - x2 * sn;
    float y2 = x2 * c + x1 * sn;

    __nv_bfloat16 h1, l1, h2, l2;
    split_bf16(y1, h1, l1);
    split_bf16(y2, h2, l2);
    __nv_bfloat16* d = qb + ((size_t)(b * NH + h) * SEQ + s) * 128;
    d[j]       = h1;  d[j + 32]  = h2;   // hi
    d[64 + j]  = l1;  d[96 + j]  = l2;   // lo
}

__global__ __launch_bounds__(256) void finish_k(const float* __restrict__ qkv,
                                                const float* __restrict__ cosT,
                                                const float* __restrict__ sinT,
                                                float* __restrict__ kout,
                                                __nv_bfloat16* __restrict__ kb) {
    int idx = blockIdx.x * 256 + threadIdx.x;
    const int total = BATCH * SEQ * NKV * 32;
    if (idx >= total) return;
    int j = idx & 31;
    int rest = idx >> 5;
    int kvh = rest % NKV;
    int row = rest / NKV;
    int s = row % SEQ, b = row / SEQ;

    const float* src = qkv + (size_t)row * NQKV + 1024 + kvh * 64;
    float c  = cosT[s * 32 + j];
    float sn = sinT[s * 32 + j];
    float x1 = src[j], x2 = src[j + 32];
    float y1 = x1 * c - x2 * sn;
    float y2 = x2 * c + x1 * sn;

    float* ko = kout + ((size_t)row * NKV + kvh) * 64;
    ko[j] = y1;
    ko[j + 32] = y2;

    __nv_bfloat16 h1, l1, h2, l2;
    split_bf16(y1, h1, l1);
    split_bf16(y2, h2, l2);
    __nv_bfloat16* d = kb + ((size_t)(b * NKV + kvh) * SEQ + s) * 128;
    d[j]       = h1;  d[j + 32]  = h2;   // hi
    d[64 + j]  = l1;  d[96 + j]  = l2;   // lo
}

// finish_v: fp32 new_v to d_out + transposed single-fp16 V
__global__ void finish_v(const float* __restrict__ qkv,
                         float* __restrict__ vout,
                         __half* __restrict__ vf) {
    __shared__ float tile[32][33];
    int bkv = blockIdx.z;
    int b = bkv / NKV, kvh = bkv % NKV;
    int s0 = blockIdx.x * 32, d0 = blockIdx.y * 32;
    int tx = threadIdx.x, ty = threadIdx.y;
#pragma unroll
    for (int i = 0; i < 32; i += 8) {
        int s = s0 + ty + i;
        float v = qkv[((size_t)b * SEQ + s) * NQKV + 1280 + kvh * 64 + d0 + tx];
        tile[ty + i][tx] = v;
        vout[(((size_t)b * SEQ + s) * NKV + kvh) * 64 + d0 + tx] = v;
    }
    __syncthreads();
#pragma unroll
    for (int i = 0; i < 32; i += 8) {
        int d = d0 + ty + i, s = s0 + tx;
        vf[((size_t)bkv * HD + d) * SEQ + s] = __float2half(tile[tx][ty + i]);
    }
}

// ---------------------------------------------------------------------------
// Tensor-core flash attention.
// S: bf16 3-term split (12 ksteps).
// PV: single-fp16 P x single-fp16 V (4 ksteps).
// Smem: qs/ks 64x136 bf16 + vs 64x72 fp16 = 44 KB.
// ---------------------------------------------------------------------------
#define APAD 136
#define VPAD2 72
#define ATTN2_SMEM ((2 * 64 * APAD + 64 * VPAD2) * 2)

__global__ __launch_bounds__(128) void attn_mma(const __nv_bfloat16* __restrict__ Qb,
                                                const __nv_bfloat16* __restrict__ Kb,
                                                const __half* __restrict__ Vf,
                                                __nv_bfloat16* __restrict__ aoc) {
    extern __shared__ __nv_bfloat16 sb[];
    __nv_bfloat16* qs = sb;
    __nv_bfloat16* ks = sb + 64 * APAD;
    __half*        vs = (__half*)(sb + 2 * 64 * APAD);
    uint32_t qsa = smem_u32(qs), ksa = smem_u32(ks), vsa = smem_u32(vs);

    int t = threadIdx.x, w = t >> 5, lane = t & 31;
    int qt = gridDim.x - 1 - blockIdx.x;   // longest CTAs first
    int h = blockIdx.y, b = blockIdx.z;
    int kvh = h >> 2;
    int li = lane >> 3, lr = lane & 7;
    int r0 = lane >> 2;
    int cc = (lane & 3) * 2;

    const __nv_bfloat16* ksrc0 = Kb + (size_t)(b * NKV + kvh) * SEQ * 128;
    const __half* vf0 = Vf + (size_t)(b * NKV + kvh) * HD * SEQ;

    auto issueK = [&](int kt) {
        const __nv_bfloat16* ksrc = ksrc0 + (size_t)kt * 64 * 128;
#pragma unroll
        for (int i = 0; i < 8; i++) {
            int c = t + 128 * i;
            int row = c >> 4, seg = c & 15;
            cp16(ksa + (row * APAD + seg * 8) * 2, ksrc + (size_t)row * 128 + seg * 8);
        }
        CP_COMMIT();
    };
    auto issueV = [&](int kt) {
#pragma unroll
        for (int i = 0; i < 4; i++) {
            int c = t + 128 * i;          // 512 chunks: 64 rows x 8 chunks
            int d = c >> 3, seg = c & 7;
            cp16(vsa + (d * VPAD2 + seg * 8) * 2,
                 vf0 + (size_t)d * SEQ + kt * 64 + seg * 8);
        }
        CP_COMMIT();
    };

    // Prologue: Q tile, then K(0), V(0)
    const __nv_bfloat16* qsrc = Qb + ((size_t)(b * NH + h) * SEQ + (size_t)qt * 64) * 128;
#pragma unroll
    for (int i = 0; i < 8; i++) {
        int c = t + 128 * i;
        int row = c >> 4, seg = c & 15;
        cp16(qsa + (row * APAD + seg * 8) * 2, qsrc + (size_t)row * 128 + seg * 8);
    }
    CP_COMMIT();
    issueK(0);
    issueV(0);

    float m0 = -1e30f, m1 = -1e30f, l0 = 0.f, l1 = 0.f;
    float of[8][4];
#pragma unroll
    for (int j = 0; j < 8; j++)
#pragma unroll
        for (int e = 0; e < 4; e++) of[j][e] = 0.f;

    for (int kt = 0; kt <= qt; kt++) {
        CP_WAIT(1);         // Q + K(kt) landed; V(kt) may be in flight
        __syncthreads();

        // ---- S = Q' K'^T: ksteps 0-3 Qhi.Khi, 4-7 Qlo.Khi, 8-11 Qhi.Klo ----
        float sf[8][4];
#pragma unroll
        for (int j = 0; j < 8; j++)
#pragma unroll
            for (int e = 0; e < 4; e++) sf[j][e] = 0.f;
#pragma unroll
        for (int ks12 = 0; ks12 < 12; ks12++) {
            int aCol = (ks12 < 8 ? ks12 : ks12 - 8) * 16;
            int bCol = (ks12 < 4 ? ks12 * 16 : (ks12 < 8 ? (ks12 - 4) * 16
                                                          : 64 + (ks12 - 8) * 16));
            uint32_t a0, a1, a2, a3;
            ldsm4(a0, a1, a2, a3,
                  qsa + ((w * 16 + (li & 1) * 8 + lr) * APAD + aCol + (li >> 1) * 8) * 2);
#pragma unroll
            for (int p = 0; p < 4; p++) {
                uint32_t b0, b1, b2, b3;
                ldsm4(b0, b1, b2, b3,
                      ksa + ((p * 16 + (li >> 1) * 8 + lr) * APAD + bCol + (li & 1) * 8) * 2);
                mma16816(sf[2 * p],     a0, a1, a2, a3, b0, b1);
                mma16816(sf[2 * p + 1], a0, a1, a2, a3, b2, b3);
            }
        }

        if (kt == qt) {
            int q0 = w * 16 + r0, q1 = q0 + 8;
#pragma unroll
            for (int j = 0; j < 8; j++) {
                int key = 8 * j + cc;
                if (key     > q0) sf[j][0] = -1e30f;
                if (key + 1 > q0) sf[j][1] = -1e30f;
                if (key     > q1) sf[j][2] = -1e30f;
                if (key + 1 > q1) sf[j][3] = -1e30f;
            }
        }

        // ---- online softmax ----
        float mx0 = -1e30f, mx1 = -1e30f;
#pragma unroll
        for (int j = 0; j < 8; j++) {
            mx0 = fmaxf(mx0, fmaxf(sf[j][0], sf[j][1]));
            mx1 = fmaxf(mx1, fmaxf(sf[j][2], sf[j][3]));
        }
        mx0 = fmaxf(mx0, __shfl_xor_sync(0xffffffffu, mx0, 1));
        mx0 = fmaxf(mx0, __shfl_xor_sync(0xffffffffu, mx0, 2));
        mx1 = fmaxf(mx1, __shfl_xor_sync(0xffffffffu, mx1, 1));
        mx1 = fmaxf(mx1, __shfl_xor_sync(0xffffffffu, mx1, 2));
        float nm0 = fmaxf(m0, mx0), nm1 = fmaxf(m1, mx1);
        float al0 = __expf(m0 - nm0), al1 = __expf(m1 - nm1);
        m0 = nm0; m1 = nm1;

        float s0 = 0.f, s1 = 0.f;
#pragma unroll
        for (int j = 0; j < 8; j++) {
            sf[j][0] = __expf(sf[j][0] - m0); s0 += sf[j][0];
            sf[j][1] = __expf(sf[j][1] - m0); s0 += sf[j][1];
            sf[j][2] = __expf(sf[j][2] - m1); s1 += sf[j][2];
            sf[j][3] = __expf(sf[j][3] - m1); s1 += sf[j][3];
        }
        s0 += __shfl_xor_sync(0xffffffffu, s0, 1);
        s0 += __shfl_xor_sync(0xffffffffu, s0, 2);
        s1 += __shfl_xor_sync(0xffffffffu, s1, 1);
        s1 += __shfl_xor_sync(0xffffffffu, s1, 2);
        l0 = l0 * al0 + s0;
        l1 = l1 * al1 + s1;

#pragma unroll
        for (int j = 0; j < 8; j++) {
            of[j][0] *= al0; of[j][1] *= al0;
            of[j][2] *= al1; of[j][3] *= al1;
        }

        // ---- pack P into single-fp16 A-fragments ----
        uint32_t ah[4][4];
#pragma unroll
        for (int kk = 0; kk < 4; kk++) {
            ah[kk][0] = pack_f16(sf[2 * kk][0],     sf[2 * kk][1]);
            ah[kk][1] = pack_f16(sf[2 * kk][2],     sf[2 * kk][3]);
            ah[kk][2] = pack_f16(sf[2 * kk + 1][0], sf[2 * kk + 1][1]);
            ah[kk][3] = pack_f16(sf[2 * kk + 1][2], sf[2 * kk + 1][3]);
        }

        CP_WAIT(0);          // V(kt) landed
        __syncthreads();     // all warps done with ks reads; vs visible

        // ks dead: prefetch K(kt+1), overlapping PV
        if (kt < qt) issueK(kt + 1);

        // ---- O += P V (fp16, 4 ksteps) ----
#pragma unroll
        for (int ks4 = 0; ks4 < 4; ks4++) {
            uint32_t* A = ah[ks4];
            int k0 = ks4 * 16;
#pragma unroll
            for (int p = 0; p < 4; p++) {
                uint32_t b0, b1, b2, b3;
                ldsm4(b0, b1, b2, b3,
                      vsa + ((p * 16 + (li >> 1) * 8 + lr) * VPAD2 + k0 + (li & 1) * 8) * 2);
                mma16816h(of[2 * p],     A[0], A[1], A[2], A[3], b0, b1);
                mma16816h(of[2 * p + 1], A[0], A[1], A[2], A[3], b2, b3);
            }
        }
        __syncthreads();     // all warps done with vs reads

        // vs dead: prefetch V(kt+1), overlapping next tile's S phase
        if (kt < qt) issueV(kt + 1);
    }

    // ---- epilogue: write split [hi|lo|hi] directly into aoc ----
    float inv0 = 1.f / l0, inv1 = 1.f / l1;
    int row0 = b * SEQ + qt * 64 + w * 16 + r0;
    int row1 = row0 + 8;
#pragma unroll
    for (int j = 0; j < 8; j++) {
        int colq = h * 64 + 8 * j + cc;
        {
            float v0 = of[j][0] * inv0, v1 = of[j][1] * inv0;
            uint32_t hp = pack_bf16(v0, v1);
            __nv_bfloat162 hb = *(__nv_bfloat162*)&hp;
            uint32_t lp = pack_bf16(v0 - __bfloat162float(hb.x), v1 - __bfloat162float(hb.y));
            uint32_t* base = (uint32_t*)(aoc + (size_t)row0 * GK + colq);
            base[0]              = hp;
            *(uint32_t*)((char*)base + 1024 * 2) = lp;
            *(uint32_t*)((char*)base + 2048 * 2) = hp;
        }
        {
            float v0 = of[j][2] * inv1, v1 = of[j][3] * inv1;
            uint32_t hp = pack_bf16(v0, v1);
            __nv_bfloat162 hb = *(__nv_bfloat162*)&hp;
            uint32_t lp = pack_bf16(v0 - __bfloat162float(hb.x), v1 - __bfloat162float(hb.y));
            uint32_t* base = (uint32_t*)(aoc + (size_t)row1 * GK + colq);
            base[0]              = hp;
            *(uint32_t*)((char*)base + 1024 * 2) = lp;
            *(uint32_t*)((char*)base + 2048 * 2) = hp;
        }
    }
}

// ---------------------------------------------------------------------------
extern "C" void kernel_launch(void* const* d_in, const int* in_sizes, int n_in,
                              void* d_out, int out_size) {
    const float* x    = (const float*)d_in[0];
    const float* cosT = (const float*)d_in[1];
    const float* sinT = (const float*)d_in[2];
    // d_in[3] = mask: unused
    const float* wq   = (const float*)d_in[4];
    const float* wk   = (const float*)d_in[5];
    const float* wv   = (const float*)d_in[6];
    const float* wo   = (const float*)d_in[7];

    float* out  = (float*)d_out;
    float* kout = out + OUT_ELEMS;
    float* vout = out + OUT_ELEMS + KV_ELEMS;

    float* qkv;
    __nv_bfloat16 *xc, *aoc, *wqkvt, *wot, *qb, *kb;
    __half* vf;
    cudaGetSymbolAddress((void**)&qkv, g_qkv);
    cudaGetSymbolAddress((void**)&xc,  g_xc);
    cudaGetSymbolAddress((void**)&aoc, g_aoc);
    cudaGetSymbolAddress((void**)&wqkvt, g_wqkvt);
    cudaGetSymbolAddress((void**)&wot, g_wot);
    cudaGetSymbolAddress((void**)&qb,  g_qb);
    cudaGetSymbolAddress((void**)&kb,  g_kb);
    cudaGetSymbolAddress((void**)&vf,  g_vf);

    cudaFuncSetAttribute(attn_mma, cudaFuncAttributeMaxDynamicSharedMemorySize, ATTN2_SMEM);
    cudaFuncSetAttribute(gemm_mma<128>, cudaFuncAttributeMaxDynamicSharedMemorySize,
                         GEMM_SMEM_FOR(128));
    cudaFuncSetAttribute(gemm_mma<192>, cudaFuncAttributeMaxDynamicSharedMemorySize,
                         GEMM_SMEM_FOR(192));

    // Split conversions
    conv_a<<<(MTOT * DMODEL / 4 + 255) / 256, 256>>>(x, xc);
    dim3 wb(32, 8);
    conv_qkv<<<dim3(NQKV / 32, DMODEL / 32), wb>>>(wq, wk, wv, wqkvt);
    conv_w<<<dim3(DMODEL / 32, DMODEL / 32), wb>>>(wo, wot, DMODEL);

    // Fused QKV projection: 128x192 tiles -> 256 CTAs = single wave
    gemm_mma<192><<<dim3(NQKV / 192, MTOT / 128), 256, GEMM_SMEM_FOR(192)>>>(
        xc, wqkvt, qkv, NQKV);

    // RoPE + compact split + fp32 kv-cache outputs
    finish_q<<<(BATCH * SEQ * NH * 32 + 255) / 256, 256>>>(qkv, cosT, sinT, qb);
    finish_k<<<(BATCH * SEQ * NKV * 32 + 255) / 256, 256>>>(qkv, cosT, sinT, kout, kb);
    finish_v<<<dim3(SEQ / 32, HD / 32, BATCH * NKV), dim3(32, 8)>>>(qkv, vout, vf);

    // Tensor-core flash attention (single-fp16 PV, pipelined prefetch)
    attn_mma<<<dim3(SEQ / 64, NH, BATCH), 128, ATTN2_SMEM>>>(qb, kb, vf, aoc);

    // Output projection
    gemm_mma<128><<<dim3(DMODEL / 128, MTOT / 128), 256, GEMM_SMEM_FOR(128)>>>(
        aoc, wot, out, DMODEL);
}

// round 15
// speedup vs baseline: 1.5803x; 1.3140x over previous
#include <cuda_runtime.h>
#include <cuda_bf16.h>
#include <cuda_fp16.h>
#include <cstdint>

// Problem constants
#define BATCH 2
#define SEQ 2048
#define DMODEL 1024
#define NH 16
#define NKV 4
#define HD 64
#define OUT_ELEMS  (BATCH*SEQ*DMODEL)
#define KV_ELEMS   (BATCH*SEQ*NKV*HD)

#define MTOT (BATCH*SEQ)        // 4096
#define GK   (2*DMODEL)         // 2048: fp16 [hi|lo] x [hi|lo] = FULL product
#define NQKV 1536               // fused QKV output width

// ---------------------------------------------------------------------------
// Scratch (device globals; no runtime allocation allowed)
// ---------------------------------------------------------------------------
__device__ float g_qkv[MTOT*NQKV];                   // fused QKV gemm output
__device__ __half g_xc   [MTOT*GK];                  // x split [M, 2K]
__device__ __half g_aoc  [MTOT*GK];                  // attn out split [M, 2K]
__device__ __half g_wqkvt[NQKV*GK];                  // [wq|wk|wv]^T split
__device__ __half g_wot  [DMODEL*GK];
// Attention operands
__device__ __half g_qb [BATCH*NH*SEQ*128];           // [b][h][s][hi|lo]
__device__ __half g_kb [BATCH*NKV*SEQ*128];          // [b][kvh][s][hi|lo]
__device__ __half g_vf [BATCH*NKV*HD*SEQ];           // [b][kvh][d][s] fp16

// ---------------------------------------------------------------------------
// Baseline-PTX helpers
// ---------------------------------------------------------------------------
__device__ __forceinline__ uint32_t smem_u32(const void* p) {
    uint32_t a;
    asm("{ .reg .u64 t; cvta.to.shared.u64 t, %1; cvt.u32.u64 %0, t; }" : "=r"(a) : "l"(p));
    return a;
}
__device__ __forceinline__ void cp16(uint32_t saddr, const void* g) {
    asm volatile("cp.async.cg.shared.global [%0], [%1], 16;" :: "r"(saddr), "l"(g) : "memory");
}
#define CP_COMMIT() asm volatile("cp.async.commit_group;" ::: "memory")
#define CP_WAIT(n)  asm volatile("cp.async.wait_group %0;" :: "n"(n) : "memory")

__device__ __forceinline__ void ldsm4(uint32_t& r0, uint32_t& r1, uint32_t& r2, uint32_t& r3,
                                      uint32_t a) {
    asm volatile("ldmatrix.sync.aligned.m8n8.x4.shared.b16 {%0,%1,%2,%3}, [%4];"
                 : "=r"(r0), "=r"(r1), "=r"(r2), "=r"(r3) : "r"(a));
}
__device__ __forceinline__ void mma16816h(float* c, uint32_t a0, uint32_t a1, uint32_t a2,
                                          uint32_t a3, uint32_t b0, uint32_t b1) {
    asm volatile(
        "mma.sync.aligned.m16n8k16.row.col.f32.f16.f16.f32 "
        "{%0,%1,%2,%3},{%4,%5,%6,%7},{%8,%9},{%0,%1,%2,%3};"
        : "+f"(c[0]), "+f"(c[1]), "+f"(c[2]), "+f"(c[3])
        : "r"(a0), "r"(a1), "r"(a2), "r"(a3), "r"(b0), "r"(b1));
}
__device__ __forceinline__ uint32_t pack_f16(float x, float y) {
    uint32_t r;
    asm("cvt.rn.f16x2.f32 %0, %1, %2;" : "=r"(r) : "f"(y), "f"(x));
    return r;
}
__device__ __forceinline__ void split_f16(float v, __half& hi, __half& lo) {
    hi = __float2half(v);
    lo = __float2half(v - __half2float(hi));
}

// ---------------------------------------------------------------------------
// A-side split: src [M, K] fp32 -> dst [M, 2K] = [hi | lo]
// ---------------------------------------------------------------------------
__global__ __launch_bounds__(256) void conv_a(const float* __restrict__ src,
                                              __half* __restrict__ dst) {
    int idx = blockIdx.x * blockDim.x + threadIdx.x;
    const int K = DMODEL;
    if (idx >= MTOT * K / 4) return;
    int flat = idx * 4;
    int m = flat / K, k = flat % K;
    float4 v = *(const float4*)(src + flat);
    float vv[4] = {v.x, v.y, v.z, v.w};
    __half h[4], l[4];
#pragma unroll
    for (int j = 0; j < 4; j++) split_f16(vv[j], h[j], l[j]);
    __half* row = dst + (size_t)m * GK;
    *(uint2*)(row + k)     = *(uint2*)h;
    *(uint2*)(row + K + k) = *(uint2*)l;
}

// Fused weight split for [wq|wk|wv] -> wqkvt [1536, 2K]
__global__ void conv_qkv(const float* __restrict__ wq, const float* __restrict__ wk,
                         const float* __restrict__ wv, __half* __restrict__ dst) {
    __shared__ float tile[32][33];
    const int K = DMODEL;
    int k0 = blockIdx.y * 32, n0 = blockIdx.x * 32;
    const float* src;
    int nloc, N;
    float scale = 1.f;
    if (n0 < 1024)      { src = wq; nloc = n0;        N = 1024; scale = 0.125f; }
    else if (n0 < 1280) { src = wk; nloc = n0 - 1024; N = 256; }
    else                { src = wv; nloc = n0 - 1280; N = 256; }
    int tx = threadIdx.x, ty = threadIdx.y;
#pragma unroll
    for (int i = 0; i < 32; i += 8)
        tile[ty + i][tx] = src[(size_t)(k0 + ty + i) * N + nloc + tx] * scale;
    __syncthreads();
#pragma unroll
    for (int i = 0; i < 32; i += 8) {
        int n = n0 + ty + i, k = k0 + tx;
        __half h, l;
        split_f16(tile[tx][ty + i], h, l);
        __half* row = dst + (size_t)n * GK;
        row[k]     = h;
        row[K + k] = l;
    }
}

// B-side split for wo
__global__ void conv_w(const float* __restrict__ src, __half* __restrict__ dst,
                       int N) {
    __shared__ float tile[32][33];
    const int K = DMODEL;
    int k0 = blockIdx.y * 32, n0 = blockIdx.x * 32;
    int tx = threadIdx.x, ty = threadIdx.y;
#pragma unroll
    for (int i = 0; i < 32; i += 8)
        tile[ty + i][tx] = src[(size_t)(k0 + ty + i) * N + n0 + tx];
    __syncthreads();
#pragma unroll
    for (int i = 0; i < 32; i += 8) {
        int n = n0 + ty + i, k = k0 + tx;
        __half h, l;
        split_f16(tile[tx][ty + i], h, l);
        __half* row = dst + (size_t)n * GK;
        row[k]     = h;
        row[K + k] = l;
    }
}

// ---------------------------------------------------------------------------
// fp16 mma.sync GEMM, templated on CTA N-tile width.
// K' = 2048 (full fp16 2-term product). Same pipeline as R10.
// ---------------------------------------------------------------------------
#define BMt 128
#define BKt 32
#define PADt 40
#define NCHt (GK/BKt)           // 64
#define STAGES 4
#define GEMM_SMEM_FOR(BN) (STAGES * (BMt + (BN)) * PADt * 2)

template<int BN>
__global__ __launch_bounds__(256, 2) void gemm_mma(const __half* __restrict__ A,
                                                   const __half* __restrict__ Bt,
                                                   float* __restrict__ C, int N) {
    constexpr int WN = BN / 4;
    constexpr int NT = WN / 8;
    constexpr int NP = WN / 16;
    constexpr int SEL = (BMt + BN) * PADt;
    constexpr int TOTCH = (BMt + BN) * 4;

    extern __shared__ __half gsm[];
    uint32_t smb = smem_u32(gsm);

    int t = threadIdx.x, w = t >> 5, lane = t & 31;
    int m0 = blockIdx.y * BMt, n0 = blockIdx.x * BN;
    int wm = (w >> 2) * 64;
    int wn = (w & 3) * WN;

    float acc[4][NT][4];
#pragma unroll
    for (int i = 0; i < 4; i++)
#pragma unroll
        for (int j = 0; j < NT; j++)
#pragma unroll
            for (int r = 0; r < 4; r++) acc[i][j][r] = 0.f;

    const __half* Ab = A  + (size_t)m0 * GK;
    const __half* Bb = Bt + (size_t)n0 * GK;

    auto load_tile = [&](int kc, int s) {
        if (kc < NCHt) {
            uint32_t ab = smb + s * (SEL * 2);
            uint32_t bb = ab + BMt * PADt * 2;
            const __half* Ak = Ab + kc * BKt;
            const __half* Bk = Bb + kc * BKt;
#pragma unroll
            for (int i = 0; i < TOTCH / 256; i++) {
                int idx = t + i * 256;
                int row = idx >> 2, ch = idx & 3;
                if (row < BMt)
                    cp16(ab + (row * PADt + ch * 8) * 2, Ak + (size_t)row * GK + ch * 8);
                else {
                    int r = row - BMt;
                    cp16(bb + (r * PADt + ch * 8) * 2, Bk + (size_t)r * GK + ch * 8);
                }
            }
        }
        CP_COMMIT();
    };

#pragma unroll
    for (int s = 0; s < STAGES - 1; s++) load_tile(s, s);

    int li = lane >> 3;
    int lr = lane & 7;

    for (int kc = 0; kc < NCHt; kc++) {
        CP_WAIT(STAGES - 2);
        __syncthreads();
        load_tile(kc + STAGES - 1, (kc + STAGES - 1) % STAGES);

        int s = kc % STAGES;
        uint32_t ab = smb + s * (SEL * 2);
        uint32_t bb = ab + BMt * PADt * 2;

#pragma unroll
        for (int ks = 0; ks < 2; ks++) {
            int k0 = ks * 16;
            uint32_t a[4][4];
#pragma unroll
            for (int mt = 0; mt < 4; mt++) {
                int row = wm + mt * 16 + (li & 1) * 8 + lr;
                int col = k0 + (li >> 1) * 8;
                ldsm4(a[mt][0], a[mt][1], a[mt][2], a[mt][3],
                      ab + (row * PADt + col) * 2);
            }
            uint32_t b[NP][4];
#pragma unroll
            for (int p = 0; p < NP; p++) {
                int row = wn + p * 16 + (li >> 1) * 8 + lr;
                int col = k0 + (li & 1) * 8;
                ldsm4(b[p][0], b[p][1], b[p][2], b[p][3],
                      bb + (row * PADt + col) * 2);
            }
#pragma unroll
            for (int mt = 0; mt < 4; mt++)
#pragma unroll
                for (int nt = 0; nt < NT; nt++) {
                    int p = nt >> 1, off = (nt & 1) * 2;
                    mma16816h(acc[mt][nt], a[mt][0], a[mt][1], a[mt][2], a[mt][3],
                              b[p][off], b[p][off + 1]);
                }
        }
    }

    int cr = lane >> 2, cc = (lane & 3) * 2;
#pragma unroll
    for (int mt = 0; mt < 4; mt++)
#pragma unroll
        for (int nt = 0; nt < NT; nt++) {
            float* Cp = C + (size_t)(m0 + wm + mt * 16 + cr) * N + n0 + wn + nt * 8 + cc;
            *(float2*)Cp = make_float2(acc[mt][nt][0], acc[mt][nt][1]);
            *(float2*)(Cp + 8 * (size_t)N) = make_float2(acc[mt][nt][2], acc[mt][nt][3]);
        }
}

// ---------------------------------------------------------------------------
// finish_q / finish_k: RoPE + fp16 [hi|lo] split (128 cols)
// ---------------------------------------------------------------------------
__global__ __launch_bounds__(256) void finish_q(const float* __restrict__ qkv,
                                                const float* __restrict__ cosT,
                                                const float* __restrict__ sinT,
                                                __half* __restrict__ qb) {
    int idx = blockIdx.x * 256 + threadIdx.x;
    const int total = BATCH * SEQ * NH * 32;
    if (idx >= total) return;
    int j = idx & 31;
    int rest = idx >> 5;
    int h = rest % NH;
    int row = rest / NH;
    int s = row % SEQ, b = row / SEQ;

    const float* src = qkv + (size_t)row * NQKV + h * 64;
    float c  = cosT[s * 32 + j];
    float sn = sinT[s * 32 + j];
    float x1 = src[j], x2 = src[j + 32];
    float y1 = x1 * c - x2 * sn;
    float y2 = x2 * c + x1 * sn;

    __half h1, l1, h2, l2;
    split_f16(y1, h1, l1);
    split_f16(y2, h2, l2);
    __half* d = qb + ((size_t)(b * NH + h) * SEQ + s) * 128;
    d[j]       = h1;  d[j + 32]  = h2;   // hi
    d[64 + j]  = l1;  d[96 + j]  = l2;   // lo
}

__global__ __launch_bounds__(256) void finish_k(const float* __restrict__ qkv,
                                                const float* __restrict__ cosT,
                                                const float* __restrict__ sinT,
                                                float* __restrict__ kout,
                                                __half* __restrict__ kb) {
    int idx = blockIdx.x * 256 + threadIdx.x;
    const int total = BATCH * SEQ * NKV * 32;
    if (idx >= total) return;
    int j = idx & 31;
    int rest = idx >> 5;
    int kvh = rest % NKV;
    int row = rest / NKV;
    int s = row % SEQ, b = row / SEQ;

    const float* src = qkv + (size_t)row * NQKV + 1024 + kvh * 64;
    float c  = cosT[s * 32 + j];
    float sn = sinT[s * 32 + j];
    float x1 = src[j], x2 = src[j + 32];
    float y1 = x1 * c - x2 * sn;
    float y2 = x2 * c + x1 * sn;

    float* ko = kout + ((size_t)row * NKV + kvh) * 64;
    ko[j] = y1;
    ko[j + 32] = y2;

    __half h1, l1, h2, l2;
    split_f16(y1, h1, l1);
    split_f16(y2, h2, l2);
    __half* d = kb + ((size_t)(b * NKV + kvh) * SEQ + s) * 128;
    d[j]       = h1;  d[j + 32]  = h2;   // hi
    d[64 + j]  = l1;  d[96 + j]  = l2;   // lo
}

// finish_v: fp32 new_v to d_out + transposed single-fp16 V
__global__ void finish_v(const float* __restrict__ qkv,
                         float* __restrict__ vout,
                         __half* __restrict__ vf) {
    __shared__ float tile[32][33];
    int bkv = blockIdx.z;
    int b = bkv / NKV, kvh = bkv % NKV;
    int s0 = blockIdx.x * 32, d0 = blockIdx.y * 32;
    int tx = threadIdx.x, ty = threadIdx.y;
#pragma unroll
    for (int i = 0; i < 32; i += 8) {
        int s = s0 + ty + i;
        float v = qkv[((size_t)b * SEQ + s) * NQKV + 1280 + kvh * 64 + d0 + tx];
        tile[ty + i][tx] = v;
        vout[(((size_t)b * SEQ + s) * NKV + kvh) * 64 + d0 + tx] = v;
    }
    __syncthreads();
#pragma unroll
    for (int i = 0; i < 32; i += 8) {
        int d = d0 + ty + i, s = s0 + tx;
        vf[((size_t)bkv * HD + d) * SEQ + s] = __float2half(tile[tx][ty + i]);
    }
}

// ---------------------------------------------------------------------------
// Tensor-core flash attention, all-fp16.
// S: fp16 [hi|lo] x [hi|lo] full product (8 ksteps over 128 cols).
// PV: single-fp16 (4 ksteps).
// ---------------------------------------------------------------------------
#define APAD 136
#define VPAD2 72
#define ATTN2_SMEM ((2 * 64 * APAD + 64 * VPAD2) * 2)

__global__ __launch_bounds__(128) void attn_mma(const __half* __restrict__ Qb,
                                                const __half* __restrict__ Kb,
                                                const __half* __restrict__ Vf,
                                                __half* __restrict__ aoc) {
    extern __shared__ __half sh[];
    __half* qs = sh;
    __half* ks = sh + 64 * APAD;
    __half* vs = sh + 2 * 64 * APAD;
    uint32_t qsa = smem_u32(qs), ksa = smem_u32(ks), vsa = smem_u32(vs);

    int t = threadIdx.x, w = t >> 5, lane = t & 31;
    int qt = gridDim.x - 1 - blockIdx.x;   // longest CTAs first
    int h = blockIdx.y, b = blockIdx.z;
    int kvh = h >> 2;
    int li = lane >> 3, lr = lane & 7;
    int r0 = lane >> 2;
    int cc = (lane & 3) * 2;

    const __half* ksrc0 = Kb + (size_t)(b * NKV + kvh) * SEQ * 128;
    const __half* vf0 = Vf + (size_t)(b * NKV + kvh) * HD * SEQ;

    auto issueK = [&](int kt) {
        const __half* ksrc = ksrc0 + (size_t)kt * 64 * 128;
#pragma unroll
        for (int i = 0; i < 8; i++) {
            int c = t + 128 * i;
            int row = c >> 4, seg = c & 15;
            cp16(ksa + (row * APAD + seg * 8) * 2, ksrc + (size_t)row * 128 + seg * 8);
        }
        CP_COMMIT();
    };
    auto issueV = [&](int kt) {
#pragma unroll
        for (int i = 0; i < 4; i++) {
            int c = t + 128 * i;
            int d = c >> 3, seg = c & 7;
            cp16(vsa + (d * VPAD2 + seg * 8) * 2,
                 vf0 + (size_t)d * SEQ + kt * 64 + seg * 8);
        }
        CP_COMMIT();
    };

    // Prologue: Q tile, then K(0), V(0)
    const __half* qsrc = Qb + ((size_t)(b * NH + h) * SEQ + (size_t)qt * 64) * 128;
#pragma unroll
    for (int i = 0; i < 8; i++) {
        int c = t + 128 * i;
        int row = c >> 4, seg = c & 15;
        cp16(qsa + (row * APAD + seg * 8) * 2, qsrc + (size_t)row * 128 + seg * 8);
    }
    CP_COMMIT();
    issueK(0);
    issueV(0);

    float m0 = -1e30f, m1 = -1e30f, l0 = 0.f, l1 = 0.f;
    float of[8][4];
#pragma unroll
    for (int j = 0; j < 8; j++)
#pragma unroll
        for (int e = 0; e < 4; e++) of[j][e] = 0.f;

    for (int kt = 0; kt <= qt; kt++) {
        CP_WAIT(1);         // Q + K(kt) landed; V(kt) may be in flight
        __syncthreads();

        // ---- S = Q K^T: full fp16 2-term product, 8 ksteps over 128 cols ----
        float sf[8][4];
#pragma unroll
        for (int j = 0; j < 8; j++)
#pragma unroll
            for (int e = 0; e < 4; e++) sf[j][e] = 0.f;
#pragma unroll
        for (int ks8 = 0; ks8 < 8; ks8++) {
            int col = ks8 * 16;
            uint32_t a0, a1, a2, a3;
            ldsm4(a0, a1, a2, a3,
                  qsa + ((w * 16 + (li & 1) * 8 + lr) * APAD + col + (li >> 1) * 8) * 2);
#pragma unroll
            for (int p = 0; p < 4; p++) {
                uint32_t b0, b1, b2, b3;
                ldsm4(b0, b1, b2, b3,
                      ksa + ((p * 16 + (li >> 1) * 8 + lr) * APAD + col + (li & 1) * 8) * 2);
                mma16816h(sf[2 * p],     a0, a1, a2, a3, b0, b1);
                mma16816h(sf[2 * p + 1], a0, a1, a2, a3, b2, b3);
            }
        }

        if (kt == qt) {
            int q0 = w * 16 + r0, q1 = q0 + 8;
#pragma unroll
            for (int j = 0; j < 8; j++) {
                int key = 8 * j + cc;
                if (key     > q0) sf[j][0] = -1e30f;
                if (key + 1 > q0) sf[j][1] = -1e30f;
                if (key     > q1) sf[j][2] = -1e30f;
                if (key + 1 > q1) sf[j][3] = -1e30f;
            }
        }

        // ---- online softmax ----
        float mx0 = -1e30f, mx1 = -1e30f;
#pragma unroll
        for (int j = 0; j < 8; j++) {
            mx0 = fmaxf(mx0, fmaxf(sf[j][0], sf[j][1]));
            mx1 = fmaxf(mx1, fmaxf(sf[j][2], sf[j][3]));
        }
        mx0 = fmaxf(mx0, __shfl_xor_sync(0xffffffffu, mx0, 1));
        mx0 = fmaxf(mx0, __shfl_xor_sync(0xffffffffu, mx0, 2));
        mx1 = fmaxf(mx1, __shfl_xor_sync(0xffffffffu, mx1, 1));
        mx1 = fmaxf(mx1, __shfl_xor_sync(0xffffffffu, mx1, 2));
        float nm0 = fmaxf(m0, mx0), nm1 = fmaxf(m1, mx1);
        float al0 = __expf(m0 - nm0), al1 = __expf(m1 - nm1);
        m0 = nm0; m1 = nm1;

        float s0 = 0.f, s1 = 0.f;
#pragma unroll
        for (int j = 0; j < 8; j++) {
            sf[j][0] = __expf(sf[j][0] - m0); s0 += sf[j][0];
            sf[j][1] = __expf(sf[j][1] - m0); s0 += sf[j][1];
            sf[j][2] = __expf(sf[j][2] - m1); s1 += sf[j][2];
            sf[j][3] = __expf(sf[j][3] - m1); s1 += sf[j][3];
        }
        s0 += __shfl_xor_sync(0xffffffffu, s0, 1);
        s0 += __shfl_xor_sync(0xffffffffu, s0, 2);
        s1 += __shfl_xor_sync(0xffffffffu, s1, 1);
        s1 += __shfl_xor_sync(0xffffffffu, s1, 2);
        l0 = l0 * al0 + s0;
        l1 = l1 * al1 + s1;

#pragma unroll
        for (int j = 0; j < 8; j++) {
            of[j][0] *= al0; of[j][1] *= al0;
            of[j][2] *= al1; of[j][3] *= al1;
        }

        // ---- pack P into single-fp16 A-fragments ----
        uint32_t ah[4][4];
#pragma unroll
        for (int kk = 0; kk < 4; kk++) {
            ah[kk][0] = pack_f16(sf[2 * kk][0],     sf[2 * kk][1]);
            ah[kk][1] = pack_f16(sf[2 * kk][2],     sf[2 * kk][3]);
            ah[kk][2] = pack_f16(sf[2 * kk + 1][0], sf[2 * kk + 1][1]);
            ah[kk][3] = pack_f16(sf[2 * kk + 1][2], sf[2 * kk + 1][3]);
        }

        CP_WAIT(0);          // V(kt) landed
        __syncthreads();     // all warps done with ks reads; vs visible

        // ks dead: prefetch K(kt+1), overlapping PV
        if (kt < qt) issueK(kt + 1);

        // ---- O += P V (fp16, 4 ksteps) ----
#pragma unroll
        for (int ks4 = 0; ks4 < 4; ks4++) {
            uint32_t* A = ah[ks4];
            int k0 = ks4 * 16;
#pragma unroll
            for (int p = 0; p < 4; p++) {
                uint32_t b0, b1, b2, b3;
                ldsm4(b0, b1, b2, b3,
                      vsa + ((p * 16 + (li >> 1) * 8 + lr) * VPAD2 + k0 + (li & 1) * 8) * 2);
                mma16816h(of[2 * p],     A[0], A[1], A[2], A[3], b0, b1);
                mma16816h(of[2 * p + 1], A[0], A[1], A[2], A[3], b2, b3);
            }
        }
        __syncthreads();     // all warps done with vs reads

        // vs dead: prefetch V(kt+1), overlapping next tile's S phase
        if (kt < qt) issueV(kt + 1);
    }

    // ---- epilogue: write fp16 [hi|lo] directly into aoc ----
    float inv0 = 1.f / l0, inv1 = 1.f / l1;
    int row0 = b * SEQ + qt * 64 + w * 16 + r0;
    int row1 = row0 + 8;
#pragma unroll
    for (int j = 0; j < 8; j++) {
        int colq = h * 64 + 8 * j + cc;
        {
            float v0 = of[j][0] * inv0, v1 = of[j][1] * inv0;
            uint32_t hp = pack_f16(v0, v1);
            __half2 hb = *(__half2*)&hp;
            uint32_t lp = pack_f16(v0 - __half2float(hb.x), v1 - __half2float(hb.y));
            uint32_t* base = (uint32_t*)(aoc + (size_t)row0 * GK + colq);
            base[0]                              = hp;
            *(uint32_t*)((char*)base + 1024 * 2) = lp;
        }
        {
            float v0 = of[j][2] * inv1, v1 = of[j][3] * inv1;
            uint32_t hp = pack_f16(v0, v1);
            __half2 hb = *(__half2*)&hp;
            uint32_t lp = pack_f16(v0 - __half2float(hb.x), v1 - __half2float(hb.y));
            uint32_t* base = (uint32_t*)(aoc + (size_t)row1 * GK + colq);
            base[0]                              = hp;
            *(uint32_t*)((char*)base + 1024 * 2) = lp;
        }
    }
}

// ---------------------------------------------------------------------------
extern "C" void kernel_launch(void* const* d_in, const int* in_sizes, int n_in,
                              void* d_out, int out_size) {
    const float* x    = (const float*)d_in[0];
    const float* cosT = (const float*)d_in[1];
    const float* sinT = (const float*)d_in[2];
    // d_in[3] = mask: unused
    const float* wq   = (const float*)d_in[4];
    const float* wk   = (const float*)d_in[5];
    const float* wv   = (const float*)d_in[6];
    const float* wo   = (const float*)d_in[7];

    float* out  = (float*)d_out;
    float* kout = out + OUT_ELEMS;
    float* vout = out + OUT_ELEMS + KV_ELEMS;

    float* qkv;
    __half *xc, *aoc, *wqkvt, *wot, *qb, *kb, *vf;
    cudaGetSymbolAddress((void**)&qkv, g_qkv);
    cudaGetSymbolAddress((void**)&xc,  g_xc);
    cudaGetSymbolAddress((void**)&aoc, g_aoc);
    cudaGetSymbolAddress((void**)&wqkvt, g_wqkvt);
    cudaGetSymbolAddress((void**)&wot, g_wot);
    cudaGetSymbolAddress((void**)&qb,  g_qb);
    cudaGetSymbolAddress((void**)&kb,  g_kb);
    cudaGetSymbolAddress((void**)&vf,  g_vf);

    cudaFuncSetAttribute(attn_mma, cudaFuncAttributeMaxDynamicSharedMemorySize, ATTN2_SMEM);
    cudaFuncSetAttribute(gemm_mma<128>, cudaFuncAttributeMaxDynamicSharedMemorySize,
                         GEMM_SMEM_FOR(128));
    cudaFuncSetAttribute(gemm_mma<192>, cudaFuncAttributeMaxDynamicSharedMemorySize,
                         GEMM_SMEM_FOR(192));

    // Split conversions (fp16 [hi|lo])
    conv_a<<<(MTOT * DMODEL / 4 + 255) / 256, 256>>>(x, xc);
    dim3 wb(32, 8);
    conv_qkv<<<dim3(NQKV / 32, DMODEL / 32), wb>>>(wq, wk, wv, wqkvt);
    conv_w<<<dim3(DMODEL / 32, DMODEL / 32), wb>>>(wo, wot, DMODEL);

    // Fused QKV projection: 128x192 tiles -> 256 CTAs = single wave
    gemm_mma<192><<<dim3(NQKV / 192, MTOT / 128), 256, GEMM_SMEM_FOR(192)>>>(
        xc, wqkvt, qkv, NQKV);

    // RoPE + fp16 split + fp32 kv-cache outputs
    finish_q<<<(BATCH * SEQ * NH * 32 + 255) / 256, 256>>>(qkv, cosT, sinT, qb);
    finish_k<<<(BATCH * SEQ * NKV * 32 + 255) / 256, 256>>>(qkv, cosT, sinT, kout, kb);
    finish_v<<<dim3(SEQ / 32, HD / 32, BATCH * NKV), dim3(32, 8)>>>(qkv, vout, vf);

    // Tensor-core flash attention (all-fp16, pipelined prefetch)
    attn_mma<<<dim3(SEQ / 64, NH, BATCH), 128, ATTN2_SMEM>>>(qb, kb, vf, aoc);

    // Output projection
    gemm_mma<128><<<dim3(DMODEL / 128, MTOT / 128), 256, GEMM_SMEM_FOR(128)>>>(
        aoc, wot, out, DMODEL);
}

// round 16
// speedup vs baseline: 1.7742x; 1.1227x over previous
#include <cuda_runtime.h>
#include <cuda_bf16.h>
#include <cuda_fp16.h>
#include <cstdint>

// Problem constants
#define BATCH 2
#define SEQ 2048
#define DMODEL 1024
#define NH 16
#define NKV 4
#define HD 64
#define OUT_ELEMS  (BATCH*SEQ*DMODEL)
#define KV_ELEMS   (BATCH*SEQ*NKV*HD)

#define MTOT (BATCH*SEQ)        // 4096
#define GK   (2*DMODEL)         // 2048: fp16 [hi|lo] x [hi|lo] = FULL product
#define GKO  (DMODEL)           // 1024: WO single-fp16
#define NQKV 1536               // fused QKV output width

// ---------------------------------------------------------------------------
// Scratch (device globals; no runtime allocation allowed)
// ---------------------------------------------------------------------------
__device__ float g_qkv[MTOT*NQKV];                   // fused QKV gemm output
__device__ __half g_xc   [MTOT*GK];                  // x split [M, 2K]
__device__ __half g_aoc  [MTOT*GKO];                 // attn out single fp16 [M, K]
__device__ __half g_wqkvt[NQKV*GK];                  // [wq|wk|wv]^T split
__device__ __half g_wot  [DMODEL*GKO];               // wo^T single fp16
// Attention operands
__device__ __half g_qb [BATCH*NH*SEQ*128];           // [b][h][s][hi|lo]
__device__ __half g_kb [BATCH*NKV*SEQ*128];          // [b][kvh][s][hi|lo]
__device__ __half g_vf [BATCH*NKV*HD*SEQ];           // [b][kvh][d][s] fp16

// ---------------------------------------------------------------------------
// Baseline-PTX helpers
// ---------------------------------------------------------------------------
__device__ __forceinline__ uint32_t smem_u32(const void* p) {
    uint32_t a;
    asm("{ .reg .u64 t; cvta.to.shared.u64 t, %1; cvt.u32.u64 %0, t; }" : "=r"(a) : "l"(p));
    return a;
}
__device__ __forceinline__ void cp16(uint32_t saddr, const void* g) {
    asm volatile("cp.async.cg.shared.global [%0], [%1], 16;" :: "r"(saddr), "l"(g) : "memory");
}
#define CP_COMMIT() asm volatile("cp.async.commit_group;" ::: "memory")
#define CP_WAIT(n)  asm volatile("cp.async.wait_group %0;" :: "n"(n) : "memory")

__device__ __forceinline__ void ldsm4(uint32_t& r0, uint32_t& r1, uint32_t& r2, uint32_t& r3,
                                      uint32_t a) {
    asm volatile("ldmatrix.sync.aligned.m8n8.x4.shared.b16 {%0,%1,%2,%3}, [%4];"
                 : "=r"(r0), "=r"(r1), "=r"(r2), "=r"(r3) : "r"(a));
}
__device__ __forceinline__ void mma16816h(float* c, uint32_t a0, uint32_t a1, uint32_t a2,
                                          uint32_t a3, uint32_t b0, uint32_t b1) {
    asm volatile(
        "mma.sync.aligned.m16n8k16.row.col.f32.f16.f16.f32 "
        "{%0,%1,%2,%3},{%4,%5,%6,%7},{%8,%9},{%0,%1,%2,%3};"
        : "+f"(c[0]), "+f"(c[1]), "+f"(c[2]), "+f"(c[3])
        : "r"(a0), "r"(a1), "r"(a2), "r"(a3), "r"(b0), "r"(b1));
}
__device__ __forceinline__ uint32_t pack_f16(float x, float y) {
    uint32_t r;
    asm("cvt.rn.f16x2.f32 %0, %1, %2;" : "=r"(r) : "f"(y), "f"(x));
    return r;
}
__device__ __forceinline__ void split_f16(float v, __half& hi, __half& lo) {
    hi = __float2half(v);
    lo = __float2half(v - __half2float(hi));
}

// ---------------------------------------------------------------------------
// A-side split: src [M, K] fp32 -> dst [M, 2K] = [hi | lo]
// ---------------------------------------------------------------------------
__global__ __launch_bounds__(256) void conv_a(const float* __restrict__ src,
                                              __half* __restrict__ dst) {
    int idx = blockIdx.x * blockDim.x + threadIdx.x;
    const int K = DMODEL;
    if (idx >= MTOT * K / 4) return;
    int flat = idx * 4;
    int m = flat / K, k = flat % K;
    float4 v = *(const float4*)(src + flat);
    float vv[4] = {v.x, v.y, v.z, v.w};
    __half h[4], l[4];
#pragma unroll
    for (int j = 0; j < 4; j++) split_f16(vv[j], h[j], l[j]);
    __half* row = dst + (size_t)m * GK;
    *(uint2*)(row + k)     = *(uint2*)h;
    *(uint2*)(row + K + k) = *(uint2*)l;
}

// Fused weight split for [wq|wk|wv] -> wqkvt [1536, 2K]
__global__ void conv_qkv(const float* __restrict__ wq, const float* __restrict__ wk,
                         const float* __restrict__ wv, __half* __restrict__ dst) {
    __shared__ float tile[32][33];
    const int K = DMODEL;
    int k0 = blockIdx.y * 32, n0 = blockIdx.x * 32;
    const float* src;
    int nloc, N;
    float scale = 1.f;
    if (n0 < 1024)      { src = wq; nloc = n0;        N = 1024; scale = 0.125f; }
    else if (n0 < 1280) { src = wk; nloc = n0 - 1024; N = 256; }
    else                { src = wv; nloc = n0 - 1280; N = 256; }
    int tx = threadIdx.x, ty = threadIdx.y;
#pragma unroll
    for (int i = 0; i < 32; i += 8)
        tile[ty + i][tx] = src[(size_t)(k0 + ty + i) * N + nloc + tx] * scale;
    __syncthreads();
#pragma unroll
    for (int i = 0; i < 32; i += 8) {
        int n = n0 + ty + i, k = k0 + tx;
        __half h, l;
        split_f16(tile[tx][ty + i], h, l);
        __half* row = dst + (size_t)n * GK;
        row[k]     = h;
        row[K + k] = l;
    }
}

// wo -> wot [1024, 1024] single fp16 (transposed)
__global__ void conv_w(const float* __restrict__ src, __half* __restrict__ dst,
                       int N) {
    __shared__ float tile[32][33];
    int k0 = blockIdx.y * 32, n0 = blockIdx.x * 32;
    int tx = threadIdx.x, ty = threadIdx.y;
#pragma unroll
    for (int i = 0; i < 32; i += 8)
        tile[ty + i][tx] = src[(size_t)(k0 + ty + i) * N + n0 + tx];
    __syncthreads();
#pragma unroll
    for (int i = 0; i < 32; i += 8) {
        int n = n0 + ty + i, k = k0 + tx;
        dst[(size_t)n * GKO + k] = __float2half(tile[tx][ty + i]);
    }
}

// ---------------------------------------------------------------------------
// fp16 mma.sync GEMM, templated on CTA N-tile width and contraction depth.
// ---------------------------------------------------------------------------
#define BMt 128
#define BKt 32
#define PADt 40
#define STAGES 4
#define GEMM_SMEM_FOR(BN) (STAGES * (BMt + (BN)) * PADt * 2)

template<int BN, int KK>
__global__ __launch_bounds__(256, 2) void gemm_mma(const __half* __restrict__ A,
                                                   const __half* __restrict__ Bt,
                                                   float* __restrict__ C, int N) {
    constexpr int WN = BN / 4;
    constexpr int NT = WN / 8;
    constexpr int NP = WN / 16;
    constexpr int SEL = (BMt + BN) * PADt;
    constexpr int TOTCH = (BMt + BN) * 4;
    constexpr int NCH = KK / BKt;

    extern __shared__ __half gsm[];
    uint32_t smb = smem_u32(gsm);

    int t = threadIdx.x, w = t >> 5, lane = t & 31;
    int m0 = blockIdx.y * BMt, n0 = blockIdx.x * BN;
    int wm = (w >> 2) * 64;
    int wn = (w & 3) * WN;

    float acc[4][NT][4];
#pragma unroll
    for (int i = 0; i < 4; i++)
#pragma unroll
        for (int j = 0; j < NT; j++)
#pragma unroll
            for (int r = 0; r < 4; r++) acc[i][j][r] = 0.f;

    const __half* Ab = A  + (size_t)m0 * KK;
    const __half* Bb = Bt + (size_t)n0 * KK;

    auto load_tile = [&](int kc, int s) {
        if (kc < NCH) {
            uint32_t ab = smb + s * (SEL * 2);
            uint32_t bb = ab + BMt * PADt * 2;
            const __half* Ak = Ab + kc * BKt;
            const __half* Bk = Bb + kc * BKt;
#pragma unroll
            for (int i = 0; i < TOTCH / 256; i++) {
                int idx = t + i * 256;
                int row = idx >> 2, ch = idx & 3;
                if (row < BMt)
                    cp16(ab + (row * PADt + ch * 8) * 2, Ak + (size_t)row * KK + ch * 8);
                else {
                    int r = row - BMt;
                    cp16(bb + (r * PADt + ch * 8) * 2, Bk + (size_t)r * KK + ch * 8);
                }
            }
        }
        CP_COMMIT();
    };

#pragma unroll
    for (int s = 0; s < STAGES - 1; s++) load_tile(s, s);

    int li = lane >> 3;
    int lr = lane & 7;

    for (int kc = 0; kc < NCH; kc++) {
        CP_WAIT(STAGES - 2);
        __syncthreads();
        load_tile(kc + STAGES - 1, (kc + STAGES - 1) % STAGES);

        int s = kc % STAGES;
        uint32_t ab = smb + s * (SEL * 2);
        uint32_t bb = ab + BMt * PADt * 2;

#pragma unroll
        for (int ks = 0; ks < 2; ks++) {
            int k0 = ks * 16;
            uint32_t a[4][4];
#pragma unroll
            for (int mt = 0; mt < 4; mt++) {
                int row = wm + mt * 16 + (li & 1) * 8 + lr;
                int col = k0 + (li >> 1) * 8;
                ldsm4(a[mt][0], a[mt][1], a[mt][2], a[mt][3],
                      ab + (row * PADt + col) * 2);
            }
            uint32_t b[NP][4];
#pragma unroll
            for (int p = 0; p < NP; p++) {
                int row = wn + p * 16 + (li >> 1) * 8 + lr;
                int col = k0 + (li & 1) * 8;
                ldsm4(b[p][0], b[p][1], b[p][2], b[p][3],
                      bb + (row * PADt + col) * 2);
            }
#pragma unroll
            for (int mt = 0; mt < 4; mt++)
#pragma unroll
                for (int nt = 0; nt < NT; nt++) {
                    int p = nt >> 1, off = (nt & 1) * 2;
                    mma16816h(acc[mt][nt], a[mt][0], a[mt][1], a[mt][2], a[mt][3],
                              b[p][off], b[p][off + 1]);
                }
        }
    }

    int cr = lane >> 2, cc = (lane & 3) * 2;
#pragma unroll
    for (int mt = 0; mt < 4; mt++)
#pragma unroll
        for (int nt = 0; nt < NT; nt++) {
            float* Cp = C + (size_t)(m0 + wm + mt * 16 + cr) * N + n0 + wn + nt * 8 + cc;
            *(float2*)Cp = make_float2(acc[mt][nt][0], acc[mt][nt][1]);
            *(float2*)(Cp + 8 * (size_t)N) = make_float2(acc[mt][nt][2], acc[mt][nt][3]);
        }
}

// ---------------------------------------------------------------------------
// finish_qk: fused RoPE + fp16 [hi|lo] split for q and k; fp32 new_k out.
// ---------------------------------------------------------------------------
__global__ __launch_bounds__(256) void finish_qk(const float* __restrict__ qkv,
                                                 const float* __restrict__ cosT,
                                                 const float* __restrict__ sinT,
                                                 float* __restrict__ kout,
                                                 __half* __restrict__ qb,
                                                 __half* __restrict__ kb) {
    int idx = blockIdx.x * 256 + threadIdx.x;
    const int total = BATCH * SEQ * (NH + NKV) * 32;
    if (idx >= total) return;
    int j = idx & 31;
    int rest = idx >> 5;
    int head = rest % (NH + NKV);
    int row = rest / (NH + NKV);
    int s = row % SEQ, b = row / SEQ;

    float c  = cosT[s * 32 + j];
    float sn = sinT[s * 32 + j];

    const float* src;
    if (head < NH) src = qkv + (size_t)row * NQKV + head * 64;
    else           src = qkv + (size_t)row * NQKV + 1024 + (head - NH) * 64;

    float x1 = src[j], x2 = src[j + 32];
    float y1 = x1 * c - x2 * sn;
    float y2 = x2 * c + x1 * sn;

    __half h1, l1, h2, l2;
    split_f16(y1, h1, l1);
    split_f16(y2, h2, l2);

    if (head < NH) {
        __half* d = qb + ((size_t)(b * NH + head) * SEQ + s) * 128;
        d[j]      = h1;  d[j + 32] = h2;
        d[64 + j] = l1;  d[96 + j] = l2;
    } else {
        int kvh = head - NH;
        float* ko = kout + ((size_t)row * NKV + kvh) * 64;
        ko[j] = y1;
        ko[j + 32] = y2;
        __half* d = kb + ((size_t)(b * NKV + kvh) * SEQ + s) * 128;
        d[j]      = h1;  d[j + 32] = h2;
        d[64 + j] = l1;  d[96 + j] = l2;
    }
}

// finish_v: fp32 new_v to d_out + transposed single-fp16 V
__global__ void finish_v(const float* __restrict__ qkv,
                         float* __restrict__ vout,
                         __half* __restrict__ vf) {
    __shared__ float tile[32][33];
    int bkv = blockIdx.z;
    int b = bkv / NKV, kvh = bkv % NKV;
    int s0 = blockIdx.x * 32, d0 = blockIdx.y * 32;
    int tx = threadIdx.x, ty = threadIdx.y;
#pragma unroll
    for (int i = 0; i < 32; i += 8) {
        int s = s0 + ty + i;
        float v = qkv[((size_t)b * SEQ + s) * NQKV + 1280 + kvh * 64 + d0 + tx];
        tile[ty + i][tx] = v;
        vout[(((size_t)b * SEQ + s) * NKV + kvh) * 64 + d0 + tx] = v;
    }
    __syncthreads();
#pragma unroll
    for (int i = 0; i < 32; i += 8) {
        int d = d0 + ty + i, s = s0 + tx;
        vf[((size_t)bkv * HD + d) * SEQ + s] = __float2half(tile[tx][ty + i]);
    }
}

// ---------------------------------------------------------------------------
// Tensor-core flash attention, all-fp16.
// S: fp16 [hi|lo] x [hi|lo] full product (8 ksteps). PV: single fp16 (4).
// Epilogue writes single-fp16 aoc [M, 1024].
// ---------------------------------------------------------------------------
#define APAD 136
#define VPAD2 72
#define ATTN2_SMEM ((2 * 64 * APAD + 64 * VPAD2) * 2)

__global__ __launch_bounds__(128) void attn_mma(const __half* __restrict__ Qb,
                                                const __half* __restrict__ Kb,
                                                const __half* __restrict__ Vf,
                                                __half* __restrict__ aoc) {
    extern __shared__ __half sh[];
    __half* qs = sh;
    __half* ks = sh + 64 * APAD;
    __half* vs = sh + 2 * 64 * APAD;
    uint32_t qsa = smem_u32(qs), ksa = smem_u32(ks), vsa = smem_u32(vs);

    int t = threadIdx.x, w = t >> 5, lane = t & 31;
    int qt = gridDim.x - 1 - blockIdx.x;   // longest CTAs first
    int h = blockIdx.y, b = blockIdx.z;
    int kvh = h >> 2;
    int li = lane >> 3, lr = lane & 7;
    int r0 = lane >> 2;
    int cc = (lane & 3) * 2;

    const __half* ksrc0 = Kb + (size_t)(b * NKV + kvh) * SEQ * 128;
    const __half* vf0 = Vf + (size_t)(b * NKV + kvh) * HD * SEQ;

    auto issueK = [&](int kt) {
        const __half* ksrc = ksrc0 + (size_t)kt * 64 * 128;
#pragma unroll
        for (int i = 0; i < 8; i++) {
            int c = t + 128 * i;
            int row = c >> 4, seg = c & 15;
            cp16(ksa + (row * APAD + seg * 8) * 2, ksrc + (size_t)row * 128 + seg * 8);
        }
        CP_COMMIT();
    };
    auto issueV = [&](int kt) {
#pragma unroll
        for (int i = 0; i < 4; i++) {
            int c = t + 128 * i;
            int d = c >> 3, seg = c & 7;
            cp16(vsa + (d * VPAD2 + seg * 8) * 2,
                 vf0 + (size_t)d * SEQ + kt * 64 + seg * 8);
        }
        CP_COMMIT();
    };

    // Prologue: Q tile, then K(0), V(0)
    const __half* qsrc = Qb + ((size_t)(b * NH + h) * SEQ + (size_t)qt * 64) * 128;
#pragma unroll
    for (int i = 0; i < 8; i++) {
        int c = t + 128 * i;
        int row = c >> 4, seg = c & 15;
        cp16(qsa + (row * APAD + seg * 8) * 2, qsrc + (size_t)row * 128 + seg * 8);
    }
    CP_COMMIT();
    issueK(0);
    issueV(0);

    float m0 = -1e30f, m1 = -1e30f, l0 = 0.f, l1 = 0.f;
    float of[8][4];
#pragma unroll
    for (int j = 0; j < 8; j++)
#pragma unroll
        for (int e = 0; e < 4; e++) of[j][e] = 0.f;

    for (int kt = 0; kt <= qt; kt++) {
        CP_WAIT(1);
        __syncthreads();

        // ---- S = Q K^T: full fp16 2-term product, 8 ksteps ----
        float sf[8][4];
#pragma unroll
        for (int j = 0; j < 8; j++)
#pragma unroll
            for (int e = 0; e < 4; e++) sf[j][e] = 0.f;
#pragma unroll
        for (int ks8 = 0; ks8 < 8; ks8++) {
            int col = ks8 * 16;
            uint32_t a0, a1, a2, a3;
            ldsm4(a0, a1, a2, a3,
                  qsa + ((w * 16 + (li & 1) * 8 + lr) * APAD + col + (li >> 1) * 8) * 2);
#pragma unroll
            for (int p = 0; p < 4; p++) {
                uint32_t b0, b1, b2, b3;
                ldsm4(b0, b1, b2, b3,
                      ksa + ((p * 16 + (li >> 1) * 8 + lr) * APAD + col + (li & 1) * 8) * 2);
                mma16816h(sf[2 * p],     a0, a1, a2, a3, b0, b1);
                mma16816h(sf[2 * p + 1], a0, a1, a2, a3, b2, b3);
            }
        }

        if (kt == qt) {
            int q0 = w * 16 + r0, q1 = q0 + 8;
#pragma unroll
            for (int j = 0; j < 8; j++) {
                int key = 8 * j + cc;
                if (key     > q0) sf[j][0] = -1e30f;
                if (key + 1 > q0) sf[j][1] = -1e30f;
                if (key     > q1) sf[j][2] = -1e30f;
                if (key + 1 > q1) sf[j][3] = -1e30f;
            }
        }

        // ---- online softmax ----
        float mx0 = -1e30f, mx1 = -1e30f;
#pragma unroll
        for (int j = 0; j < 8; j++) {
            mx0 = fmaxf(mx0, fmaxf(sf[j][0], sf[j][1]));
            mx1 = fmaxf(mx1, fmaxf(sf[j][2], sf[j][3]));
        }
        mx0 = fmaxf(mx0, __shfl_xor_sync(0xffffffffu, mx0, 1));
        mx0 = fmaxf(mx0, __shfl_xor_sync(0xffffffffu, mx0, 2));
        mx1 = fmaxf(mx1, __shfl_xor_sync(0xffffffffu, mx1, 1));
        mx1 = fmaxf(mx1, __shfl_xor_sync(0xffffffffu, mx1, 2));
        float nm0 = fmaxf(m0, mx0), nm1 = fmaxf(m1, mx1);
        float al0 = __expf(m0 - nm0), al1 = __expf(m1 - nm1);
        m0 = nm0; m1 = nm1;

        float s0 = 0.f, s1 = 0.f;
#pragma unroll
        for (int j = 0; j < 8; j++) {
            sf[j][0] = __expf(sf[j][0] - m0); s0 += sf[j][0];
            sf[j][1] = __expf(sf[j][1] - m0); s0 += sf[j][1];
            sf[j][2] = __expf(sf[j][2] - m1); s1 += sf[j][2];
            sf[j][3] = __expf(sf[j][3] - m1); s1 += sf[j][3];
        }
        s0 += __shfl_xor_sync(0xffffffffu, s0, 1);
        s0 += __shfl_xor_sync(0xffffffffu, s0, 2);
        s1 += __shfl_xor_sync(0xffffffffu, s1, 1);
        s1 += __shfl_xor_sync(0xffffffffu, s1, 2);
        l0 = l0 * al0 + s0;
        l1 = l1 * al1 + s1;

#pragma unroll
        for (int j = 0; j < 8; j++) {
            of[j][0] *= al0; of[j][1] *= al0;
            of[j][2] *= al1; of[j][3] *= al1;
        }

        // ---- pack P into single-fp16 A-fragments ----
        uint32_t ah[4][4];
#pragma unroll
        for (int kk = 0; kk < 4; kk++) {
            ah[kk][0] = pack_f16(sf[2 * kk][0],     sf[2 * kk][1]);
            ah[kk][1] = pack_f16(sf[2 * kk][2],     sf[2 * kk][3]);
            ah[kk][2] = pack_f16(sf[2 * kk + 1][0], sf[2 * kk + 1][1]);
            ah[kk][3] = pack_f16(sf[2 * kk + 1][2], sf[2 * kk + 1][3]);
        }

        CP_WAIT(0);
        __syncthreads();

        if (kt < qt) issueK(kt + 1);

        // ---- O += P V (fp16, 4 ksteps) ----
#pragma unroll
        for (int ks4 = 0; ks4 < 4; ks4++) {
            uint32_t* A = ah[ks4];
            int k0 = ks4 * 16;
#pragma unroll
            for (int p = 0; p < 4; p++) {
                uint32_t b0, b1, b2, b3;
                ldsm4(b0, b1, b2, b3,
                      vsa + ((p * 16 + (li >> 1) * 8 + lr) * VPAD2 + k0 + (li & 1) * 8) * 2);
                mma16816h(of[2 * p],     A[0], A[1], A[2], A[3], b0, b1);
                mma16816h(of[2 * p + 1], A[0], A[1], A[2], A[3], b2, b3);
            }
        }
        __syncthreads();

        if (kt < qt) issueV(kt + 1);
    }

    // ---- epilogue: write single-fp16 aoc [M, 1024] ----
    float inv0 = 1.f / l0, inv1 = 1.f / l1;
    int row0 = b * SEQ + qt * 64 + w * 16 + r0;
    int row1 = row0 + 8;
#pragma unroll
    for (int j = 0; j < 8; j++) {
        int colq = h * 64 + 8 * j + cc;
        *(uint32_t*)(aoc + (size_t)row0 * GKO + colq) =
            pack_f16(of[j][0] * inv0, of[j][1] * inv0);
        *(uint32_t*)(aoc + (size_t)row1 * GKO + colq) =
            pack_f16(of[j][2] * inv1, of[j][3] * inv1);
    }
}

// ---------------------------------------------------------------------------
extern "C" void kernel_launch(void* const* d_in, const int* in_sizes, int n_in,
                              void* d_out, int out_size) {
    const float* x    = (const float*)d_in[0];
    const float* cosT = (const float*)d_in[1];
    const float* sinT = (const float*)d_in[2];
    // d_in[3] = mask: unused
    const float* wq   = (const float*)d_in[4];
    const float* wk   = (const float*)d_in[5];
    const float* wv   = (const float*)d_in[6];
    const float* wo   = (const float*)d_in[7];

    float* out  = (float*)d_out;
    float* kout = out + OUT_ELEMS;
    float* vout = out + OUT_ELEMS + KV_ELEMS;

    float* qkv;
    __half *xc, *aoc, *wqkvt, *wot, *qb, *kb, *vf;
    cudaGetSymbolAddress((void**)&qkv, g_qkv);
    cudaGetSymbolAddress((void**)&xc,  g_xc);
    cudaGetSymbolAddress((void**)&aoc, g_aoc);
    cudaGetSymbolAddress((void**)&wqkvt, g_wqkvt);
    cudaGetSymbolAddress((void**)&wot, g_wot);
    cudaGetSymbolAddress((void**)&qb,  g_qb);
    cudaGetSymbolAddress((void**)&kb,  g_kb);
    cudaGetSymbolAddress((void**)&vf,  g_vf);

    cudaFuncSetAttribute(attn_mma, cudaFuncAttributeMaxDynamicSharedMemorySize, ATTN2_SMEM);
    cudaFuncSetAttribute((const void*)gemm_mma<192, GK>,
                         cudaFuncAttributeMaxDynamicSharedMemorySize, GEMM_SMEM_FOR(192));
    cudaFuncSetAttribute((const void*)gemm_mma<128, GKO>,
                         cudaFuncAttributeMaxDynamicSharedMemorySize, GEMM_SMEM_FOR(128));

    // Split conversions
    conv_a<<<(MTOT * DMODEL / 4 + 255) / 256, 256>>>(x, xc);
    dim3 wb(32, 8);
    conv_qkv<<<dim3(NQKV / 32, DMODEL / 32), wb>>>(wq, wk, wv, wqkvt);
    conv_w<<<dim3(DMODEL / 32, DMODEL / 32), wb>>>(wo, wot, DMODEL);

    // Fused QKV projection (full-precision fp16 2-term, K'=2048)
    gemm_mma<192, GK><<<dim3(NQKV / 192, MTOT / 128), 256, GEMM_SMEM_FOR(192)>>>(
        xc, wqkvt, qkv, NQKV);

    // RoPE + fp16 split + fp32 kv-cache outputs
    finish_qk<<<(BATCH * SEQ * (NH + NKV) * 32 + 255) / 256, 256>>>(
        qkv, cosT, sinT, kout, qb, kb);
    finish_v<<<dim3(SEQ / 32, HD / 32, BATCH * NKV), dim3(32, 8)>>>(qkv, vout, vf);

    // Tensor-core flash attention (all-fp16, pipelined prefetch)
    attn_mma<<<dim3(SEQ / 64, NH, BATCH), 128, ATTN2_SMEM>>>(qb, kb, vf, aoc);

    // Output projection (single fp16, K'=1024)
    gemm_mma<128, GKO><<<dim3(DMODEL / 128, MTOT / 128), 256, GEMM_SMEM_FOR(128)>>>(
        aoc, wot, out, DMODEL);
}

// round 17
// speedup vs baseline: 2.0671x; 1.1651x over previous
#include <cuda_runtime.h>
#include <cuda_bf16.h>
#include <cuda_fp16.h>
#include <cstdint>

// Problem constants
#define BATCH 2
#define SEQ 2048
#define DMODEL 1024
#define NH 16
#define NKV 4
#define HD 64
#define OUT_ELEMS  (BATCH*SEQ*DMODEL)
#define KV_ELEMS   (BATCH*SEQ*NKV*HD)

#define MTOT (BATCH*SEQ)        // 4096
#define GK   (2*DMODEL)         // 2048: fp16 [hi|lo] x [hi|lo] = FULL product
#define GKO  (DMODEL)           // 1024: WO single-fp16
#define NQKV 1536               // fused QKV output width

// ---------------------------------------------------------------------------
// Scratch (device globals; no runtime allocation allowed)
// ---------------------------------------------------------------------------
__device__ float g_qkv[MTOT*NQKV];                   // fused QKV gemm output
__device__ __half g_xc   [MTOT*GK];                  // x split [M, 2K]
__device__ __half g_aoc  [MTOT*GKO];                 // attn out single fp16 [M, K]
__device__ __half g_wqkvt[NQKV*GK];                  // [wq|wk|wv]^T split
__device__ __half g_wot  [DMODEL*GKO];               // wo^T single fp16
// Attention operands (hi-only q/k: residual cross-terms ~1.6e-4 logit RMS)
__device__ __half g_qb [BATCH*NH*SEQ*64];            // [b][h][s][hd] fp16
__device__ __half g_kb [BATCH*NKV*SEQ*64];           // [b][kvh][s][hd] fp16
__device__ __half g_vf [BATCH*NKV*HD*SEQ];           // [b][kvh][d][s] fp16

// ---------------------------------------------------------------------------
// Baseline-PTX helpers
// ---------------------------------------------------------------------------
__device__ __forceinline__ uint32_t smem_u32(const void* p) {
    uint32_t a;
    asm("{ .reg .u64 t; cvta.to.shared.u64 t, %1; cvt.u32.u64 %0, t; }" : "=r"(a) : "l"(p));
    return a;
}
__device__ __forceinline__ void cp16(uint32_t saddr, const void* g) {
    asm volatile("cp.async.cg.shared.global [%0], [%1], 16;" :: "r"(saddr), "l"(g) : "memory");
}
#define CP_COMMIT() asm volatile("cp.async.commit_group;" ::: "memory")
#define CP_WAIT(n)  asm volatile("cp.async.wait_group %0;" :: "n"(n) : "memory")

__device__ __forceinline__ void ldsm4(uint32_t& r0, uint32_t& r1, uint32_t& r2, uint32_t& r3,
                                      uint32_t a) {
    asm volatile("ldmatrix.sync.aligned.m8n8.x4.shared.b16 {%0,%1,%2,%3}, [%4];"
                 : "=r"(r0), "=r"(r1), "=r"(r2), "=r"(r3) : "r"(a));
}
__device__ __forceinline__ void mma16816h(float* c, uint32_t a0, uint32_t a1, uint32_t a2,
                                          uint32_t a3, uint32_t b0, uint32_t b1) {
    asm volatile(
        "mma.sync.aligned.m16n8k16.row.col.f32.f16.f16.f32 "
        "{%0,%1,%2,%3},{%4,%5,%6,%7},{%8,%9},{%0,%1,%2,%3};"
        : "+f"(c[0]), "+f"(c[1]), "+f"(c[2]), "+f"(c[3])
        : "r"(a0), "r"(a1), "r"(a2), "r"(a3), "r"(b0), "r"(b1));
}
__device__ __forceinline__ uint32_t pack_f16(float x, float y) {
    uint32_t r;
    asm("cvt.rn.f16x2.f32 %0, %1, %2;" : "=r"(r) : "f"(y), "f"(x));
    return r;
}
__device__ __forceinline__ void split_f16(float v, __half& hi, __half& lo) {
    hi = __float2half(v);
    lo = __float2half(v - __half2float(hi));
}

// ---------------------------------------------------------------------------
// A-side split: src [M, K] fp32 -> dst [M, 2K] = [hi | lo]
// ---------------------------------------------------------------------------
__global__ __launch_bounds__(256) void conv_a(const float* __restrict__ src,
                                              __half* __restrict__ dst) {
    int idx = blockIdx.x * blockDim.x + threadIdx.x;
    const int K = DMODEL;
    if (idx >= MTOT * K / 4) return;
    int flat = idx * 4;
    int m = flat / K, k = flat % K;
    float4 v = *(const float4*)(src + flat);
    float vv[4] = {v.x, v.y, v.z, v.w};
    __half h[4], l[4];
#pragma unroll
    for (int j = 0; j < 4; j++) split_f16(vv[j], h[j], l[j]);
    __half* row = dst + (size_t)m * GK;
    *(uint2*)(row + k)     = *(uint2*)h;
    *(uint2*)(row + K + k) = *(uint2*)l;
}

// Merged weight conversion: blocks 0..47 -> [wq|wk|wv] 2-term split into wqkvt;
// blocks 48..79 -> wo single-fp16 transpose into wot.
__global__ void conv_wts(const float* __restrict__ wq, const float* __restrict__ wk,
                         const float* __restrict__ wv, const float* __restrict__ wo,
                         __half* __restrict__ dqkv, __half* __restrict__ dwo) {
    __shared__ float tile[32][33];
    const int K = DMODEL;
    int bx = blockIdx.x;
    int k0 = blockIdx.y * 32;
    int tx = threadIdx.x, ty = threadIdx.y;

    if (bx < 48) {
        int n0 = bx * 32;
        const float* src;
        int nloc, N;
        float scale = 1.f;
        if (n0 < 1024)      { src = wq; nloc = n0;        N = 1024; scale = 0.125f; }
        else if (n0 < 1280) { src = wk; nloc = n0 - 1024; N = 256; }
        else                { src = wv; nloc = n0 - 1280; N = 256; }
#pragma unroll
        for (int i = 0; i < 32; i += 8)
            tile[ty + i][tx] = src[(size_t)(k0 + ty + i) * N + nloc + tx] * scale;
        __syncthreads();
#pragma unroll
        for (int i = 0; i < 32; i += 8) {
            int n = n0 + ty + i, k = k0 + tx;
            __half h, l;
            split_f16(tile[tx][ty + i], h, l);
            __half* row = dqkv + (size_t)n * GK;
            row[k]     = h;
            row[K + k] = l;
        }
    } else {
        int n0 = (bx - 48) * 32;
#pragma unroll
        for (int i = 0; i < 32; i += 8)
            tile[ty + i][tx] = wo[(size_t)(k0 + ty + i) * DMODEL + n0 + tx];
        __syncthreads();
#pragma unroll
        for (int i = 0; i < 32; i += 8) {
            int n = n0 + ty + i, k = k0 + tx;
            dwo[(size_t)n * GKO + k] = __float2half(tile[tx][ty + i]);
        }
    }
}

// ---------------------------------------------------------------------------
// fp16 mma.sync GEMM, templated on CTA N-tile width and contraction depth.
// ---------------------------------------------------------------------------
#define BMt 128
#define BKt 32
#define PADt 40
#define STAGES 4
#define GEMM_SMEM_FOR(BN) (STAGES * (BMt + (BN)) * PADt * 2)

template<int BN, int KK>
__global__ __launch_bounds__(256, 2) void gemm_mma(const __half* __restrict__ A,
                                                   const __half* __restrict__ Bt,
                                                   float* __restrict__ C, int N) {
    constexpr int WN = BN / 4;
    constexpr int NT = WN / 8;
    constexpr int NP = WN / 16;
    constexpr int SEL = (BMt + BN) * PADt;
    constexpr int TOTCH = (BMt + BN) * 4;
    constexpr int NCH = KK / BKt;

    extern __shared__ __half gsm[];
    uint32_t smb = smem_u32(gsm);

    int t = threadIdx.x, w = t >> 5, lane = t & 31;
    int m0 = blockIdx.y * BMt, n0 = blockIdx.x * BN;
    int wm = (w >> 2) * 64;
    int wn = (w & 3) * WN;

    float acc[4][NT][4];
#pragma unroll
    for (int i = 0; i < 4; i++)
#pragma unroll
        for (int j = 0; j < NT; j++)
#pragma unroll
            for (int r = 0; r < 4; r++) acc[i][j][r] = 0.f;

    const __half* Ab = A  + (size_t)m0 * KK;
    const __half* Bb = Bt + (size_t)n0 * KK;

    auto load_tile = [&](int kc, int s) {
        if (kc < NCH) {
            uint32_t ab = smb + s * (SEL * 2);
            uint32_t bb = ab + BMt * PADt * 2;
            const __half* Ak = Ab + kc * BKt;
            const __half* Bk = Bb + kc * BKt;
#pragma unroll
            for (int i = 0; i < TOTCH / 256; i++) {
                int idx = t + i * 256;
                int row = idx >> 2, ch = idx & 3;
                if (row < BMt)
                    cp16(ab + (row * PADt + ch * 8) * 2, Ak + (size_t)row * KK + ch * 8);
                else {
                    int r = row - BMt;
                    cp16(bb + (r * PADt + ch * 8) * 2, Bk + (size_t)r * KK + ch * 8);
                }
            }
        }
        CP_COMMIT();
    };

#pragma unroll
    for (int s = 0; s < STAGES - 1; s++) load_tile(s, s);

    int li = lane >> 3;
    int lr = lane & 7;

    for (int kc = 0; kc < NCH; kc++) {
        CP_WAIT(STAGES - 2);
        __syncthreads();
        load_tile(kc + STAGES - 1, (kc + STAGES - 1) % STAGES);

        int s = kc % STAGES;
        uint32_t ab = smb + s * (SEL * 2);
        uint32_t bb = ab + BMt * PADt * 2;

#pragma unroll
        for (int ks = 0; ks < 2; ks++) {
            int k0 = ks * 16;
            uint32_t a[4][4];
#pragma unroll
            for (int mt = 0; mt < 4; mt++) {
                int row = wm + mt * 16 + (li & 1) * 8 + lr;
                int col = k0 + (li >> 1) * 8;
                ldsm4(a[mt][0], a[mt][1], a[mt][2], a[mt][3],
                      ab + (row * PADt + col) * 2);
            }
            uint32_t b[NP][4];
#pragma unroll
            for (int p = 0; p < NP; p++) {
                int row = wn + p * 16 + (li >> 1) * 8 + lr;
                int col = k0 + (li & 1) * 8;
                ldsm4(b[p][0], b[p][1], b[p][2], b[p][3],
                      bb + (row * PADt + col) * 2);
            }
#pragma unroll
            for (int mt = 0; mt < 4; mt++)
#pragma unroll
                for (int nt = 0; nt < NT; nt++) {
                    int p = nt >> 1, off = (nt & 1) * 2;
                    mma16816h(acc[mt][nt], a[mt][0], a[mt][1], a[mt][2], a[mt][3],
                              b[p][off], b[p][off + 1]);
                }
        }
    }

    int cr = lane >> 2, cc = (lane & 3) * 2;
#pragma unroll
    for (int mt = 0; mt < 4; mt++)
#pragma unroll
        for (int nt = 0; nt < NT; nt++) {
            float* Cp = C + (size_t)(m0 + wm + mt * 16 + cr) * N + n0 + wn + nt * 8 + cc;
            *(float2*)Cp = make_float2(acc[mt][nt][0], acc[mt][nt][1]);
            *(float2*)(Cp + 8 * (size_t)N) = make_float2(acc[mt][nt][2], acc[mt][nt][3]);
        }
}

// ---------------------------------------------------------------------------
// finish_qk: fused RoPE; q/k stored hi-only fp16 (64 cols); fp32 new_k out.
// ---------------------------------------------------------------------------
__global__ __launch_bounds__(256) void finish_qk(const float* __restrict__ qkv,
                                                 const float* __restrict__ cosT,
                                                 const float* __restrict__ sinT,
                                                 float* __restrict__ kout,
                                                 __half* __restrict__ qb,
                                                 __half* __restrict__ kb) {
    int idx = blockIdx.x * 256 + threadIdx.x;
    const int total = BATCH * SEQ * (NH + NKV) * 32;
    if (idx >= total) return;
    int j = idx & 31;
    int rest = idx >> 5;
    int head = rest % (NH + NKV);
    int row = rest / (NH + NKV);
    int s = row % SEQ, b = row / SEQ;

    float c  = cosT[s * 32 + j];
    float sn = sinT[s * 32 + j];

    const float* src;
    if (head < NH) src = qkv + (size_t)row * NQKV + head * 64;
    else           src = qkv + (size_t)row * NQKV + 1024 + (head - NH) * 64;

    float x1 = src[j], x2 = src[j + 32];
    float y1 = x1 * c - x2 * sn;
    float y2 = x2 * c + x1 * sn;

    if (head < NH) {
        __half* d = qb + ((size_t)(b * NH + head) * SEQ + s) * 64;
        d[j]      = __float2half(y1);
        d[j + 32] = __float2half(y2);
    } else {
        int kvh = head - NH;
        float* ko = kout + ((size_t)row * NKV + kvh) * 64;
        ko[j] = y1;
        ko[j + 32] = y2;
        __half* d = kb + ((size_t)(b * NKV + kvh) * SEQ + s) * 64;
        d[j]      = __float2half(y1);
        d[j + 32] = __float2half(y2);
    }
}

// finish_v: fp32 new_v to d_out + transposed single-fp16 V
__global__ void finish_v(const float* __restrict__ qkv,
                         float* __restrict__ vout,
                         __half* __restrict__ vf) {
    __shared__ float tile[32][33];
    int bkv = blockIdx.z;
    int b = bkv / NKV, kvh = bkv % NKV;
    int s0 = blockIdx.x * 32, d0 = blockIdx.y * 32;
    int tx = threadIdx.x, ty = threadIdx.y;
#pragma unroll
    for (int i = 0; i < 32; i += 8) {
        int s = s0 + ty + i;
        float v = qkv[((size_t)b * SEQ + s) * NQKV + 1280 + kvh * 64 + d0 + tx];
        tile[ty + i][tx] = v;
        vout[(((size_t)b * SEQ + s) * NKV + kvh) * 64 + d0 + tx] = v;
    }
    __syncthreads();
#pragma unroll
    for (int i = 0; i < 32; i += 8) {
        int d = d0 + ty + i, s = s0 + tx;
        vf[((size_t)bkv * HD + d) * SEQ + s] = __float2half(tile[tx][ty + i]);
    }
}

// ---------------------------------------------------------------------------
// Tensor-core flash attention, all-fp16 hi-only operands.
// S: qhi x khi (4 ksteps, 64 cols). PV: single fp16 (4 ksteps).
// Smem: 3 x 64 x 72 fp16 = 27 KB -> ~5 CTAs/SM.
// ---------------------------------------------------------------------------
#define HPAD 72
#define ATTN2_SMEM (3 * 64 * HPAD * 2)

__global__ __launch_bounds__(128) void attn_mma(const __half* __restrict__ Qb,
                                                const __half* __restrict__ Kb,
                                                const __half* __restrict__ Vf,
                                                __half* __restrict__ aoc) {
    extern __shared__ __half sh[];
    __half* qs = sh;
    __half* ks = sh + 64 * HPAD;
    __half* vs = sh + 2 * 64 * HPAD;
    uint32_t qsa = smem_u32(qs), ksa = smem_u32(ks), vsa = smem_u32(vs);

    int t = threadIdx.x, w = t >> 5, lane = t & 31;
    int qt = gridDim.x - 1 - blockIdx.x;   // longest CTAs first
    int h = blockIdx.y, b = blockIdx.z;
    int kvh = h >> 2;
    int li = lane >> 3, lr = lane & 7;
    int r0 = lane >> 2;
    int cc = (lane & 3) * 2;

    const __half* ksrc0 = Kb + (size_t)(b * NKV + kvh) * SEQ * 64;
    const __half* vf0 = Vf + (size_t)(b * NKV + kvh) * HD * SEQ;

    auto issueK = [&](int kt) {
        const __half* ksrc = ksrc0 + (size_t)kt * 64 * 64;
#pragma unroll
        for (int i = 0; i < 4; i++) {
            int c = t + 128 * i;
            int row = c >> 3, seg = c & 7;
            cp16(ksa + (row * HPAD + seg * 8) * 2, ksrc + (size_t)row * 64 + seg * 8);
        }
        CP_COMMIT();
    };
    auto issueV = [&](int kt) {
#pragma unroll
        for (int i = 0; i < 4; i++) {
            int c = t + 128 * i;
            int d = c >> 3, seg = c & 7;
            cp16(vsa + (d * HPAD + seg * 8) * 2,
                 vf0 + (size_t)d * SEQ + kt * 64 + seg * 8);
        }
        CP_COMMIT();
    };

    // Prologue: Q tile [64][64], then K(0), V(0)
    const __half* qsrc = Qb + ((size_t)(b * NH + h) * SEQ + (size_t)qt * 64) * 64;
#pragma unroll
    for (int i = 0; i < 4; i++) {
        int c = t + 128 * i;
        int row = c >> 3, seg = c & 7;
        cp16(qsa + (row * HPAD + seg * 8) * 2, qsrc + (size_t)row * 64 + seg * 8);
    }
    CP_COMMIT();
    issueK(0);
    issueV(0);

    float m0 = -1e30f, m1 = -1e30f, l0 = 0.f, l1 = 0.f;
    float of[8][4];
#pragma unroll
    for (int j = 0; j < 8; j++)
#pragma unroll
        for (int e = 0; e < 4; e++) of[j][e] = 0.f;

    for (int kt = 0; kt <= qt; kt++) {
        CP_WAIT(1);
        __syncthreads();

        // ---- S = Qhi Khi^T (4 ksteps over 64 cols) ----
        float sf[8][4];
#pragma unroll
        for (int j = 0; j < 8; j++)
#pragma unroll
            for (int e = 0; e < 4; e++) sf[j][e] = 0.f;
#pragma unroll
        for (int ks4 = 0; ks4 < 4; ks4++) {
            int col = ks4 * 16;
            uint32_t a0, a1, a2, a3;
            ldsm4(a0, a1, a2, a3,
                  qsa + ((w * 16 + (li & 1) * 8 + lr) * HPAD + col + (li >> 1) * 8) * 2);
#pragma unroll
            for (int p = 0; p < 4; p++) {
                uint32_t b0, b1, b2, b3;
                ldsm4(b0, b1, b2, b3,
                      ksa + ((p * 16 + (li >> 1) * 8 + lr) * HPAD + col + (li & 1) * 8) * 2);
                mma16816h(sf[2 * p],     a0, a1, a2, a3, b0, b1);
                mma16816h(sf[2 * p + 1], a0, a1, a2, a3, b2, b3);
            }
        }

        if (kt == qt) {
            int q0 = w * 16 + r0, q1 = q0 + 8;
#pragma unroll
            for (int j = 0; j < 8; j++) {
                int key = 8 * j + cc;
                if (key     > q0) sf[j][0] = -1e30f;
                if (key + 1 > q0) sf[j][1] = -1e30f;
                if (key     > q1) sf[j][2] = -1e30f;
                if (key + 1 > q1) sf[j][3] = -1e30f;
            }
        }

        // ---- online softmax ----
        float mx0 = -1e30f, mx1 = -1e30f;
#pragma unroll
        for (int j = 0; j < 8; j++) {
            mx0 = fmaxf(mx0, fmaxf(sf[j][0], sf[j][1]));
            mx1 = fmaxf(mx1, fmaxf(sf[j][2], sf[j][3]));
        }
        mx0 = fmaxf(mx0, __shfl_xor_sync(0xffffffffu, mx0, 1));
        mx0 = fmaxf(mx0, __shfl_xor_sync(0xffffffffu, mx0, 2));
        mx1 = fmaxf(mx1, __shfl_xor_sync(0xffffffffu, mx1, 1));
        mx1 = fmaxf(mx1, __shfl_xor_sync(0xffffffffu, mx1, 2));
        float nm0 = fmaxf(m0, mx0), nm1 = fmaxf(m1, mx1);
        float al0 = __expf(m0 - nm0), al1 = __expf(m1 - nm1);
        m0 = nm0; m1 = nm1;

        float s0 = 0.f, s1 = 0.f;
#pragma unroll
        for (int j = 0; j < 8; j++) {
            sf[j][0] = __expf(sf[j][0] - m0); s0 += sf[j][0];
            sf[j][1] = __expf(sf[j][1] - m0); s0 += sf[j][1];
            sf[j][2] = __expf(sf[j][2] - m1); s1 += sf[j][2];
            sf[j][3] = __expf(sf[j][3] - m1); s1 += sf[j][3];
        }
        s0 += __shfl_xor_sync(0xffffffffu, s0, 1);
        s0 += __shfl_xor_sync(0xffffffffu, s0, 2);
        s1 += __shfl_xor_sync(0xffffffffu, s1, 1);
        s1 += __shfl_xor_sync(0xffffffffu, s1, 2);
        l0 = l0 * al0 + s0;
        l1 = l1 * al1 + s1;

#pragma unroll
        for (int j = 0; j < 8; j++) {
            of[j][0] *= al0; of[j][1] *= al0;
            of[j][2] *= al1; of[j][3] *= al1;
        }

        // ---- pack P into single-fp16 A-fragments ----
        uint32_t ah[4][4];
#pragma unroll
        for (int kk = 0; kk < 4; kk++) {
            ah[kk][0] = pack_f16(sf[2 * kk][0],     sf[2 * kk][1]);
            ah[kk][1] = pack_f16(sf[2 * kk][2],     sf[2 * kk][3]);
            ah[kk][2] = pack_f16(sf[2 * kk + 1][0], sf[2 * kk + 1][1]);
            ah[kk][3] = pack_f16(sf[2 * kk + 1][2], sf[2 * kk + 1][3]);
        }

        CP_WAIT(0);
        __syncthreads();

        if (kt < qt) issueK(kt + 1);

        // ---- O += P V (fp16, 4 ksteps) ----
#pragma unroll
        for (int ks4 = 0; ks4 < 4; ks4++) {
            uint32_t* A = ah[ks4];
            int k0 = ks4 * 16;
#pragma unroll
            for (int p = 0; p < 4; p++) {
                uint32_t b0, b1, b2, b3;
                ldsm4(b0, b1, b2, b3,
                      vsa + ((p * 16 + (li >> 1) * 8 + lr) * HPAD + k0 + (li & 1) * 8) * 2);
                mma16816h(of[2 * p],     A[0], A[1], A[2], A[3], b0, b1);
                mma16816h(of[2 * p + 1], A[0], A[1], A[2], A[3], b2, b3);
            }
        }
        __syncthreads();

        if (kt < qt) issueV(kt + 1);
    }

    // ---- epilogue: write single-fp16 aoc [M, 1024] ----
    float inv0 = 1.f / l0, inv1 = 1.f / l1;
    int row0 = b * SEQ + qt * 64 + w * 16 + r0;
    int row1 = row0 + 8;
#pragma unroll
    for (int j = 0; j < 8; j++) {
        int colq = h * 64 + 8 * j + cc;
        *(uint32_t*)(aoc + (size_t)row0 * GKO + colq) =
            pack_f16(of[j][0] * inv0, of[j][1] * inv0);
        *(uint32_t*)(aoc + (size_t)row1 * GKO + colq) =
            pack_f16(of[j][2] * inv1, of[j][3] * inv1);
    }
}

// ---------------------------------------------------------------------------
extern "C" void kernel_launch(void* const* d_in, const int* in_sizes, int n_in,
                              void* d_out, int out_size) {
    const float* x    = (const float*)d_in[0];
    const float* cosT = (const float*)d_in[1];
    const float* sinT = (const float*)d_in[2];
    // d_in[3] = mask: unused
    const float* wq   = (const float*)d_in[4];
    const float* wk   = (const float*)d_in[5];
    const float* wv   = (const float*)d_in[6];
    const float* wo   = (const float*)d_in[7];

    float* out  = (float*)d_out;
    float* kout = out + OUT_ELEMS;
    float* vout = out + OUT_ELEMS + KV_ELEMS;

    float* qkv;
    __half *xc, *aoc, *wqkvt, *wot, *qb, *kb, *vf;
    cudaGetSymbolAddress((void**)&qkv, g_qkv);
    cudaGetSymbolAddress((void**)&xc,  g_xc);
    cudaGetSymbolAddress((void**)&aoc, g_aoc);
    cudaGetSymbolAddress((void**)&wqkvt, g_wqkvt);
    cudaGetSymbolAddress((void**)&wot, g_wot);
    cudaGetSymbolAddress((void**)&qb,  g_qb);
    cudaGetSymbolAddress((void**)&kb,  g_kb);
    cudaGetSymbolAddress((void**)&vf,  g_vf);

    cudaFuncSetAttribute(attn_mma, cudaFuncAttributeMaxDynamicSharedMemorySize, ATTN2_SMEM);
    cudaFuncSetAttribute((const void*)gemm_mma<192, GK>,
                         cudaFuncAttributeMaxDynamicSharedMemorySize, GEMM_SMEM_FOR(192));
    cudaFuncSetAttribute((const void*)gemm_mma<128, GKO>,
                         cudaFuncAttributeMaxDynamicSharedMemorySize, GEMM_SMEM_FOR(128));

    // Split conversions (merged weight kernel)
    conv_a<<<(MTOT * DMODEL / 4 + 255) / 256, 256>>>(x, xc);
    conv_wts<<<dim3(80, DMODEL / 32), dim3(32, 8)>>>(wq, wk, wv, wo, wqkvt, wot);

    // Fused QKV projection (full-precision fp16 2-term, K'=2048)
    gemm_mma<192, GK><<<dim3(NQKV / 192, MTOT / 128), 256, GEMM_SMEM_FOR(192)>>>(
        xc, wqkvt, qkv, NQKV);

    // RoPE + hi-only fp16 + fp32 kv-cache outputs
    finish_qk<<<(BATCH * SEQ * (NH + NKV) * 32 + 255) / 256, 256>>>(
        qkv, cosT, sinT, kout, qb, kb);
    finish_v<<<dim3(SEQ / 32, HD / 32, BATCH * NKV), dim3(32, 8)>>>(qkv, vout, vf);

    // Tensor-core flash attention (hi-only S, single-fp16 PV)
    attn_mma<<<dim3(SEQ / 64, NH, BATCH), 128, ATTN2_SMEM>>>(qb, kb, vf, aoc);

    // Output projection (single fp16, K'=1024)
    gemm_mma<128, GKO><<<dim3(DMODEL / 128, MTOT / 128), 256, GEMM_SMEM_FOR(128)>>>(
        aoc, wot, out, DMODEL);
}